// round 4
// baseline (speedup 1.0000x reference)
#include <cuda_runtime.h>
#include <math.h>

#define NTOK 32768
#define HW 4096
#define EPSV 1e-5f

// ---------------- scratch (static device memory; no allocations) ----------------
__device__ float g_mu1[NTOK], g_rs1[NTOK], g_mu2[NTOK], g_rs2[NTOK];
__device__ float g_q1[NTOK * 256];
__device__ float g_q2[NTOK * 256];
__device__ float g_kv1[NTOK * 512];
__device__ float g_kv2[NTOK * 512];
__device__ float g_oh1[NTOK * 256], g_ow1[NTOK * 256];
__device__ float g_oh2[NTOK * 256], g_ow2[NTOK * 256];
__device__ float g_sc[NTOK * 256];
__device__ float g_Wq1f[384 * 256], g_Wkv1f[384 * 512];
__device__ float g_Wq2f[256 * 256], g_Wkv2f[256 * 512];
__device__ float g_Wscf[384 * 256];
__device__ float g_bq1[256], g_bkv1[512], g_bq2[256], g_bkv2[512], g_bsc[256];

// ---------------- weight folding: LN affine / BN folded into GEMM weights ----------------
__global__ void k_fold_w(const float* __restrict__ W, const float* __restrict__ lnw,
                         float* __restrict__ Wf, int C, int Nout) {
    int idx = blockIdx.x * 256 + threadIdx.x;
    if (idx < C * Nout) {
        int c = idx / Nout;
        Wf[idx] = W[idx] * lnw[c];
    }
}

__global__ void k_fold_b(const float* __restrict__ W, const float* __restrict__ lnb,
                         float* __restrict__ bf, int C, int Nout) {
    int o = blockIdx.x * 256 + threadIdx.x;
    if (o < Nout) {
        float s = 0.f;
        for (int c = 0; c < C; c++) s += lnb[c] * W[c * Nout + o];
        bf[o] = s;
    }
}

// shortcut: sc = x1f @ Wsc^T (Wsc is [256,384]); then BN(inference). Fold BN into weights.
__global__ void k_fold_sc(const float* __restrict__ Wsc, const float* __restrict__ gamma,
                          const float* __restrict__ beta, const float* __restrict__ mean,
                          const float* __restrict__ var,
                          float* __restrict__ Wf, float* __restrict__ bf) {
    int idx = blockIdx.x * 256 + threadIdx.x;
    if (idx < 384 * 256) {
        int c = idx >> 8, o = idx & 255;
        float g = gamma[o] * rsqrtf(var[o] + EPSV);
        Wf[idx] = Wsc[o * 384 + c] * g;
        if (c == 0) bf[o] = beta[o] - mean[o] * g;
    }
}

// ---------------- per-token LN statistics (mean, rstd) over channel dim ----------------
__global__ void k_stats(const float* __restrict__ X, int C,
                        float* __restrict__ mu, float* __restrict__ rs) {
    int t = blockIdx.x * blockDim.x + threadIdx.x;
    if (t >= NTOK) return;
    int b = t >> 12, hw = t & 4095;
    const float* p = X + (size_t)b * C * HW + hw;
    float s = 0.f, s2 = 0.f;
    for (int c = 0; c < C; c++) {
        float v = p[(size_t)c * HW];
        s += v; s2 += v * v;
    }
    float m = s / C;
    float vvar = s2 / C - m * m;
    mu[t] = m;
    rs[t] = rsqrtf(vvar + EPSV);
}

// ---------------- projection GEMM: out[t,o] = LN(x)[t,:] @ Wf + bias ----------------
// X is [B, C, HW] (NCHW). A-tile load does the implicit transpose + LN, coalesced over hw.
// 64x64 tile, BK=16, 256 threads, 4x4 microtile.
__global__ void k_gemm(const float* __restrict__ X,
                       const float* __restrict__ mu, const float* __restrict__ rs,
                       const float* __restrict__ Wf, const float* __restrict__ bias,
                       float* __restrict__ out, int C, int Nout) {
    __shared__ float As[16][64];
    __shared__ float Bs[16][64];
    __shared__ float smu[64], srs[64];
    int t0 = blockIdx.x * 64, o0 = blockIdx.y * 64;
    int tid = threadIdx.x;
    int b = t0 >> 12, hw0 = t0 & 4095;
    if (tid < 64) {
        if (mu) { smu[tid] = mu[t0 + tid]; srs[tid] = rs[t0 + tid]; }
        else    { smu[tid] = 0.f;          srs[tid] = 1.f; }
    }
    __syncthreads();
    int ty = tid >> 4, tx = tid & 15;
    float acc[4][4] = {};
    const float* Xb = X + (size_t)b * C * HW + hw0;
    for (int k0 = 0; k0 < C; k0 += 16) {
#pragma unroll
        for (int j = 0; j < 4; j++) {
            int i = tid + 256 * j;
            int kk = i >> 6, tt = i & 63;
            float v = Xb[(size_t)(k0 + kk) * HW + tt];
            As[kk][tt] = (v - smu[tt]) * srs[tt];
            Bs[kk][tt] = Wf[(k0 + kk) * Nout + o0 + tt];
        }
        __syncthreads();
#pragma unroll
        for (int kk = 0; kk < 16; kk++) {
            float4 a  = *(const float4*)&As[kk][ty * 4];
            float4 bb = *(const float4*)&Bs[kk][tx * 4];
            float av[4] = {a.x, a.y, a.z, a.w};
            float bv[4] = {bb.x, bb.y, bb.z, bb.w};
#pragma unroll
            for (int r = 0; r < 4; r++)
#pragma unroll
                for (int c = 0; c < 4; c++)
                    acc[r][c] += av[r] * bv[c];
        }
        __syncthreads();
    }
#pragma unroll
    for (int r = 0; r < 4; r++) {
        int t = t0 + ty * 4 + r;
#pragma unroll
        for (int c = 0; c < 4; c++) {
            int o = o0 + tx * 4 + c;
            out[(size_t)t * Nout + o] = acc[r][c] + bias[o];
        }
    }
}

// ---------------- axial attention: one (b, line, head) 64x64 attention per block ----------------
// axis=0: attend over H (line = w, token stride 64). axis=1: attend over W (line = h, stride 1).
__global__ void k_attn(const float* __restrict__ Q,
                       const float* __restrict__ K, const float* __restrict__ V,
                       int kvpitch, float* __restrict__ O, int axis) {
    __shared__ float Qs[64][36];
    __shared__ float Ks[64][36];
    __shared__ float Vs[64][36];
    __shared__ float S[64][65];
    int bx = blockIdx.x;
    int head = bx & 7, line = (bx >> 3) & 63, b = bx >> 9;
    int tstride = axis ? 1 : 64;
    int tbase = b * 4096 + (axis ? line * 64 : line);
    int hoff = head * 32;
    int tid = threadIdx.x; // 128 threads

    for (int i = tid; i < 64 * 32; i += 128) {
        int r = i >> 5, d = i & 31;
        int t = tbase + r * tstride;
        Qs[r][d] = Q[(size_t)t * 256 + hoff + d];
        Ks[r][d] = K[(size_t)t * kvpitch + hoff + d];
        Vs[r][d] = V[(size_t)t * kvpitch + hoff + d];
    }
    __syncthreads();

    // S = Q K^T * scale ; each thread: one q row, 32 k rows
    {
        int si = tid >> 1, j0 = (tid & 1) * 32;
        float4 q[8];
#pragma unroll
        for (int d4 = 0; d4 < 8; d4++) q[d4] = *(const float4*)&Qs[si][d4 * 4];
        const float scale = 0.17677669529663687f; // 1/sqrt(32)
#pragma unroll 4
        for (int j = 0; j < 32; j++) {
            float s = 0.f;
#pragma unroll
            for (int d4 = 0; d4 < 8; d4++) {
                float4 kv = *(const float4*)&Ks[j0 + j][d4 * 4];
                s += q[d4].x * kv.x + q[d4].y * kv.y + q[d4].z * kv.z + q[d4].w * kv.w;
            }
            S[si][j0 + j] = s * scale;
        }
    }
    __syncthreads();

    // softmax over rows
    if (tid < 64) {
        float m = -1e30f;
#pragma unroll 8
        for (int j = 0; j < 64; j++) m = fmaxf(m, S[tid][j]);
        float sum = 0.f;
#pragma unroll 8
        for (int j = 0; j < 64; j++) { float e = __expf(S[tid][j] - m); S[tid][j] = e; sum += e; }
        float inv = 1.f / sum;
#pragma unroll 8
        for (int j = 0; j < 64; j++) S[tid][j] *= inv;
    }
    __syncthreads();

    // O = P V ; each thread: one o row, 16 of 32 d-columns
    {
        int oi = tid >> 1, d0 = (tid & 1) * 16;
        float4 acc[4] = {};
        for (int j = 0; j < 64; j++) {
            float p = S[oi][j];
#pragma unroll
            for (int d4 = 0; d4 < 4; d4++) {
                float4 v = *(const float4*)&Vs[j][d0 + d4 * 4];
                acc[d4].x += p * v.x; acc[d4].y += p * v.y;
                acc[d4].z += p * v.z; acc[d4].w += p * v.w;
            }
        }
        int t = tbase + oi * tstride;
#pragma unroll
        for (int d4 = 0; d4 < 4; d4++)
            *(float4*)&O[(size_t)t * 256 + hoff + d0 + d4 * 4] = acc[d4];
    }
}

// ---------------- final fused GEMM: out = sc + x2 + (o1@Wout1+b1) + (o2@Wout2+b2), NCHW write ----------------
__global__ void k_final(const float* __restrict__ oh1, const float* __restrict__ ow1,
                        const float* __restrict__ oh2, const float* __restrict__ ow2,
                        const float* __restrict__ W1, const float* __restrict__ W2,
                        const float* __restrict__ b1, const float* __restrict__ b2,
                        const float* __restrict__ scY, const float* __restrict__ x2,
                        float* __restrict__ out) {
    __shared__ float As[16][68];   // padded: row stride 272B keeps float4 alignment
    __shared__ float Bs[16][64];
    int t0 = blockIdx.x * 64, o0 = blockIdx.y * 64;
    int tid = threadIdx.x;
    int ty = tid >> 4, tx = tid & 15;
    float acc[4][4] = {};
    for (int k0 = 0; k0 < 512; k0 += 16) {
        const float* A0 = (k0 < 256) ? oh1 : oh2;
        const float* A1 = (k0 < 256) ? ow1 : ow2;
        const float* W  = (k0 < 256) ? W1 : W2;
        int kb = (k0 < 256) ? k0 : (k0 - 256);
#pragma unroll
        for (int j = 0; j < 4; j++) {
            int i = tid + 256 * j;
            int kk = i & 15, tt = i >> 4;
            size_t ai = (size_t)(t0 + tt) * 256 + kb + kk;
            As[kk][tt] = A0[ai] + A1[ai];
        }
#pragma unroll
        for (int j = 0; j < 4; j++) {
            int i = tid + 256 * j;
            int kk = i >> 6, oo = i & 63;
            Bs[kk][oo] = W[(kb + kk) * 256 + o0 + oo];
        }
        __syncthreads();
#pragma unroll
        for (int kk = 0; kk < 16; kk++) {
            float4 a  = *(const float4*)&As[kk][ty * 4];
            float4 bb = *(const float4*)&Bs[kk][tx * 4];
            float av[4] = {a.x, a.y, a.z, a.w};
            float bv[4] = {bb.x, bb.y, bb.z, bb.w};
#pragma unroll
            for (int r = 0; r < 4; r++)
#pragma unroll
                for (int c = 0; c < 4; c++)
                    acc[r][c] += av[r] * bv[c];
        }
        __syncthreads();
    }
    int b = t0 >> 12, hw0 = t0 & 4095;
#pragma unroll
    for (int r = 0; r < 4; r++) {
        int t = t0 + ty * 4 + r;
        int hw = hw0 + ty * 4 + r;
#pragma unroll
        for (int c = 0; c < 4; c++) {
            int o = o0 + tx * 4 + c;
            out[((size_t)b * 256 + o) * HW + hw] =
                acc[r][c] + b1[o] + b2[o] + scY[(size_t)t * 256 + o]
                + x2[((size_t)b * 256 + o) * HW + hw];
        }
    }
}

// ---------------- host launch ----------------
extern "C" void kernel_launch(void* const* d_in, const int* in_sizes, int n_in,
                              void* d_out, int out_size) {
    const float* x1      = (const float*)d_in[0];
    const float* x2      = (const float*)d_in[1];
    const float* ln1q_w  = (const float*)d_in[2];
    const float* ln1q_b  = (const float*)d_in[3];
    const float* ln2kv_w = (const float*)d_in[4];
    const float* ln2kv_b = (const float*)d_in[5];
    const float* Wq1     = (const float*)d_in[6];
    const float* Wkv2    = (const float*)d_in[7];
    const float* Wout1   = (const float*)d_in[8];
    const float* bout1   = (const float*)d_in[9];
    const float* ln2q_w  = (const float*)d_in[10];
    const float* ln2q_b  = (const float*)d_in[11];
    const float* ln1kv_w = (const float*)d_in[12];
    const float* ln1kv_b = (const float*)d_in[13];
    const float* Wq2     = (const float*)d_in[14];
    const float* Wkv1    = (const float*)d_in[15];
    const float* Wout2   = (const float*)d_in[16];
    const float* bout2   = (const float*)d_in[17];
    const float* Wsc     = (const float*)d_in[18];
    const float* bn_g    = (const float*)d_in[19];
    const float* bn_b    = (const float*)d_in[20];
    const float* bn_m    = (const float*)d_in[21];
    const float* bn_v    = (const float*)d_in[22];
    float* out = (float*)d_out;

    float *mu1, *rs1, *mu2, *rs2, *q1, *q2, *kv1, *kv2;
    float *oh1, *ow1, *oh2, *ow2, *sc;
    float *Wq1f, *Wkv1f, *Wq2f, *Wkv2f, *Wscf;
    float *bq1, *bkv1, *bq2, *bkv2, *bsc;
    cudaGetSymbolAddress((void**)&mu1, g_mu1);
    cudaGetSymbolAddress((void**)&rs1, g_rs1);
    cudaGetSymbolAddress((void**)&mu2, g_mu2);
    cudaGetSymbolAddress((void**)&rs2, g_rs2);
    cudaGetSymbolAddress((void**)&q1, g_q1);
    cudaGetSymbolAddress((void**)&q2, g_q2);
    cudaGetSymbolAddress((void**)&kv1, g_kv1);
    cudaGetSymbolAddress((void**)&kv2, g_kv2);
    cudaGetSymbolAddress((void**)&oh1, g_oh1);
    cudaGetSymbolAddress((void**)&ow1, g_ow1);
    cudaGetSymbolAddress((void**)&oh2, g_oh2);
    cudaGetSymbolAddress((void**)&ow2, g_ow2);
    cudaGetSymbolAddress((void**)&sc, g_sc);
    cudaGetSymbolAddress((void**)&Wq1f, g_Wq1f);
    cudaGetSymbolAddress((void**)&Wkv1f, g_Wkv1f);
    cudaGetSymbolAddress((void**)&Wq2f, g_Wq2f);
    cudaGetSymbolAddress((void**)&Wkv2f, g_Wkv2f);
    cudaGetSymbolAddress((void**)&Wscf, g_Wscf);
    cudaGetSymbolAddress((void**)&bq1, g_bq1);
    cudaGetSymbolAddress((void**)&bkv1, g_bkv1);
    cudaGetSymbolAddress((void**)&bq2, g_bq2);
    cudaGetSymbolAddress((void**)&bkv2, g_bkv2);
    cudaGetSymbolAddress((void**)&bsc, g_bsc);

    // fold LN/BN affine into weights
    k_fold_w<<<(384 * 256 + 255) / 256, 256>>>(Wq1, ln1q_w, Wq1f, 384, 256);
    k_fold_w<<<(384 * 512 + 255) / 256, 256>>>(Wkv1, ln1kv_w, Wkv1f, 384, 512);
    k_fold_w<<<(256 * 256 + 255) / 256, 256>>>(Wq2, ln2q_w, Wq2f, 256, 256);
    k_fold_w<<<(256 * 512 + 255) / 256, 256>>>(Wkv2, ln2kv_w, Wkv2f, 256, 512);
    k_fold_b<<<1, 256>>>(Wq1, ln1q_b, bq1, 384, 256);
    k_fold_b<<<2, 256>>>(Wkv1, ln1kv_b, bkv1, 384, 512);
    k_fold_b<<<1, 256>>>(Wq2, ln2q_b, bq2, 256, 256);
    k_fold_b<<<2, 256>>>(Wkv2, ln2kv_b, bkv2, 256, 512);
    k_fold_sc<<<(384 * 256 + 255) / 256, 256>>>(Wsc, bn_g, bn_b, bn_m, bn_v, Wscf, bsc);

    // LN stats
    k_stats<<<NTOK / 256, 256>>>(x1, 384, mu1, rs1);
    k_stats<<<NTOK / 256, 256>>>(x2, 256, mu2, rs2);

    // projections (LN folded; shortcut uses raw x1)
    k_gemm<<<dim3(512, 4), 256>>>(x1, mu1, rs1, Wq1f, bq1, q1, 384, 256);
    k_gemm<<<dim3(512, 8), 256>>>(x1, mu1, rs1, Wkv1f, bkv1, kv1, 384, 512);
    k_gemm<<<dim3(512, 4), 256>>>(x1, nullptr, nullptr, Wscf, bsc, sc, 384, 256);
    k_gemm<<<dim3(512, 4), 256>>>(x2, mu2, rs2, Wq2f, bq2, q2, 256, 256);
    k_gemm<<<dim3(512, 8), 256>>>(x2, mu2, rs2, Wkv2f, bkv2, kv2, 256, 512);

    // axial attention: branch1 (q1 x kv2), branch2 (q2 x kv1); axis 0 = rows(H), 1 = cols(W)
    k_attn<<<4096, 128>>>(q1, kv2, kv2 + 256, 512, oh1, 0);
    k_attn<<<4096, 128>>>(q1, kv2, kv2 + 256, 512, ow1, 1);
    k_attn<<<4096, 128>>>(q2, kv1, kv1 + 256, 512, oh2, 0);
    k_attn<<<4096, 128>>>(q2, kv1, kv1 + 256, 512, ow2, 1);

    // output GEMMs + shortcut + residual + NCHW transpose
    k_final<<<dim3(512, 4), 256>>>(oh1, ow1, oh2, ow2, Wout1, Wout2, bout1, bout2,
                                   sc, x2, out);
}

// round 5
// speedup vs baseline: 1.6684x; 1.6684x over previous
#include <cuda_runtime.h>
#include <math.h>

#define NTOK 32768
#define HW 4096
#define EPSV 1e-5f

// ---------------- scratch (static device memory; no allocations) ----------------
__device__ float g_mu1[NTOK], g_rs1[NTOK], g_mu2[NTOK], g_rs2[NTOK];
__device__ float g_p1[NTOK * 1024];   // per token: [q1(256) | k1(256) | v1(256) | sc(256)]
__device__ float g_p2[NTOK * 768];    // per token: [q2(256) | k2(256) | v2(256)]
__device__ float g_oh1[NTOK * 256], g_ow1[NTOK * 256];
__device__ float g_oh2[NTOK * 256], g_ow2[NTOK * 256];
__device__ float g_W1cat[384 * 1024];  // [C=384][q1|k1|v1|sc] folded
__device__ float g_W2cat[256 * 768];   // [C=256][q2|k2|v2] folded
__device__ float g_b1cat[1024], g_b2cat[768], g_Ssc[256];

// ---------------- fold all weights into two concatenated GEMM-B matrices ----------------
// W1cat[c,0:256]=Wq1*ln1q_w ; [256:768]=Wkv1*ln1kv_w ; [768:1024]=Wsc^T*bn_scale
// W2cat[c,0:256]=Wq2*ln2q_w ; [256:768]=Wkv2*ln2kv_w
__global__ void k_fold_wcat(const float* __restrict__ Wq1, const float* __restrict__ ln1qw,
                            const float* __restrict__ Wkv1, const float* __restrict__ ln1kvw,
                            const float* __restrict__ Wsc, const float* __restrict__ bng,
                            const float* __restrict__ bnv,
                            const float* __restrict__ Wq2, const float* __restrict__ ln2qw,
                            const float* __restrict__ Wkv2, const float* __restrict__ ln2kvw,
                            float* __restrict__ W1cat, float* __restrict__ W2cat) {
    int idx = blockIdx.x * 256 + threadIdx.x;
    const int N1 = 384 * 1024;
    if (idx < N1) {
        int c = idx >> 10, o = idx & 1023;
        float v;
        if (o < 256)      v = Wq1[c * 256 + o] * ln1qw[c];
        else if (o < 768) v = Wkv1[c * 512 + (o - 256)] * ln1kvw[c];
        else { int oo = o - 768; v = Wsc[oo * 384 + c] * bng[oo] * rsqrtf(bnv[oo] + EPSV); }
        W1cat[idx] = v;
    } else if (idx < N1 + 256 * 768) {
        int i2 = idx - N1;
        int c = i2 / 768, o = i2 % 768;
        float v;
        if (o < 256) v = Wq2[c * 256 + o] * ln2qw[c];
        else         v = Wkv2[c * 512 + (o - 256)] * ln2kvw[c];
        W2cat[i2] = v;
    }
}

// biases: b1cat (LN-beta folded through W; sc slot = BN beta-mean*g), b2cat, and
// Ssc[o] = g[o] * sum_c Wsc[o,c]  (for the mu*colsum shortcut term)
__global__ void k_fold_bias(const float* __restrict__ Wq1, const float* __restrict__ ln1qb,
                            const float* __restrict__ Wkv1, const float* __restrict__ ln1kvb,
                            const float* __restrict__ Wsc, const float* __restrict__ bng,
                            const float* __restrict__ bnb, const float* __restrict__ bnm,
                            const float* __restrict__ bnv,
                            const float* __restrict__ Wq2, const float* __restrict__ ln2qb,
                            const float* __restrict__ Wkv2, const float* __restrict__ ln2kvb,
                            float* __restrict__ b1cat, float* __restrict__ b2cat,
                            float* __restrict__ Ssc) {
    int og = blockIdx.x * 256 + threadIdx.x;
    if (og < 1024) {
        float b = 0.f;
        if (og < 256) {
            for (int c = 0; c < 384; c++) b += ln1qb[c] * Wq1[c * 256 + og];
        } else if (og < 768) {
            int o = og - 256;
            for (int c = 0; c < 384; c++) b += ln1kvb[c] * Wkv1[c * 512 + o];
        } else {
            int oo = og - 768;
            float g = bng[oo] * rsqrtf(bnv[oo] + EPSV);
            b = bnb[oo] - bnm[oo] * g;
            float s = 0.f;
            for (int c = 0; c < 384; c++) s += Wsc[oo * 384 + c];
            Ssc[oo] = s * g;
        }
        b1cat[og] = b;
    } else if (og < 1792) {
        int o2 = og - 1024;
        float b = 0.f;
        if (o2 < 256) {
            for (int c = 0; c < 256; c++) b += ln2qb[c] * Wq2[c * 256 + o2];
        } else {
            int o = o2 - 256;
            for (int c = 0; c < 256; c++) b += ln2kvb[c] * Wkv2[c * 512 + o];
        }
        b2cat[o2] = b;
    }
}

// ---------------- per-token LN statistics ----------------
__global__ void k_stats(const float* __restrict__ X, int C,
                        float* __restrict__ mu, float* __restrict__ rs) {
    int t = blockIdx.x * blockDim.x + threadIdx.x;
    if (t >= NTOK) return;
    int b = t >> 12, hw = t & 4095;
    const float* p = X + (size_t)b * C * HW + hw;
    float s = 0.f, s2 = 0.f;
    for (int c = 0; c < C; c++) {
        float v = p[(size_t)c * HW];
        s += v; s2 += v * v;
    }
    float m = s / C;
    mu[t] = m;
    rs[t] = rsqrtf(s2 / C - m * m + EPSV);
}

// ---------------- fused projection GEMM: out[t,:] = LN(x)[t,:] @ Wcat (+ shortcut cols) -------
// 128x64 tile, BK=16, 256 threads, 8x4 microtile, double-buffered smem.
// Columns >= sc_start get the BN-shortcut epilogue: acc/rs + mu*S + b  (undoes LN).
__global__ __launch_bounds__(256) void k_proj(
    const float* __restrict__ X, int C, int Nout,
    const float* __restrict__ mu, const float* __restrict__ rs,
    const float* __restrict__ W, const float* __restrict__ bias,
    const float* __restrict__ S, int sc_start,
    float* __restrict__ out) {
    __shared__ float As[2][16][128];
    __shared__ float Bs[2][16][64];
    __shared__ float smu[128], srs[128];
    int t0 = blockIdx.x * 128, o0 = blockIdx.y * 64;
    int tid = threadIdx.x;
    if (tid < 128) { smu[tid] = mu[t0 + tid]; srs[tid] = rs[t0 + tid]; }
    __syncthreads();
    int b = t0 >> 12, hw0 = t0 & 4095;
    const float* Xb = X + (size_t)b * C * HW + hw0;

    // tile 0
#pragma unroll
    for (int j = 0; j < 8; j++) {
        int i = tid + 256 * j; int kk = i >> 7, tt = i & 127;
        As[0][kk][tt] = (Xb[(size_t)kk * HW + tt] - smu[tt]) * srs[tt];
    }
#pragma unroll
    for (int j = 0; j < 4; j++) {
        int i = tid + 256 * j; int kk = i >> 6, oo = i & 63;
        Bs[0][kk][oo] = W[kk * Nout + o0 + oo];
    }
    __syncthreads();

    int ty = tid >> 4, tx = tid & 15;
    float acc[8][4] = {};
    int KT = C >> 4;
    int cur = 0;
    for (int kt = 0; kt < KT; kt++) {
        float ra[8], rb[4];
        if (kt + 1 < KT) {
            int k0n = (kt + 1) << 4;
#pragma unroll
            for (int j = 0; j < 8; j++) {
                int i = tid + 256 * j; int kk = i >> 7, tt = i & 127;
                ra[j] = Xb[(size_t)(k0n + kk) * HW + tt];
            }
#pragma unroll
            for (int j = 0; j < 4; j++) {
                int i = tid + 256 * j; int kk = i >> 6, oo = i & 63;
                rb[j] = W[(k0n + kk) * Nout + o0 + oo];
            }
        }
#pragma unroll
        for (int kk = 0; kk < 16; kk++) {
            float4 a0 = *(const float4*)&As[cur][kk][ty * 8];
            float4 a1 = *(const float4*)&As[cur][kk][ty * 8 + 4];
            float4 bb = *(const float4*)&Bs[cur][kk][tx * 4];
            float av[8] = {a0.x, a0.y, a0.z, a0.w, a1.x, a1.y, a1.z, a1.w};
            float bv[4] = {bb.x, bb.y, bb.z, bb.w};
#pragma unroll
            for (int r = 0; r < 8; r++)
#pragma unroll
                for (int c = 0; c < 4; c++)
                    acc[r][c] += av[r] * bv[c];
        }
        if (kt + 1 < KT) {
            int nb = cur ^ 1;
#pragma unroll
            for (int j = 0; j < 8; j++) {
                int i = tid + 256 * j; int kk = i >> 7, tt = i & 127;
                As[nb][kk][tt] = (ra[j] - smu[tt]) * srs[tt];
            }
#pragma unroll
            for (int j = 0; j < 4; j++) {
                int i = tid + 256 * j; int kk = i >> 6, oo = i & 63;
                Bs[nb][kk][oo] = rb[j];
            }
            cur = nb;
            __syncthreads();
        }
    }

    bool isc = (o0 >= sc_start);
    int ob = o0 + tx * 4;
    float4 bv = *(const float4*)&bias[ob];
    float4 sv = make_float4(0.f, 0.f, 0.f, 0.f);
    if (isc) sv = *(const float4*)&S[ob - sc_start];
#pragma unroll
    for (int r = 0; r < 8; r++) {
        int tt = ty * 8 + r;
        float4 v;
        if (isc) {
            float inv = 1.f / srs[tt], m = smu[tt];
            v.x = acc[r][0] * inv + m * sv.x + bv.x;
            v.y = acc[r][1] * inv + m * sv.y + bv.y;
            v.z = acc[r][2] * inv + m * sv.z + bv.z;
            v.w = acc[r][3] * inv + m * sv.w + bv.w;
        } else {
            v.x = acc[r][0] + bv.x; v.y = acc[r][1] + bv.y;
            v.z = acc[r][2] + bv.z; v.w = acc[r][3] + bv.w;
        }
        *(float4*)&out[(size_t)(t0 + tt) * Nout + ob] = v;
    }
}

// ---------------- axial attention: one (b, line, head) 64x64 attention per block ----------------
__global__ void k_attn(const float* __restrict__ Q, int qpitch,
                       const float* __restrict__ K, const float* __restrict__ V,
                       int kvpitch, float* __restrict__ O, int axis) {
    __shared__ float Qs[64][36];
    __shared__ float Ks[64][36];
    __shared__ float Vs[64][36];
    __shared__ float S[64][65];
    int bx = blockIdx.x;
    int head = bx & 7, line = (bx >> 3) & 63, b = bx >> 9;
    int tstride = axis ? 1 : 64;
    int tbase = b * 4096 + (axis ? line * 64 : line);
    int hoff = head * 32;
    int tid = threadIdx.x; // 128 threads

    for (int i = tid; i < 64 * 32; i += 128) {
        int r = i >> 5, d = i & 31;
        int t = tbase + r * tstride;
        Qs[r][d] = Q[(size_t)t * qpitch + hoff + d];
        Ks[r][d] = K[(size_t)t * kvpitch + hoff + d];
        Vs[r][d] = V[(size_t)t * kvpitch + hoff + d];
    }
    __syncthreads();

    {
        int si = tid >> 1, j0 = (tid & 1) * 32;
        float4 q[8];
#pragma unroll
        for (int d4 = 0; d4 < 8; d4++) q[d4] = *(const float4*)&Qs[si][d4 * 4];
        const float scale = 0.17677669529663687f; // 1/sqrt(32)
#pragma unroll 4
        for (int j = 0; j < 32; j++) {
            float s = 0.f;
#pragma unroll
            for (int d4 = 0; d4 < 8; d4++) {
                float4 kv = *(const float4*)&Ks[j0 + j][d4 * 4];
                s += q[d4].x * kv.x + q[d4].y * kv.y + q[d4].z * kv.z + q[d4].w * kv.w;
            }
            S[si][j0 + j] = s * scale;
        }
    }
    __syncthreads();

    if (tid < 64) {
        float m = -1e30f;
#pragma unroll 8
        for (int j = 0; j < 64; j++) m = fmaxf(m, S[tid][j]);
        float sum = 0.f;
#pragma unroll 8
        for (int j = 0; j < 64; j++) { float e = __expf(S[tid][j] - m); S[tid][j] = e; sum += e; }
        float inv = 1.f / sum;
#pragma unroll 8
        for (int j = 0; j < 64; j++) S[tid][j] *= inv;
    }
    __syncthreads();

    {
        int oi = tid >> 1, d0 = (tid & 1) * 16;
        float4 acc[4] = {};
        for (int j = 0; j < 64; j++) {
            float p = S[oi][j];
#pragma unroll
            for (int d4 = 0; d4 < 4; d4++) {
                float4 v = *(const float4*)&Vs[j][d0 + d4 * 4];
                acc[d4].x += p * v.x; acc[d4].y += p * v.y;
                acc[d4].z += p * v.z; acc[d4].w += p * v.w;
            }
        }
        int t = tbase + oi * tstride;
#pragma unroll
        for (int d4 = 0; d4 < 4; d4++)
            *(float4*)&O[(size_t)t * 256 + hoff + d0 + d4 * 4] = acc[d4];
    }
}

// ---------------- final fused GEMM: out = sc + x2 + (o1@W1+b1) + (o2@W2+b2), NCHW write --------
// 128x64 tile, virtual K=512 (branch1 then branch2), double-buffered.
__global__ __launch_bounds__(256) void k_final(
    const float* __restrict__ oh1, const float* __restrict__ ow1,
    const float* __restrict__ oh2, const float* __restrict__ ow2,
    const float* __restrict__ W1, const float* __restrict__ W2,
    const float* __restrict__ b1, const float* __restrict__ b2,
    const float* __restrict__ p1, const float* __restrict__ x2,
    float* __restrict__ out) {
    __shared__ float As[2][16][132];   // k-fastest loads; pad to 132 for banks
    __shared__ float Bs[2][16][64];
    int t0 = blockIdx.x * 128, o0 = blockIdx.y * 64;
    int tid = threadIdx.x;
    int ty = tid >> 4, tx = tid & 15;

    // tile 0 (kb=0 -> branch1)
#pragma unroll
    for (int j = 0; j < 2; j++) {
        int i = tid + 256 * j; int kk4 = i & 3, tt = i >> 2;
        float4 va = *(const float4*)&oh1[(size_t)(t0 + tt) * 256 + kk4 * 4];
        float4 vb = *(const float4*)&ow1[(size_t)(t0 + tt) * 256 + kk4 * 4];
        As[0][kk4 * 4 + 0][tt] = va.x + vb.x;
        As[0][kk4 * 4 + 1][tt] = va.y + vb.y;
        As[0][kk4 * 4 + 2][tt] = va.z + vb.z;
        As[0][kk4 * 4 + 3][tt] = va.w + vb.w;
    }
#pragma unroll
    for (int j = 0; j < 4; j++) {
        int i = tid + 256 * j; int kk = i >> 6, oo = i & 63;
        Bs[0][kk][oo] = W1[kk * 256 + o0 + oo];
    }
    __syncthreads();

    float acc[8][4] = {};
    int cur = 0;
    for (int kt = 0; kt < 32; kt++) {
        float ra[2][4], rb[4];
        if (kt + 1 < 32) {
            int kbn = (kt + 1) << 4;
            const float* A0 = (kbn < 256) ? oh1 : oh2;
            const float* A1 = (kbn < 256) ? ow1 : ow2;
            const float* W  = (kbn < 256) ? W1 : W2;
            int kboff = kbn & 255;
#pragma unroll
            for (int j = 0; j < 2; j++) {
                int i = tid + 256 * j; int kk4 = i & 3, tt = i >> 2;
                float4 va = *(const float4*)&A0[(size_t)(t0 + tt) * 256 + kboff + kk4 * 4];
                float4 vb = *(const float4*)&A1[(size_t)(t0 + tt) * 256 + kboff + kk4 * 4];
                ra[j][0] = va.x + vb.x; ra[j][1] = va.y + vb.y;
                ra[j][2] = va.z + vb.z; ra[j][3] = va.w + vb.w;
            }
#pragma unroll
            for (int j = 0; j < 4; j++) {
                int i = tid + 256 * j; int kk = i >> 6, oo = i & 63;
                rb[j] = W[(kboff + kk) * 256 + o0 + oo];
            }
        }
#pragma unroll
        for (int kk = 0; kk < 16; kk++) {
            float4 a0 = *(const float4*)&As[cur][kk][ty * 8];
            float4 a1 = *(const float4*)&As[cur][kk][ty * 8 + 4];
            float4 bb = *(const float4*)&Bs[cur][kk][tx * 4];
            float av[8] = {a0.x, a0.y, a0.z, a0.w, a1.x, a1.y, a1.z, a1.w};
            float bv[4] = {bb.x, bb.y, bb.z, bb.w};
#pragma unroll
            for (int r = 0; r < 8; r++)
#pragma unroll
                for (int c = 0; c < 4; c++)
                    acc[r][c] += av[r] * bv[c];
        }
        if (kt + 1 < 32) {
            int nb = cur ^ 1;
#pragma unroll
            for (int j = 0; j < 2; j++) {
                int i = tid + 256 * j; int kk4 = i & 3, tt = i >> 2;
                As[nb][kk4 * 4 + 0][tt] = ra[j][0];
                As[nb][kk4 * 4 + 1][tt] = ra[j][1];
                As[nb][kk4 * 4 + 2][tt] = ra[j][2];
                As[nb][kk4 * 4 + 3][tt] = ra[j][3];
            }
#pragma unroll
            for (int j = 0; j < 4; j++) {
                int i = tid + 256 * j; int kk = i >> 6, oo = i & 63;
                Bs[nb][kk][oo] = rb[j];
            }
            cur = nb;
            __syncthreads();
        }
    }

    int b = t0 >> 12, hw0 = t0 & 4095;
    int ob = o0 + tx * 4;
    float4 b1v = *(const float4*)&b1[ob];
    float4 b2v = *(const float4*)&b2[ob];
#pragma unroll
    for (int r = 0; r < 8; r++) {
        int tt = ty * 8 + r;
        int t = t0 + tt, hw = hw0 + tt;
        float4 sc = *(const float4*)&p1[(size_t)t * 1024 + 768 + ob];  // shortcut cols
        float v[4];
        v[0] = acc[r][0] + b1v.x + b2v.x + sc.x;
        v[1] = acc[r][1] + b1v.y + b2v.y + sc.y;
        v[2] = acc[r][2] + b1v.z + b2v.z + sc.z;
        v[3] = acc[r][3] + b1v.w + b2v.w + sc.w;
#pragma unroll
        for (int c = 0; c < 4; c++) {
            size_t gi = ((size_t)(b * 256 + ob + c)) * HW + hw;
            out[gi] = v[c] + x2[gi];
        }
    }
}

// ---------------- host launch ----------------
extern "C" void kernel_launch(void* const* d_in, const int* in_sizes, int n_in,
                              void* d_out, int out_size) {
    const float* x1      = (const float*)d_in[0];
    const float* x2      = (const float*)d_in[1];
    const float* ln1q_w  = (const float*)d_in[2];
    const float* ln1q_b  = (const float*)d_in[3];
    const float* ln2kv_w = (const float*)d_in[4];
    const float* ln2kv_b = (const float*)d_in[5];
    const float* Wq1     = (const float*)d_in[6];
    const float* Wkv2    = (const float*)d_in[7];
    const float* Wout1   = (const float*)d_in[8];
    const float* bout1   = (const float*)d_in[9];
    const float* ln2q_w  = (const float*)d_in[10];
    const float* ln2q_b  = (const float*)d_in[11];
    const float* ln1kv_w = (const float*)d_in[12];
    const float* ln1kv_b = (const float*)d_in[13];
    const float* Wq2     = (const float*)d_in[14];
    const float* Wkv1    = (const float*)d_in[15];
    const float* Wout2   = (const float*)d_in[16];
    const float* bout2   = (const float*)d_in[17];
    const float* Wsc     = (const float*)d_in[18];
    const float* bn_g    = (const float*)d_in[19];
    const float* bn_b    = (const float*)d_in[20];
    const float* bn_m    = (const float*)d_in[21];
    const float* bn_v    = (const float*)d_in[22];
    float* out = (float*)d_out;

    float *mu1, *rs1, *mu2, *rs2, *p1, *p2, *oh1, *ow1, *oh2, *ow2;
    float *W1cat, *W2cat, *b1cat, *b2cat, *Ssc;
    cudaGetSymbolAddress((void**)&mu1, g_mu1);
    cudaGetSymbolAddress((void**)&rs1, g_rs1);
    cudaGetSymbolAddress((void**)&mu2, g_mu2);
    cudaGetSymbolAddress((void**)&rs2, g_rs2);
    cudaGetSymbolAddress((void**)&p1, g_p1);
    cudaGetSymbolAddress((void**)&p2, g_p2);
    cudaGetSymbolAddress((void**)&oh1, g_oh1);
    cudaGetSymbolAddress((void**)&ow1, g_ow1);
    cudaGetSymbolAddress((void**)&oh2, g_oh2);
    cudaGetSymbolAddress((void**)&ow2, g_ow2);
    cudaGetSymbolAddress((void**)&W1cat, g_W1cat);
    cudaGetSymbolAddress((void**)&W2cat, g_W2cat);
    cudaGetSymbolAddress((void**)&b1cat, g_b1cat);
    cudaGetSymbolAddress((void**)&b2cat, g_b2cat);
    cudaGetSymbolAddress((void**)&Ssc, g_Ssc);

    // weight/bias folding (2 launches)
    k_fold_wcat<<<(384 * 1024 + 256 * 768 + 255) / 256, 256>>>(
        Wq1, ln1q_w, Wkv1, ln1kv_w, Wsc, bn_g, bn_v, Wq2, ln2q_w, Wkv2, ln2kv_w,
        W1cat, W2cat);
    k_fold_bias<<<7, 256>>>(Wq1, ln1q_b, Wkv1, ln1kv_b, Wsc, bn_g, bn_b, bn_m, bn_v,
                            Wq2, ln2q_b, Wkv2, ln2kv_b, b1cat, b2cat, Ssc);

    // LN stats
    k_stats<<<NTOK / 256, 256>>>(x1, 384, mu1, rs1);
    k_stats<<<NTOK / 256, 256>>>(x2, 256, mu2, rs2);

    // fused projections: x1 -> [q1|k1|v1|sc], x2 -> [q2|k2|v2]
    k_proj<<<dim3(256, 16), 256>>>(x1, 384, 1024, mu1, rs1, W1cat, b1cat, Ssc, 768, p1);
    k_proj<<<dim3(256, 12), 256>>>(x2, 256, 768, mu2, rs2, W2cat, b2cat, nullptr, 1 << 30, p2);

    // axial attention: branch1 (q1 x kv2), branch2 (q2 x kv1); axis 0=H, 1=W
    k_attn<<<4096, 128>>>(p1, 1024, p2 + 256, p2 + 512, 768, oh1, 0);
    k_attn<<<4096, 128>>>(p1, 1024, p2 + 256, p2 + 512, 768, ow1, 1);
    k_attn<<<4096, 128>>>(p2, 768, p1 + 256, p1 + 512, 1024, oh2, 0);
    k_attn<<<4096, 128>>>(p2, 768, p1 + 256, p1 + 512, 1024, ow2, 1);

    // output GEMMs + shortcut + residual + NCHW transpose
    k_final<<<dim3(256, 4), 256>>>(oh1, ow1, oh2, ow2, Wout1, Wout2, bout1, bout2,
                                   p1, x2, out);
}

// round 6
// speedup vs baseline: 2.4110x; 1.4451x over previous
#include <cuda_runtime.h>
#include <math.h>
#include <stdint.h>

#define NTOK 32768
#define HW 4096
#define EPSV 1e-5f

// ---------------- scratch (static device memory; no allocations) ----------------
__device__ float g_mu1[NTOK], g_rs1[NTOK], g_mu2[NTOK], g_rs2[NTOK];
__device__ float g_p1[NTOK * 1024];   // per token: [q1(256) | k1(256) | v1(256) | sc(256)]
__device__ float g_p2[NTOK * 768];    // per token: [q2(256) | k2(256) | v2(256)]
__device__ float g_oh1[NTOK * 256], g_ow1[NTOK * 256];
__device__ float g_oh2[NTOK * 256], g_ow2[NTOK * 256];
__device__ float g_W1cat[384 * 1024];  // [C=384][q1|k1|v1|sc] folded
__device__ float g_W2cat[256 * 768];   // [C=256][q2|k2|v2] folded
__device__ float g_b1cat[1024], g_b2cat[768], g_Ssc[256];

// ---------------- tf32 helpers ----------------
__device__ __forceinline__ float to_tf32(float x) {
    float y;
    asm("cvt.rna.tf32.f32 %0, %1;" : "=f"(y) : "f"(x));
    return y;
}

__device__ __forceinline__ void mma_tf32(float* d, const uint32_t* a, const uint32_t* b) {
    asm volatile(
        "mma.sync.aligned.m16n8k8.row.col.f32.tf32.tf32.f32 "
        "{%0,%1,%2,%3}, {%4,%5,%6,%7}, {%8,%9}, {%0,%1,%2,%3};\n"
        : "+f"(d[0]), "+f"(d[1]), "+f"(d[2]), "+f"(d[3])
        : "r"(a[0]), "r"(a[1]), "r"(a[2]), "r"(a[3]), "r"(b[0]), "r"(b[1]));
}

// ---------------- fold all weights into two concatenated GEMM-B matrices ----------------
__global__ void k_fold_wcat(const float* __restrict__ Wq1, const float* __restrict__ ln1qw,
                            const float* __restrict__ Wkv1, const float* __restrict__ ln1kvw,
                            const float* __restrict__ Wsc, const float* __restrict__ bng,
                            const float* __restrict__ bnv,
                            const float* __restrict__ Wq2, const float* __restrict__ ln2qw,
                            const float* __restrict__ Wkv2, const float* __restrict__ ln2kvw,
                            float* __restrict__ W1cat, float* __restrict__ W2cat) {
    int idx = blockIdx.x * 256 + threadIdx.x;
    const int N1 = 384 * 1024;
    if (idx < N1) {
        int c = idx >> 10, o = idx & 1023;
        float v;
        if (o < 256)      v = Wq1[c * 256 + o] * ln1qw[c];
        else if (o < 768) v = Wkv1[c * 512 + (o - 256)] * ln1kvw[c];
        else { int oo = o - 768; v = Wsc[oo * 384 + c] * bng[oo] * rsqrtf(bnv[oo] + EPSV); }
        W1cat[idx] = v;
    } else if (idx < N1 + 256 * 768) {
        int i2 = idx - N1;
        int c = i2 / 768, o = i2 % 768;
        float v;
        if (o < 256) v = Wq2[c * 256 + o] * ln2qw[c];
        else         v = Wkv2[c * 512 + (o - 256)] * ln2kvw[c];
        W2cat[i2] = v;
    }
}

__global__ void k_fold_bias(const float* __restrict__ Wq1, const float* __restrict__ ln1qb,
                            const float* __restrict__ Wkv1, const float* __restrict__ ln1kvb,
                            const float* __restrict__ Wsc, const float* __restrict__ bng,
                            const float* __restrict__ bnb, const float* __restrict__ bnm,
                            const float* __restrict__ bnv,
                            const float* __restrict__ Wq2, const float* __restrict__ ln2qb,
                            const float* __restrict__ Wkv2, const float* __restrict__ ln2kvb,
                            float* __restrict__ b1cat, float* __restrict__ b2cat,
                            float* __restrict__ Ssc) {
    int og = blockIdx.x * 256 + threadIdx.x;
    if (og < 1024) {
        float b = 0.f;
        if (og < 256) {
            for (int c = 0; c < 384; c++) b += ln1qb[c] * Wq1[c * 256 + og];
        } else if (og < 768) {
            int o = og - 256;
            for (int c = 0; c < 384; c++) b += ln1kvb[c] * Wkv1[c * 512 + o];
        } else {
            int oo = og - 768;
            float g = bng[oo] * rsqrtf(bnv[oo] + EPSV);
            b = bnb[oo] - bnm[oo] * g;
            float s = 0.f;
            for (int c = 0; c < 384; c++) s += Wsc[oo * 384 + c];
            Ssc[oo] = s * g;
        }
        b1cat[og] = b;
    } else if (og < 1792) {
        int o2 = og - 1024;
        float b = 0.f;
        if (o2 < 256) {
            for (int c = 0; c < 256; c++) b += ln2qb[c] * Wq2[c * 256 + o2];
        } else {
            int o = o2 - 256;
            for (int c = 0; c < 256; c++) b += ln2kvb[c] * Wkv2[c * 512 + o];
        }
        b2cat[o2] = b;
    }
}

// ---------------- per-token LN statistics: 8-way channel-split, block = 32 tok x 8 slices ----
__global__ void k_stats(const float* __restrict__ X, int C,
                        float* __restrict__ mu, float* __restrict__ rs) {
    __shared__ float ss[8][33], sq[8][33];
    int lane = threadIdx.x & 31, cs = threadIdx.x >> 5;
    int t = blockIdx.x * 32 + lane;
    int b = t >> 12, hw = t & 4095;
    const float* p = X + (size_t)b * C * HW + hw;
    float s = 0.f, s2 = 0.f;
    for (int c = cs; c < C; c += 8) {
        float v = p[(size_t)c * HW];
        s += v; s2 += v * v;
    }
    ss[cs][lane] = s; sq[cs][lane] = s2;
    __syncthreads();
    if (threadIdx.x < 32) {
        float a = 0.f, q = 0.f;
#pragma unroll
        for (int j = 0; j < 8; j++) { a += ss[j][lane]; q += sq[j][lane]; }
        float m = a / C;
        mu[t] = m;
        rs[t] = rsqrtf(q / C - m * m + EPSV);
    }
}

// ---------------- tensor-core projection GEMM (tf32): 128x128 tile, BK=16, 8 warps ----------
// out[t,:] = LN(x)[t,:] @ Wcat (+ BN-shortcut epilogue on columns >= sc_start)
__global__ __launch_bounds__(256) void k_proj(
    const float* __restrict__ X, int C, int Nout,
    const float* __restrict__ mu, const float* __restrict__ rs,
    const float* __restrict__ W, const float* __restrict__ bias,
    const float* __restrict__ S, int sc_start,
    float* __restrict__ out) {
    __shared__ float As[2][16][132];
    __shared__ float Bs[2][16][132];
    __shared__ float smu[128], srs[128];
    int t0 = blockIdx.x * 128, o0 = blockIdx.y * 128;
    int tid = threadIdx.x;
    if (tid < 128) { smu[tid] = mu[t0 + tid]; srs[tid] = rs[t0 + tid]; }
    __syncthreads();
    int bb = t0 >> 12, hw0 = t0 & 4095;
    const float* Xb = X + (size_t)bb * C * HW + hw0;

    // tile 0
#pragma unroll
    for (int j = 0; j < 8; j++) {
        int i = tid + 256 * j; int kk = i >> 7, tt = i & 127;
        As[0][kk][tt] = to_tf32((Xb[(size_t)kk * HW + tt] - smu[tt]) * srs[tt]);
    }
#pragma unroll
    for (int j = 0; j < 8; j++) {
        int i = tid + 256 * j; int kk = i >> 7, oo = i & 127;
        Bs[0][kk][oo] = to_tf32(W[kk * Nout + o0 + oo]);
    }
    __syncthreads();

    int warp = tid >> 5, lane = tid & 31;
    int warpM = warp >> 2, warpN = warp & 3;     // warp tile: 64 rows x 32 cols
    int grp = lane >> 2, tig = lane & 3;
    float acc[4][4][4] = {};
    int KT = C >> 4;
    int cur = 0;
    for (int kt = 0; kt < KT; kt++) {
        float ra[8], rb[8];
        if (kt + 1 < KT) {
            int k0n = (kt + 1) << 4;
#pragma unroll
            for (int j = 0; j < 8; j++) {
                int i = tid + 256 * j; int kk = i >> 7, tt = i & 127;
                ra[j] = Xb[(size_t)(k0n + kk) * HW + tt];
            }
#pragma unroll
            for (int j = 0; j < 8; j++) {
                int i = tid + 256 * j; int kk = i >> 7, oo = i & 127;
                rb[j] = W[(k0n + kk) * Nout + o0 + oo];
            }
        }
#pragma unroll
        for (int k8 = 0; k8 < 16; k8 += 8) {
            uint32_t af[4][4], bf[4][2];
#pragma unroll
            for (int mm = 0; mm < 4; mm++) {
                int r = warpM * 64 + mm * 16 + grp;
                af[mm][0] = __float_as_uint(As[cur][k8 + tig][r]);
                af[mm][1] = __float_as_uint(As[cur][k8 + tig][r + 8]);
                af[mm][2] = __float_as_uint(As[cur][k8 + tig + 4][r]);
                af[mm][3] = __float_as_uint(As[cur][k8 + tig + 4][r + 8]);
            }
#pragma unroll
            for (int nn = 0; nn < 4; nn++) {
                int c = warpN * 32 + nn * 8 + grp;
                bf[nn][0] = __float_as_uint(Bs[cur][k8 + tig][c]);
                bf[nn][1] = __float_as_uint(Bs[cur][k8 + tig + 4][c]);
            }
#pragma unroll
            for (int mm = 0; mm < 4; mm++)
#pragma unroll
                for (int nn = 0; nn < 4; nn++)
                    mma_tf32(acc[mm][nn], af[mm], bf[nn]);
        }
        if (kt + 1 < KT) {
            int nb = cur ^ 1;
#pragma unroll
            for (int j = 0; j < 8; j++) {
                int i = tid + 256 * j; int kk = i >> 7, tt = i & 127;
                As[nb][kk][tt] = to_tf32((ra[j] - smu[tt]) * srs[tt]);
            }
#pragma unroll
            for (int j = 0; j < 8; j++) {
                int i = tid + 256 * j; int kk = i >> 7, oo = i & 127;
                Bs[nb][kk][oo] = to_tf32(rb[j]);
            }
            cur = nb;
            __syncthreads();
        }
    }

    bool isc = (o0 >= sc_start);
#pragma unroll
    for (int mm = 0; mm < 4; mm++) {
#pragma unroll
        for (int nn = 0; nn < 4; nn++) {
            int c = o0 + warpN * 32 + nn * 8 + tig * 2;
            float bv0 = bias[c], bv1 = bias[c + 1];
            float sv0 = 0.f, sv1 = 0.f;
            if (isc) { sv0 = S[c - sc_start]; sv1 = S[c + 1 - sc_start]; }
#pragma unroll
            for (int h = 0; h < 2; h++) {
                int r = warpM * 64 + mm * 16 + grp + h * 8;
                float v0 = acc[mm][nn][h * 2], v1 = acc[mm][nn][h * 2 + 1];
                if (isc) {
                    float inv = 1.f / srs[r], m = smu[r];
                    v0 = v0 * inv + m * sv0 + bv0;
                    v1 = v1 * inv + m * sv1 + bv1;
                } else { v0 += bv0; v1 += bv1; }
                float2 w = make_float2(v0, v1);
                *(float2*)&out[(size_t)(t0 + r) * Nout + c] = w;
            }
        }
    }
}

// ---------------- axial attention: one (b, line, head) 64x64 attention per block ----------------
__global__ void k_attn(const float* __restrict__ Q, int qpitch,
                       const float* __restrict__ K, const float* __restrict__ V,
                       int kvpitch, float* __restrict__ O, int axis) {
    __shared__ float Qs[64][36];
    __shared__ float Ks[64][36];
    __shared__ float Vs[64][36];
    __shared__ float S[64][65];
    int bx = blockIdx.x;
    int head = bx & 7, line = (bx >> 3) & 63, b = bx >> 9;
    int tstride = axis ? 1 : 64;
    int tbase = b * 4096 + (axis ? line * 64 : line);
    int hoff = head * 32;
    int tid = threadIdx.x; // 128 threads

    for (int i = tid; i < 64 * 32; i += 128) {
        int r = i >> 5, d = i & 31;
        int t = tbase + r * tstride;
        Qs[r][d] = Q[(size_t)t * qpitch + hoff + d];
        Ks[r][d] = K[(size_t)t * kvpitch + hoff + d];
        Vs[r][d] = V[(size_t)t * kvpitch + hoff + d];
    }
    __syncthreads();

    {
        int si = tid >> 1, j0 = (tid & 1) * 32;
        float4 q[8];
#pragma unroll
        for (int d4 = 0; d4 < 8; d4++) q[d4] = *(const float4*)&Qs[si][d4 * 4];
        const float scale = 0.17677669529663687f; // 1/sqrt(32)
#pragma unroll 4
        for (int j = 0; j < 32; j++) {
            float s = 0.f;
#pragma unroll
            for (int d4 = 0; d4 < 8; d4++) {
                float4 kv = *(const float4*)&Ks[j0 + j][d4 * 4];
                s += q[d4].x * kv.x + q[d4].y * kv.y + q[d4].z * kv.z + q[d4].w * kv.w;
            }
            S[si][j0 + j] = s * scale;
        }
    }
    __syncthreads();

    if (tid < 64) {
        float m = -1e30f;
#pragma unroll 8
        for (int j = 0; j < 64; j++) m = fmaxf(m, S[tid][j]);
        float sum = 0.f;
#pragma unroll 8
        for (int j = 0; j < 64; j++) { float e = __expf(S[tid][j] - m); S[tid][j] = e; sum += e; }
        float inv = 1.f / sum;
#pragma unroll 8
        for (int j = 0; j < 64; j++) S[tid][j] *= inv;
    }
    __syncthreads();

    {
        int oi = tid >> 1, d0 = (tid & 1) * 16;
        float4 acc[4] = {};
        for (int j = 0; j < 64; j++) {
            float p = S[oi][j];
#pragma unroll
            for (int d4 = 0; d4 < 4; d4++) {
                float4 v = *(const float4*)&Vs[j][d0 + d4 * 4];
                acc[d4].x += p * v.x; acc[d4].y += p * v.y;
                acc[d4].z += p * v.z; acc[d4].w += p * v.w;
            }
        }
        int t = tbase + oi * tstride;
#pragma unroll
        for (int d4 = 0; d4 < 4; d4++)
            *(float4*)&O[(size_t)t * 256 + hoff + d0 + d4 * 4] = acc[d4];
    }
}

// ---------------- tensor-core final GEMM (tf32): out = sc + x2 + (o1@W1+b1) + (o2@W2+b2) -----
// 128x128 tile, virtual K=512 (branch1 then branch2), NCHW transposed write.
__global__ __launch_bounds__(256) void k_final(
    const float* __restrict__ oh1, const float* __restrict__ ow1,
    const float* __restrict__ oh2, const float* __restrict__ ow2,
    const float* __restrict__ W1, const float* __restrict__ W2,
    const float* __restrict__ b1, const float* __restrict__ b2,
    const float* __restrict__ p1, const float* __restrict__ x2,
    float* __restrict__ out) {
    __shared__ float As[2][16][132];
    __shared__ float Bs[2][16][132];
    int t0 = blockIdx.x * 128, o0 = blockIdx.y * 128;
    int tid = threadIdx.x;

    // tile 0 (branch1, k=0)
#pragma unroll
    for (int j = 0; j < 2; j++) {
        int i = tid + 256 * j; int kk4 = i & 3, tt = i >> 2;
        float4 va = *(const float4*)&oh1[(size_t)(t0 + tt) * 256 + kk4 * 4];
        float4 vb = *(const float4*)&ow1[(size_t)(t0 + tt) * 256 + kk4 * 4];
        As[0][kk4 * 4 + 0][tt] = to_tf32(va.x + vb.x);
        As[0][kk4 * 4 + 1][tt] = to_tf32(va.y + vb.y);
        As[0][kk4 * 4 + 2][tt] = to_tf32(va.z + vb.z);
        As[0][kk4 * 4 + 3][tt] = to_tf32(va.w + vb.w);
    }
#pragma unroll
    for (int j = 0; j < 8; j++) {
        int i = tid + 256 * j; int kk = i >> 7, oo = i & 127;
        Bs[0][kk][oo] = to_tf32(W1[kk * 256 + o0 + oo]);
    }
    __syncthreads();

    int warp = tid >> 5, lane = tid & 31;
    int warpM = warp >> 2, warpN = warp & 3;
    int grp = lane >> 2, tig = lane & 3;
    float acc[4][4][4] = {};
    int cur = 0;
    for (int kt = 0; kt < 32; kt++) {
        float ra[2][4], rb[8];
        if (kt + 1 < 32) {
            int kbn = (kt + 1) << 4;
            const float* A0 = (kbn < 256) ? oh1 : oh2;
            const float* A1 = (kbn < 256) ? ow1 : ow2;
            const float* W  = (kbn < 256) ? W1 : W2;
            int kboff = kbn & 255;
#pragma unroll
            for (int j = 0; j < 2; j++) {
                int i = tid + 256 * j; int kk4 = i & 3, tt = i >> 2;
                float4 va = *(const float4*)&A0[(size_t)(t0 + tt) * 256 + kboff + kk4 * 4];
                float4 vb = *(const float4*)&A1[(size_t)(t0 + tt) * 256 + kboff + kk4 * 4];
                ra[j][0] = va.x + vb.x; ra[j][1] = va.y + vb.y;
                ra[j][2] = va.z + vb.z; ra[j][3] = va.w + vb.w;
            }
#pragma unroll
            for (int j = 0; j < 8; j++) {
                int i = tid + 256 * j; int kk = i >> 7, oo = i & 127;
                rb[j] = W[(kboff + kk) * 256 + o0 + oo];
            }
        }
#pragma unroll
        for (int k8 = 0; k8 < 16; k8 += 8) {
            uint32_t af[4][4], bf[4][2];
#pragma unroll
            for (int mm = 0; mm < 4; mm++) {
                int r = warpM * 64 + mm * 16 + grp;
                af[mm][0] = __float_as_uint(As[cur][k8 + tig][r]);
                af[mm][1] = __float_as_uint(As[cur][k8 + tig][r + 8]);
                af[mm][2] = __float_as_uint(As[cur][k8 + tig + 4][r]);
                af[mm][3] = __float_as_uint(As[cur][k8 + tig + 4][r + 8]);
            }
#pragma unroll
            for (int nn = 0; nn < 4; nn++) {
                int c = warpN * 32 + nn * 8 + grp;
                bf[nn][0] = __float_as_uint(Bs[cur][k8 + tig][c]);
                bf[nn][1] = __float_as_uint(Bs[cur][k8 + tig + 4][c]);
            }
#pragma unroll
            for (int mm = 0; mm < 4; mm++)
#pragma unroll
                for (int nn = 0; nn < 4; nn++)
                    mma_tf32(acc[mm][nn], af[mm], bf[nn]);
        }
        if (kt + 1 < 32) {
            int nb = cur ^ 1;
#pragma unroll
            for (int j = 0; j < 2; j++) {
                int i = tid + 256 * j; int kk4 = i & 3, tt = i >> 2;
                As[nb][kk4 * 4 + 0][tt] = to_tf32(ra[j][0]);
                As[nb][kk4 * 4 + 1][tt] = to_tf32(ra[j][1]);
                As[nb][kk4 * 4 + 2][tt] = to_tf32(ra[j][2]);
                As[nb][kk4 * 4 + 3][tt] = to_tf32(ra[j][3]);
            }
#pragma unroll
            for (int j = 0; j < 8; j++) {
                int i = tid + 256 * j; int kk = i >> 7, oo = i & 127;
                Bs[nb][kk][oo] = to_tf32(rb[j]);
            }
            cur = nb;
            __syncthreads();
        }
    }

    int b = t0 >> 12, hw0 = t0 & 4095;
#pragma unroll
    for (int mm = 0; mm < 4; mm++) {
#pragma unroll
        for (int nn = 0; nn < 4; nn++) {
            int c = o0 + warpN * 32 + nn * 8 + tig * 2;
            float bv0 = b1[c] + b2[c], bv1 = b1[c + 1] + b2[c + 1];
#pragma unroll
            for (int h = 0; h < 2; h++) {
                int r = warpM * 64 + mm * 16 + grp + h * 8;
                int t = t0 + r, hw = hw0 + r;
                float2 sc = *(const float2*)&p1[(size_t)t * 1024 + 768 + c];
                size_t gi0 = ((size_t)(b * 256 + c)) * HW + hw;
                size_t gi1 = ((size_t)(b * 256 + c + 1)) * HW + hw;
                out[gi0] = acc[mm][nn][h * 2]     + bv0 + sc.x + x2[gi0];
                out[gi1] = acc[mm][nn][h * 2 + 1] + bv1 + sc.y + x2[gi1];
            }
        }
    }
}

// ---------------- host launch ----------------
extern "C" void kernel_launch(void* const* d_in, const int* in_sizes, int n_in,
                              void* d_out, int out_size) {
    const float* x1      = (const float*)d_in[0];
    const float* x2      = (const float*)d_in[1];
    const float* ln1q_w  = (const float*)d_in[2];
    const float* ln1q_b  = (const float*)d_in[3];
    const float* ln2kv_w = (const float*)d_in[4];
    const float* ln2kv_b = (const float*)d_in[5];
    const float* Wq1     = (const float*)d_in[6];
    const float* Wkv2    = (const float*)d_in[7];
    const float* Wout1   = (const float*)d_in[8];
    const float* bout1   = (const float*)d_in[9];
    const float* ln2q_w  = (const float*)d_in[10];
    const float* ln2q_b  = (const float*)d_in[11];
    const float* ln1kv_w = (const float*)d_in[12];
    const float* ln1kv_b = (const float*)d_in[13];
    const float* Wq2     = (const float*)d_in[14];
    const float* Wkv1    = (const float*)d_in[15];
    const float* Wout2   = (const float*)d_in[16];
    const float* bout2   = (const float*)d_in[17];
    const float* Wsc     = (const float*)d_in[18];
    const float* bn_g    = (const float*)d_in[19];
    const float* bn_b    = (const float*)d_in[20];
    const float* bn_m    = (const float*)d_in[21];
    const float* bn_v    = (const float*)d_in[22];
    float* out = (float*)d_out;

    float *mu1, *rs1, *mu2, *rs2, *p1, *p2, *oh1, *ow1, *oh2, *ow2;
    float *W1cat, *W2cat, *b1cat, *b2cat, *Ssc;
    cudaGetSymbolAddress((void**)&mu1, g_mu1);
    cudaGetSymbolAddress((void**)&rs1, g_rs1);
    cudaGetSymbolAddress((void**)&mu2, g_mu2);
    cudaGetSymbolAddress((void**)&rs2, g_rs2);
    cudaGetSymbolAddress((void**)&p1, g_p1);
    cudaGetSymbolAddress((void**)&p2, g_p2);
    cudaGetSymbolAddress((void**)&oh1, g_oh1);
    cudaGetSymbolAddress((void**)&ow1, g_ow1);
    cudaGetSymbolAddress((void**)&oh2, g_oh2);
    cudaGetSymbolAddress((void**)&ow2, g_ow2);
    cudaGetSymbolAddress((void**)&W1cat, g_W1cat);
    cudaGetSymbolAddress((void**)&W2cat, g_W2cat);
    cudaGetSymbolAddress((void**)&b1cat, g_b1cat);
    cudaGetSymbolAddress((void**)&b2cat, g_b2cat);
    cudaGetSymbolAddress((void**)&Ssc, g_Ssc);

    // weight/bias folding
    k_fold_wcat<<<(384 * 1024 + 256 * 768 + 255) / 256, 256>>>(
        Wq1, ln1q_w, Wkv1, ln1kv_w, Wsc, bn_g, bn_v, Wq2, ln2q_w, Wkv2, ln2kv_w,
        W1cat, W2cat);
    k_fold_bias<<<7, 256>>>(Wq1, ln1q_b, Wkv1, ln1kv_b, Wsc, bn_g, bn_b, bn_m, bn_v,
                            Wq2, ln2q_b, Wkv2, ln2kv_b, b1cat, b2cat, Ssc);

    // LN stats
    k_stats<<<NTOK / 32, 256>>>(x1, 384, mu1, rs1);
    k_stats<<<NTOK / 32, 256>>>(x2, 256, mu2, rs2);

    // fused projections (tf32 tensor cores): x1 -> [q1|k1|v1|sc], x2 -> [q2|k2|v2]
    k_proj<<<dim3(256, 8), 256>>>(x1, 384, 1024, mu1, rs1, W1cat, b1cat, Ssc, 768, p1);
    k_proj<<<dim3(256, 6), 256>>>(x2, 256, 768, mu2, rs2, W2cat, b2cat, b2cat, 1 << 30, p2);

    // axial attention: branch1 (q1 x kv2), branch2 (q2 x kv1); axis 0=H, 1=W
    k_attn<<<4096, 128>>>(p1, 1024, p2 + 256, p2 + 512, 768, oh1, 0);
    k_attn<<<4096, 128>>>(p1, 1024, p2 + 256, p2 + 512, 768, ow1, 1);
    k_attn<<<4096, 128>>>(p2, 768, p1 + 256, p1 + 512, 1024, oh2, 0);
    k_attn<<<4096, 128>>>(p2, 768, p1 + 256, p1 + 512, 1024, ow2, 1);

    // output GEMMs + shortcut + residual + NCHW transpose (tf32 tensor cores)
    k_final<<<dim3(256, 2), 256>>>(oh1, ow1, oh2, ow2, Wout1, Wout2, bout1, bout2,
                                   p1, x2, out);
}

// round 7
// speedup vs baseline: 2.8875x; 1.1976x over previous
#include <cuda_runtime.h>
#include <math.h>
#include <stdint.h>

#define NTOK 32768
#define HW 4096
#define EPSV 1e-5f

// ---------------- scratch (static device memory; no allocations) ----------------
__device__ float g_mu1[NTOK], g_rs1[NTOK], g_mu2[NTOK], g_rs2[NTOK];
__device__ float g_p1[NTOK * 1024];   // per token: [q1(256) | k1(256) | v1(256) | sc(256)]
__device__ float g_p2[NTOK * 768];    // per token: [q2(256) | k2(256) | v2(256)]
__device__ float g_o1[NTOK * 256];    // branch1 attention out (axis0 + axis1 accumulated)
__device__ float g_o2[NTOK * 256];    // branch2 attention out
__device__ float g_W1cat[384 * 1024];  // [C=384][q1|k1|v1|sc] folded
__device__ float g_W2cat[256 * 768];   // [C=256][q2|k2|v2] folded
__device__ float g_b1cat[1024], g_b2cat[768], g_Ssc[256];

// ---------------- tf32 helpers ----------------
__device__ __forceinline__ float to_tf32(float x) {
    float y;
    asm("cvt.rna.tf32.f32 %0, %1;" : "=f"(y) : "f"(x));
    return y;
}

__device__ __forceinline__ void mma_tf32(float* d, const uint32_t* a, const uint32_t* b) {
    asm volatile(
        "mma.sync.aligned.m16n8k8.row.col.f32.tf32.tf32.f32 "
        "{%0,%1,%2,%3}, {%4,%5,%6,%7}, {%8,%9}, {%0,%1,%2,%3};\n"
        : "+f"(d[0]), "+f"(d[1]), "+f"(d[2]), "+f"(d[3])
        : "r"(a[0]), "r"(a[1]), "r"(a[2]), "r"(a[3]), "r"(b[0]), "r"(b[1]));
}

// ---------------- fold all weights into two concatenated GEMM-B matrices ----------------
__global__ void k_fold_wcat(const float* __restrict__ Wq1, const float* __restrict__ ln1qw,
                            const float* __restrict__ Wkv1, const float* __restrict__ ln1kvw,
                            const float* __restrict__ Wsc, const float* __restrict__ bng,
                            const float* __restrict__ bnv,
                            const float* __restrict__ Wq2, const float* __restrict__ ln2qw,
                            const float* __restrict__ Wkv2, const float* __restrict__ ln2kvw,
                            float* __restrict__ W1cat, float* __restrict__ W2cat) {
    int idx = blockIdx.x * 256 + threadIdx.x;
    const int N1 = 384 * 1024;
    if (idx < N1) {
        int c = idx >> 10, o = idx & 1023;
        float v;
        if (o < 256)      v = Wq1[c * 256 + o] * ln1qw[c];
        else if (o < 768) v = Wkv1[c * 512 + (o - 256)] * ln1kvw[c];
        else { int oo = o - 768; v = Wsc[oo * 384 + c] * bng[oo] * rsqrtf(bnv[oo] + EPSV); }
        W1cat[idx] = v;
    } else if (idx < N1 + 256 * 768) {
        int i2 = idx - N1;
        int c = i2 / 768, o = i2 % 768;
        float v;
        if (o < 256) v = Wq2[c * 256 + o] * ln2qw[c];
        else         v = Wkv2[c * 512 + (o - 256)] * ln2kvw[c];
        W2cat[i2] = v;
    }
}

__global__ void k_fold_bias(const float* __restrict__ Wq1, const float* __restrict__ ln1qb,
                            const float* __restrict__ Wkv1, const float* __restrict__ ln1kvb,
                            const float* __restrict__ Wsc, const float* __restrict__ bng,
                            const float* __restrict__ bnb, const float* __restrict__ bnm,
                            const float* __restrict__ bnv,
                            const float* __restrict__ Wq2, const float* __restrict__ ln2qb,
                            const float* __restrict__ Wkv2, const float* __restrict__ ln2kvb,
                            float* __restrict__ b1cat, float* __restrict__ b2cat,
                            float* __restrict__ Ssc) {
    int og = blockIdx.x * 256 + threadIdx.x;
    if (og < 1024) {
        float b = 0.f;
        if (og < 256) {
            for (int c = 0; c < 384; c++) b += ln1qb[c] * Wq1[c * 256 + og];
        } else if (og < 768) {
            int o = og - 256;
            for (int c = 0; c < 384; c++) b += ln1kvb[c] * Wkv1[c * 512 + o];
        } else {
            int oo = og - 768;
            float g = bng[oo] * rsqrtf(bnv[oo] + EPSV);
            b = bnb[oo] - bnm[oo] * g;
            float s = 0.f;
            for (int c = 0; c < 384; c++) s += Wsc[oo * 384 + c];
            Ssc[oo] = s * g;
        }
        b1cat[og] = b;
    } else if (og < 1792) {
        int o2 = og - 1024;
        float b = 0.f;
        if (o2 < 256) {
            for (int c = 0; c < 256; c++) b += ln2qb[c] * Wq2[c * 256 + o2];
        } else {
            int o = o2 - 256;
            for (int c = 0; c < 256; c++) b += ln2kvb[c] * Wkv2[c * 512 + o];
        }
        b2cat[o2] = b;
    }
}

// ---------------- per-token LN statistics: 8-way channel-split, block = 32 tok x 8 slices ----
__global__ void k_stats(const float* __restrict__ X, int C,
                        float* __restrict__ mu, float* __restrict__ rs) {
    __shared__ float ss[8][33], sq[8][33];
    int lane = threadIdx.x & 31, cs = threadIdx.x >> 5;
    int t = blockIdx.x * 32 + lane;
    int b = t >> 12, hw = t & 4095;
    const float* p = X + (size_t)b * C * HW + hw;
    float s = 0.f, s2 = 0.f;
    for (int c = cs; c < C; c += 8) {
        float v = p[(size_t)c * HW];
        s += v; s2 += v * v;
    }
    ss[cs][lane] = s; sq[cs][lane] = s2;
    __syncthreads();
    if (threadIdx.x < 32) {
        float a = 0.f, q = 0.f;
#pragma unroll
        for (int j = 0; j < 8; j++) { a += ss[j][lane]; q += sq[j][lane]; }
        float m = a / C;
        mu[t] = m;
        rs[t] = rsqrtf(q / C - m * m + EPSV);
    }
}

// ---------------- tensor-core projection GEMM (tf32): 128x128 tile, BK=16, 8 warps ----------
__global__ __launch_bounds__(256) void k_proj(
    const float* __restrict__ X, int C, int Nout,
    const float* __restrict__ mu, const float* __restrict__ rs,
    const float* __restrict__ W, const float* __restrict__ bias,
    const float* __restrict__ S, int sc_start,
    float* __restrict__ out) {
    __shared__ float As[2][16][132];
    __shared__ float Bs[2][16][132];
    __shared__ float smu[128], srs[128];
    int t0 = blockIdx.x * 128, o0 = blockIdx.y * 128;
    int tid = threadIdx.x;
    if (tid < 128) { smu[tid] = mu[t0 + tid]; srs[tid] = rs[t0 + tid]; }
    __syncthreads();
    int bb = t0 >> 12, hw0 = t0 & 4095;
    const float* Xb = X + (size_t)bb * C * HW + hw0;

#pragma unroll
    for (int j = 0; j < 8; j++) {
        int i = tid + 256 * j; int kk = i >> 7, tt = i & 127;
        As[0][kk][tt] = to_tf32((Xb[(size_t)kk * HW + tt] - smu[tt]) * srs[tt]);
    }
#pragma unroll
    for (int j = 0; j < 8; j++) {
        int i = tid + 256 * j; int kk = i >> 7, oo = i & 127;
        Bs[0][kk][oo] = to_tf32(W[kk * Nout + o0 + oo]);
    }
    __syncthreads();

    int warp = tid >> 5, lane = tid & 31;
    int warpM = warp >> 2, warpN = warp & 3;
    int grp = lane >> 2, tig = lane & 3;
    float acc[4][4][4] = {};
    int KT = C >> 4;
    int cur = 0;
    for (int kt = 0; kt < KT; kt++) {
        float ra[8], rb[8];
        if (kt + 1 < KT) {
            int k0n = (kt + 1) << 4;
#pragma unroll
            for (int j = 0; j < 8; j++) {
                int i = tid + 256 * j; int kk = i >> 7, tt = i & 127;
                ra[j] = Xb[(size_t)(k0n + kk) * HW + tt];
            }
#pragma unroll
            for (int j = 0; j < 8; j++) {
                int i = tid + 256 * j; int kk = i >> 7, oo = i & 127;
                rb[j] = W[(k0n + kk) * Nout + o0 + oo];
            }
        }
#pragma unroll
        for (int k8 = 0; k8 < 16; k8 += 8) {
            uint32_t af[4][4], bf[4][2];
#pragma unroll
            for (int mm = 0; mm < 4; mm++) {
                int r = warpM * 64 + mm * 16 + grp;
                af[mm][0] = __float_as_uint(As[cur][k8 + tig][r]);
                af[mm][1] = __float_as_uint(As[cur][k8 + tig][r + 8]);
                af[mm][2] = __float_as_uint(As[cur][k8 + tig + 4][r]);
                af[mm][3] = __float_as_uint(As[cur][k8 + tig + 4][r + 8]);
            }
#pragma unroll
            for (int nn = 0; nn < 4; nn++) {
                int c = warpN * 32 + nn * 8 + grp;
                bf[nn][0] = __float_as_uint(Bs[cur][k8 + tig][c]);
                bf[nn][1] = __float_as_uint(Bs[cur][k8 + tig + 4][c]);
            }
#pragma unroll
            for (int mm = 0; mm < 4; mm++)
#pragma unroll
                for (int nn = 0; nn < 4; nn++)
                    mma_tf32(acc[mm][nn], af[mm], bf[nn]);
        }
        if (kt + 1 < KT) {
            int nb = cur ^ 1;
#pragma unroll
            for (int j = 0; j < 8; j++) {
                int i = tid + 256 * j; int kk = i >> 7, tt = i & 127;
                As[nb][kk][tt] = to_tf32((ra[j] - smu[tt]) * srs[tt]);
            }
#pragma unroll
            for (int j = 0; j < 8; j++) {
                int i = tid + 256 * j; int kk = i >> 7, oo = i & 127;
                Bs[nb][kk][oo] = to_tf32(rb[j]);
            }
            cur = nb;
            __syncthreads();
        }
    }

    bool isc = (o0 >= sc_start);
#pragma unroll
    for (int mm = 0; mm < 4; mm++) {
#pragma unroll
        for (int nn = 0; nn < 4; nn++) {
            int c = o0 + warpN * 32 + nn * 8 + tig * 2;
            float bv0 = bias[c], bv1 = bias[c + 1];
            float sv0 = 0.f, sv1 = 0.f;
            if (isc) { sv0 = S[c - sc_start]; sv1 = S[c + 1 - sc_start]; }
#pragma unroll
            for (int h = 0; h < 2; h++) {
                int r = warpM * 64 + mm * 16 + grp + h * 8;
                float v0 = acc[mm][nn][h * 2], v1 = acc[mm][nn][h * 2 + 1];
                if (isc) {
                    float inv = 1.f / srs[r], m = smu[r];
                    v0 = v0 * inv + m * sv0 + bv0;
                    v1 = v1 * inv + m * sv1 + bv1;
                } else { v0 += bv0; v1 += bv1; }
                float2 w = make_float2(v0, v1);
                *(float2*)&out[(size_t)(t0 + r) * Nout + c] = w;
            }
        }
    }
}

// ---------------- axial attention (tf32 tensor cores) ----------------
// One (b, line, head) 64x64x32 attention per block, 128 threads = 4 warps.
// Warp w handles rows [w*16, w*16+16). accum!=0: add into O (axis-1 pass).
__global__ __launch_bounds__(128) void k_attn(
    const float* __restrict__ Q, int qpitch,
    const float* __restrict__ K, const float* __restrict__ V,
    int kvpitch, float* __restrict__ O, int axis, int accum) {
    __shared__ float Qs[64][36];
    __shared__ float Ks[64][36];
    __shared__ float Vs[64][36];
    __shared__ float S[64][68];
    int bx = blockIdx.x;
    int head = bx & 7, line = (bx >> 3) & 63, b = bx >> 9;
    int tstride = axis ? 1 : 64;
    int tbase = b * 4096 + (axis ? line * 64 : line);
    int hoff = head * 32;
    int tid = threadIdx.x;
    const float scale = 0.17677669529663687f; // 1/sqrt(32), folded into Q

    for (int i = tid; i < 64 * 32; i += 128) {
        int r = i >> 5, d = i & 31;
        int t = tbase + r * tstride;
        Qs[r][d] = to_tf32(Q[(size_t)t * qpitch + hoff + d] * scale);
        Ks[r][d] = to_tf32(K[(size_t)t * kvpitch + hoff + d]);
        Vs[r][d] = to_tf32(V[(size_t)t * kvpitch + hoff + d]);
    }
    __syncthreads();

    int warp = tid >> 5, lane = tid & 31;
    int grp = lane >> 2, tig = lane & 3;
    int m0 = warp * 16;

    // ---- S = (Q*scale) K^T : M=16/warp, N=64, K=32 ----
    {
        uint32_t af[4][4];
#pragma unroll
        for (int k8 = 0; k8 < 4; k8++) {
            af[k8][0] = __float_as_uint(Qs[m0 + grp][k8 * 8 + tig]);
            af[k8][1] = __float_as_uint(Qs[m0 + grp + 8][k8 * 8 + tig]);
            af[k8][2] = __float_as_uint(Qs[m0 + grp][k8 * 8 + tig + 4]);
            af[k8][3] = __float_as_uint(Qs[m0 + grp + 8][k8 * 8 + tig + 4]);
        }
#pragma unroll
        for (int n8 = 0; n8 < 8; n8++) {
            float sacc[4] = {};
#pragma unroll
            for (int k8 = 0; k8 < 4; k8++) {
                uint32_t bf[2];
                bf[0] = __float_as_uint(Ks[n8 * 8 + grp][k8 * 8 + tig]);
                bf[1] = __float_as_uint(Ks[n8 * 8 + grp][k8 * 8 + tig + 4]);
                mma_tf32(sacc, af[k8], bf);
            }
            // C frag: (grp, tig*2),(grp,tig*2+1),(grp+8,tig*2),(grp+8,tig*2+1)
            *(float2*)&S[m0 + grp][n8 * 8 + tig * 2]     = make_float2(sacc[0], sacc[1]);
            *(float2*)&S[m0 + grp + 8][n8 * 8 + tig * 2] = make_float2(sacc[2], sacc[3]);
        }
    }
    __syncthreads();

    // ---- softmax: 2 threads per row (halves combined via shfl) ----
    {
        int row = tid >> 1, half = tid & 1;
        float* sr = &S[row][half * 32];
        float ev[32];
        float m = -1e30f;
#pragma unroll 8
        for (int j = 0; j < 32; j++) m = fmaxf(m, sr[j]);
        m = fmaxf(m, __shfl_xor_sync(0xffffffffu, m, 1));
        float sum = 0.f;
#pragma unroll 8
        for (int j = 0; j < 32; j++) { ev[j] = __expf(sr[j] - m); sum += ev[j]; }
        sum += __shfl_xor_sync(0xffffffffu, sum, 1);
        float inv = 1.f / sum;
#pragma unroll 8
        for (int j = 0; j < 32; j++) sr[j] = to_tf32(ev[j] * inv);
    }
    __syncthreads();

    // ---- O = P V : M=16/warp, N=32, K=64 ----
    {
        float oacc[4][4] = {};
#pragma unroll
        for (int k8 = 0; k8 < 8; k8++) {
            uint32_t af[4];
            af[0] = __float_as_uint(S[m0 + grp][k8 * 8 + tig]);
            af[1] = __float_as_uint(S[m0 + grp + 8][k8 * 8 + tig]);
            af[2] = __float_as_uint(S[m0 + grp][k8 * 8 + tig + 4]);
            af[3] = __float_as_uint(S[m0 + grp + 8][k8 * 8 + tig + 4]);
#pragma unroll
            for (int nn = 0; nn < 4; nn++) {
                uint32_t bf[2];
                bf[0] = __float_as_uint(Vs[k8 * 8 + tig][nn * 8 + grp]);
                bf[1] = __float_as_uint(Vs[k8 * 8 + tig + 4][nn * 8 + grp]);
                mma_tf32(oacc[nn], af, bf);
            }
        }
        int ta = tbase + (m0 + grp) * tstride;
        int tb = tbase + (m0 + grp + 8) * tstride;
        float* Oa = O + (size_t)ta * 256 + hoff;
        float* Ob = O + (size_t)tb * 256 + hoff;
#pragma unroll
        for (int nn = 0; nn < 4; nn++) {
            int c = nn * 8 + tig * 2;
            float2 v0 = make_float2(oacc[nn][0], oacc[nn][1]);
            float2 v1 = make_float2(oacc[nn][2], oacc[nn][3]);
            if (accum) {
                float2 p0 = *(float2*)&Oa[c], p1 = *(float2*)&Ob[c];
                v0.x += p0.x; v0.y += p0.y; v1.x += p1.x; v1.y += p1.y;
            }
            *(float2*)&Oa[c] = v0;
            *(float2*)&Ob[c] = v1;
        }
    }
}

// ---------------- tensor-core final GEMM (tf32): out = sc + x2 + o1@W1 + o2@W2 + b ----------
// 128x128 tile, virtual K=512 (branch1 then branch2), NCHW transposed write.
__global__ __launch_bounds__(256) void k_final(
    const float* __restrict__ o1, const float* __restrict__ o2,
    const float* __restrict__ W1, const float* __restrict__ W2,
    const float* __restrict__ b1, const float* __restrict__ b2,
    const float* __restrict__ p1, const float* __restrict__ x2,
    float* __restrict__ out) {
    __shared__ float As[2][16][132];
    __shared__ float Bs[2][16][132];
    int t0 = blockIdx.x * 128, o0 = blockIdx.y * 128;
    int tid = threadIdx.x;

    // tile 0 (branch1, k=0)
#pragma unroll
    for (int j = 0; j < 2; j++) {
        int i = tid + 256 * j; int kk4 = i & 3, tt = i >> 2;
        float4 va = *(const float4*)&o1[(size_t)(t0 + tt) * 256 + kk4 * 4];
        As[0][kk4 * 4 + 0][tt] = to_tf32(va.x);
        As[0][kk4 * 4 + 1][tt] = to_tf32(va.y);
        As[0][kk4 * 4 + 2][tt] = to_tf32(va.z);
        As[0][kk4 * 4 + 3][tt] = to_tf32(va.w);
    }
#pragma unroll
    for (int j = 0; j < 8; j++) {
        int i = tid + 256 * j; int kk = i >> 7, oo = i & 127;
        Bs[0][kk][oo] = to_tf32(W1[kk * 256 + o0 + oo]);
    }
    __syncthreads();

    int warp = tid >> 5, lane = tid & 31;
    int warpM = warp >> 2, warpN = warp & 3;
    int grp = lane >> 2, tig = lane & 3;
    float acc[4][4][4] = {};
    int cur = 0;
    for (int kt = 0; kt < 32; kt++) {
        float ra[2][4], rb[8];
        if (kt + 1 < 32) {
            int kbn = (kt + 1) << 4;
            const float* A0 = (kbn < 256) ? o1 : o2;
            const float* W  = (kbn < 256) ? W1 : W2;
            int kboff = kbn & 255;
#pragma unroll
            for (int j = 0; j < 2; j++) {
                int i = tid + 256 * j; int kk4 = i & 3, tt = i >> 2;
                float4 va = *(const float4*)&A0[(size_t)(t0 + tt) * 256 + kboff + kk4 * 4];
                ra[j][0] = va.x; ra[j][1] = va.y; ra[j][2] = va.z; ra[j][3] = va.w;
            }
#pragma unroll
            for (int j = 0; j < 8; j++) {
                int i = tid + 256 * j; int kk = i >> 7, oo = i & 127;
                rb[j] = W[(kboff + kk) * 256 + o0 + oo];
            }
        }
#pragma unroll
        for (int k8 = 0; k8 < 16; k8 += 8) {
            uint32_t af[4][4], bf[4][2];
#pragma unroll
            for (int mm = 0; mm < 4; mm++) {
                int r = warpM * 64 + mm * 16 + grp;
                af[mm][0] = __float_as_uint(As[cur][k8 + tig][r]);
                af[mm][1] = __float_as_uint(As[cur][k8 + tig][r + 8]);
                af[mm][2] = __float_as_uint(As[cur][k8 + tig + 4][r]);
                af[mm][3] = __float_as_uint(As[cur][k8 + tig + 4][r + 8]);
            }
#pragma unroll
            for (int nn = 0; nn < 4; nn++) {
                int c = warpN * 32 + nn * 8 + grp;
                bf[nn][0] = __float_as_uint(Bs[cur][k8 + tig][c]);
                bf[nn][1] = __float_as_uint(Bs[cur][k8 + tig + 4][c]);
            }
#pragma unroll
            for (int mm = 0; mm < 4; mm++)
#pragma unroll
                for (int nn = 0; nn < 4; nn++)
                    mma_tf32(acc[mm][nn], af[mm], bf[nn]);
        }
        if (kt + 1 < 32) {
            int nb = cur ^ 1;
#pragma unroll
            for (int j = 0; j < 2; j++) {
                int i = tid + 256 * j; int kk4 = i & 3, tt = i >> 2;
                As[nb][kk4 * 4 + 0][tt] = to_tf32(ra[j][0]);
                As[nb][kk4 * 4 + 1][tt] = to_tf32(ra[j][1]);
                As[nb][kk4 * 4 + 2][tt] = to_tf32(ra[j][2]);
                As[nb][kk4 * 4 + 3][tt] = to_tf32(ra[j][3]);
            }
#pragma unroll
            for (int j = 0; j < 8; j++) {
                int i = tid + 256 * j; int kk = i >> 7, oo = i & 127;
                Bs[nb][kk][oo] = to_tf32(rb[j]);
            }
            cur = nb;
            __syncthreads();
        }
    }

    int b = t0 >> 12, hw0 = t0 & 4095;
#pragma unroll
    for (int mm = 0; mm < 4; mm++) {
#pragma unroll
        for (int nn = 0; nn < 4; nn++) {
            int c = o0 + warpN * 32 + nn * 8 + tig * 2;
            float bv0 = b1[c] + b2[c], bv1 = b1[c + 1] + b2[c + 1];
#pragma unroll
            for (int h = 0; h < 2; h++) {
                int r = warpM * 64 + mm * 16 + grp + h * 8;
                int t = t0 + r, hw = hw0 + r;
                float2 sc = *(const float2*)&p1[(size_t)t * 1024 + 768 + c];
                size_t gi0 = ((size_t)(b * 256 + c)) * HW + hw;
                size_t gi1 = ((size_t)(b * 256 + c + 1)) * HW + hw;
                out[gi0] = acc[mm][nn][h * 2]     + bv0 + sc.x + x2[gi0];
                out[gi1] = acc[mm][nn][h * 2 + 1] + bv1 + sc.y + x2[gi1];
            }
        }
    }
}

// ---------------- host launch ----------------
extern "C" void kernel_launch(void* const* d_in, const int* in_sizes, int n_in,
                              void* d_out, int out_size) {
    const float* x1      = (const float*)d_in[0];
    const float* x2      = (const float*)d_in[1];
    const float* ln1q_w  = (const float*)d_in[2];
    const float* ln1q_b  = (const float*)d_in[3];
    const float* ln2kv_w = (const float*)d_in[4];
    const float* ln2kv_b = (const float*)d_in[5];
    const float* Wq1     = (const float*)d_in[6];
    const float* Wkv2    = (const float*)d_in[7];
    const float* Wout1   = (const float*)d_in[8];
    const float* bout1   = (const float*)d_in[9];
    const float* ln2q_w  = (const float*)d_in[10];
    const float* ln2q_b  = (const float*)d_in[11];
    const float* ln1kv_w = (const float*)d_in[12];
    const float* ln1kv_b = (const float*)d_in[13];
    const float* Wq2     = (const float*)d_in[14];
    const float* Wkv1    = (const float*)d_in[15];
    const float* Wout2   = (const float*)d_in[16];
    const float* bout2   = (const float*)d_in[17];
    const float* Wsc     = (const float*)d_in[18];
    const float* bn_g    = (const float*)d_in[19];
    const float* bn_b    = (const float*)d_in[20];
    const float* bn_m    = (const float*)d_in[21];
    const float* bn_v    = (const float*)d_in[22];
    float* out = (float*)d_out;

    float *mu1, *rs1, *mu2, *rs2, *p1, *p2, *o1, *o2;
    float *W1cat, *W2cat, *b1cat, *b2cat, *Ssc;
    cudaGetSymbolAddress((void**)&mu1, g_mu1);
    cudaGetSymbolAddress((void**)&rs1, g_rs1);
    cudaGetSymbolAddress((void**)&mu2, g_mu2);
    cudaGetSymbolAddress((void**)&rs2, g_rs2);
    cudaGetSymbolAddress((void**)&p1, g_p1);
    cudaGetSymbolAddress((void**)&p2, g_p2);
    cudaGetSymbolAddress((void**)&o1, g_o1);
    cudaGetSymbolAddress((void**)&o2, g_o2);
    cudaGetSymbolAddress((void**)&W1cat, g_W1cat);
    cudaGetSymbolAddress((void**)&W2cat, g_W2cat);
    cudaGetSymbolAddress((void**)&b1cat, g_b1cat);
    cudaGetSymbolAddress((void**)&b2cat, g_b2cat);
    cudaGetSymbolAddress((void**)&Ssc, g_Ssc);

    // weight/bias folding
    k_fold_wcat<<<(384 * 1024 + 256 * 768 + 255) / 256, 256>>>(
        Wq1, ln1q_w, Wkv1, ln1kv_w, Wsc, bn_g, bn_v, Wq2, ln2q_w, Wkv2, ln2kv_w,
        W1cat, W2cat);
    k_fold_bias<<<7, 256>>>(Wq1, ln1q_b, Wkv1, ln1kv_b, Wsc, bn_g, bn_b, bn_m, bn_v,
                            Wq2, ln2q_b, Wkv2, ln2kv_b, b1cat, b2cat, Ssc);

    // LN stats
    k_stats<<<NTOK / 32, 256>>>(x1, 384, mu1, rs1);
    k_stats<<<NTOK / 32, 256>>>(x2, 256, mu2, rs2);

    // fused projections (tf32 tensor cores): x1 -> [q1|k1|v1|sc], x2 -> [q2|k2|v2]
    k_proj<<<dim3(256, 8), 256>>>(x1, 384, 1024, mu1, rs1, W1cat, b1cat, Ssc, 768, p1);
    k_proj<<<dim3(256, 6), 256>>>(x2, 256, 768, mu2, rs2, W2cat, b2cat, b2cat, 1 << 30, p2);

    // axial attention (tf32 mma): branch1 (q1 x kv2), branch2 (q2 x kv1)
    // axis0 writes, axis1 accumulates into the same buffer
    k_attn<<<4096, 128>>>(p1, 1024, p2 + 256, p2 + 512, 768, o1, 0, 0);
    k_attn<<<4096, 128>>>(p1, 1024, p2 + 256, p2 + 512, 768, o1, 1, 1);
    k_attn<<<4096, 128>>>(p2, 768, p1 + 256, p1 + 512, 1024, o2, 0, 0);
    k_attn<<<4096, 128>>>(p2, 768, p1 + 256, p1 + 512, 1024, o2, 1, 1);

    // output GEMMs + shortcut + residual + NCHW transpose (tf32 tensor cores)
    k_final<<<dim3(256, 2), 256>>>(o1, o2, Wout1, Wout2, bout1, bout2, p1, x2, out);
}

// round 8
// speedup vs baseline: 3.4215x; 1.1850x over previous
#include <cuda_runtime.h>
#include <math.h>
#include <stdint.h>

#define NTOK 32768
#define HW 4096
#define EPSV 1e-5f

// ---------------- scratch (static device memory; no allocations) ----------------
__device__ float g_mu1[NTOK], g_rs1[NTOK], g_mu2[NTOK], g_rs2[NTOK];
__device__ float g_p1[NTOK * 1024];   // per token: [q1(256) | k1(256) | v1(256) | sc(256)]
__device__ float g_p2[NTOK * 768];    // per token: [q2(256) | k2(256) | v2(256)]
__device__ float g_oh1[NTOK * 256], g_ow1[NTOK * 256];
__device__ float g_oh2[NTOK * 256], g_ow2[NTOK * 256];
__device__ float g_W1cat[384 * 1024];  // [C=384][q1|k1|v1|sc] folded
__device__ float g_W2cat[256 * 768];   // [C=256][q2|k2|v2] folded
__device__ float g_b1cat[1024], g_b2cat[768], g_Ssc[256];

// ---------------- tf32 helpers ----------------
__device__ __forceinline__ float to_tf32(float x) {
    float y;
    asm("cvt.rna.tf32.f32 %0, %1;" : "=f"(y) : "f"(x));
    return y;
}

__device__ __forceinline__ void mma_tf32(float* d, const uint32_t* a, const uint32_t* b) {
    asm volatile(
        "mma.sync.aligned.m16n8k8.row.col.f32.tf32.tf32.f32 "
        "{%0,%1,%2,%3}, {%4,%5,%6,%7}, {%8,%9}, {%0,%1,%2,%3};\n"
        : "+f"(d[0]), "+f"(d[1]), "+f"(d[2]), "+f"(d[3])
        : "r"(a[0]), "r"(a[1]), "r"(a[2]), "r"(a[3]), "r"(b[0]), "r"(b[1]));
}

// ---------------- fold all weights into two concatenated GEMM-B matrices ----------------
__global__ void k_fold_wcat(const float* __restrict__ Wq1, const float* __restrict__ ln1qw,
                            const float* __restrict__ Wkv1, const float* __restrict__ ln1kvw,
                            const float* __restrict__ Wsc, const float* __restrict__ bng,
                            const float* __restrict__ bnv,
                            const float* __restrict__ Wq2, const float* __restrict__ ln2qw,
                            const float* __restrict__ Wkv2, const float* __restrict__ ln2kvw,
                            float* __restrict__ W1cat, float* __restrict__ W2cat) {
    int idx = blockIdx.x * 256 + threadIdx.x;
    const int N1 = 384 * 1024;
    if (idx < N1) {
        int c = idx >> 10, o = idx & 1023;
        float v;
        if (o < 256)      v = Wq1[c * 256 + o] * ln1qw[c];
        else if (o < 768) v = Wkv1[c * 512 + (o - 256)] * ln1kvw[c];
        else { int oo = o - 768; v = Wsc[oo * 384 + c] * bng[oo] * rsqrtf(bnv[oo] + EPSV); }
        W1cat[idx] = v;
    } else if (idx < N1 + 256 * 768) {
        int i2 = idx - N1;
        int c = i2 / 768, o = i2 % 768;
        float v;
        if (o < 256) v = Wq2[c * 256 + o] * ln2qw[c];
        else         v = Wkv2[c * 512 + (o - 256)] * ln2kvw[c];
        W2cat[i2] = v;
    }
}

__global__ void k_fold_bias(const float* __restrict__ Wq1, const float* __restrict__ ln1qb,
                            const float* __restrict__ Wkv1, const float* __restrict__ ln1kvb,
                            const float* __restrict__ Wsc, const float* __restrict__ bng,
                            const float* __restrict__ bnb, const float* __restrict__ bnm,
                            const float* __restrict__ bnv,
                            const float* __restrict__ Wq2, const float* __restrict__ ln2qb,
                            const float* __restrict__ Wkv2, const float* __restrict__ ln2kvb,
                            float* __restrict__ b1cat, float* __restrict__ b2cat,
                            float* __restrict__ Ssc) {
    int og = blockIdx.x * 256 + threadIdx.x;
    if (og < 1024) {
        float b = 0.f;
        if (og < 256) {
            for (int c = 0; c < 384; c++) b += ln1qb[c] * Wq1[c * 256 + og];
        } else if (og < 768) {
            int o = og - 256;
            for (int c = 0; c < 384; c++) b += ln1kvb[c] * Wkv1[c * 512 + o];
        } else {
            int oo = og - 768;
            float g = bng[oo] * rsqrtf(bnv[oo] + EPSV);
            b = bnb[oo] - bnm[oo] * g;
            float s = 0.f;
            for (int c = 0; c < 384; c++) s += Wsc[oo * 384 + c];
            Ssc[oo] = s * g;
        }
        b1cat[og] = b;
    } else if (og < 1792) {
        int o2 = og - 1024;
        float b = 0.f;
        if (o2 < 256) {
            for (int c = 0; c < 256; c++) b += ln2qb[c] * Wq2[c * 256 + o2];
        } else {
            int o = o2 - 256;
            for (int c = 0; c < 256; c++) b += ln2kvb[c] * Wkv2[c * 512 + o];
        }
        b2cat[o2] = b;
    }
}

// ---------------- per-token LN statistics for BOTH inputs in one launch ----------------
// blocks [0,1024): x1 (C=384); blocks [1024,2048): x2 (C=256)
__global__ void k_stats(const float* __restrict__ X1, const float* __restrict__ X2,
                        float* __restrict__ mu1, float* __restrict__ rs1,
                        float* __restrict__ mu2, float* __restrict__ rs2) {
    __shared__ float ss[8][33], sq[8][33];
    int half = blockIdx.x >> 10;
    const float* X = half ? X2 : X1;
    int C = half ? 256 : 384;
    float* mu = half ? mu2 : mu1;
    float* rs = half ? rs2 : rs1;
    int lane = threadIdx.x & 31, cs = threadIdx.x >> 5;
    int t = (blockIdx.x & 1023) * 32 + lane;
    int b = t >> 12, hw = t & 4095;
    const float* p = X + (size_t)b * C * HW + hw;
    float s = 0.f, s2 = 0.f;
    for (int c = cs; c < C; c += 8) {
        float v = p[(size_t)c * HW];
        s += v; s2 += v * v;
    }
    ss[cs][lane] = s; sq[cs][lane] = s2;
    __syncthreads();
    if (threadIdx.x < 32) {
        float a = 0.f, q = 0.f;
#pragma unroll
        for (int j = 0; j < 8; j++) { a += ss[j][lane]; q += sq[j][lane]; }
        float m = a / C;
        mu[t] = m;
        rs[t] = rsqrtf(q / C - m * m + EPSV);
    }
}

// ---------------- tensor-core projection GEMM (tf32): 128x128 tile, BK=16, 8 warps ----------
__global__ __launch_bounds__(256) void k_proj(
    const float* __restrict__ X, int C, int Nout,
    const float* __restrict__ mu, const float* __restrict__ rs,
    const float* __restrict__ W, const float* __restrict__ bias,
    const float* __restrict__ S, int sc_start,
    float* __restrict__ out) {
    __shared__ float As[2][16][132];
    __shared__ float Bs[2][16][132];
    __shared__ float smu[128], srs[128];
    int t0 = blockIdx.x * 128, o0 = blockIdx.y * 128;
    int tid = threadIdx.x;
    if (tid < 128) { smu[tid] = mu[t0 + tid]; srs[tid] = rs[t0 + tid]; }
    __syncthreads();
    int bb = t0 >> 12, hw0 = t0 & 4095;
    const float* Xb = X + (size_t)bb * C * HW + hw0;

#pragma unroll
    for (int j = 0; j < 8; j++) {
        int i = tid + 256 * j; int kk = i >> 7, tt = i & 127;
        As[0][kk][tt] = to_tf32((Xb[(size_t)kk * HW + tt] - smu[tt]) * srs[tt]);
    }
#pragma unroll
    for (int j = 0; j < 8; j++) {
        int i = tid + 256 * j; int kk = i >> 7, oo = i & 127;
        Bs[0][kk][oo] = to_tf32(W[kk * Nout + o0 + oo]);
    }
    __syncthreads();

    int warp = tid >> 5, lane = tid & 31;
    int warpM = warp >> 2, warpN = warp & 3;
    int grp = lane >> 2, tig = lane & 3;
    float acc[4][4][4] = {};
    int KT = C >> 4;
    int cur = 0;
    for (int kt = 0; kt < KT; kt++) {
        float ra[8], rb[8];
        if (kt + 1 < KT) {
            int k0n = (kt + 1) << 4;
#pragma unroll
            for (int j = 0; j < 8; j++) {
                int i = tid + 256 * j; int kk = i >> 7, tt = i & 127;
                ra[j] = Xb[(size_t)(k0n + kk) * HW + tt];
            }
#pragma unroll
            for (int j = 0; j < 8; j++) {
                int i = tid + 256 * j; int kk = i >> 7, oo = i & 127;
                rb[j] = W[(k0n + kk) * Nout + o0 + oo];
            }
        }
#pragma unroll
        for (int k8 = 0; k8 < 16; k8 += 8) {
            uint32_t af[4][4], bf[4][2];
#pragma unroll
            for (int mm = 0; mm < 4; mm++) {
                int r = warpM * 64 + mm * 16 + grp;
                af[mm][0] = __float_as_uint(As[cur][k8 + tig][r]);
                af[mm][1] = __float_as_uint(As[cur][k8 + tig][r + 8]);
                af[mm][2] = __float_as_uint(As[cur][k8 + tig + 4][r]);
                af[mm][3] = __float_as_uint(As[cur][k8 + tig + 4][r + 8]);
            }
#pragma unroll
            for (int nn = 0; nn < 4; nn++) {
                int c = warpN * 32 + nn * 8 + grp;
                bf[nn][0] = __float_as_uint(Bs[cur][k8 + tig][c]);
                bf[nn][1] = __float_as_uint(Bs[cur][k8 + tig + 4][c]);
            }
#pragma unroll
            for (int mm = 0; mm < 4; mm++)
#pragma unroll
                for (int nn = 0; nn < 4; nn++)
                    mma_tf32(acc[mm][nn], af[mm], bf[nn]);
        }
        if (kt + 1 < KT) {
            int nb = cur ^ 1;
#pragma unroll
            for (int j = 0; j < 8; j++) {
                int i = tid + 256 * j; int kk = i >> 7, tt = i & 127;
                As[nb][kk][tt] = to_tf32((ra[j] - smu[tt]) * srs[tt]);
            }
#pragma unroll
            for (int j = 0; j < 8; j++) {
                int i = tid + 256 * j; int kk = i >> 7, oo = i & 127;
                Bs[nb][kk][oo] = to_tf32(rb[j]);
            }
            cur = nb;
            __syncthreads();
        }
    }

    bool isc = (o0 >= sc_start);
#pragma unroll
    for (int mm = 0; mm < 4; mm++) {
#pragma unroll
        for (int nn = 0; nn < 4; nn++) {
            int c = o0 + warpN * 32 + nn * 8 + tig * 2;
            float bv0 = bias[c], bv1 = bias[c + 1];
            float sv0 = 0.f, sv1 = 0.f;
            if (isc) { sv0 = S[c - sc_start]; sv1 = S[c + 1 - sc_start]; }
#pragma unroll
            for (int h = 0; h < 2; h++) {
                int r = warpM * 64 + mm * 16 + grp + h * 8;
                float v0 = acc[mm][nn][h * 2], v1 = acc[mm][nn][h * 2 + 1];
                if (isc) {
                    float inv = 1.f / srs[r], m = smu[r];
                    v0 = v0 * inv + m * sv0 + bv0;
                    v1 = v1 * inv + m * sv1 + bv1;
                } else { v0 += bv0; v1 += bv1; }
                float2 w = make_float2(v0, v1);
                *(float2*)&out[(size_t)(t0 + r) * Nout + c] = w;
            }
        }
    }
}

// ---------------- axial attention (tf32 tensor cores), BOTH axes in one launch -------------
// 8192 blocks: axis = bx>>12, b = (bx>>9)&7, line = (bx>>3)&63, head = bx&7.
// axis0 -> Oh, axis1 -> Ow. 128 threads = 4 warps; warp w owns rows [w*16, w*16+16).
// Softmax normalization deferred: P holds unnormalized exp (tf32); O scaled by 1/sum.
__global__ __launch_bounds__(128) void k_attn(
    const float* __restrict__ Q, int qpitch,
    const float* __restrict__ K, const float* __restrict__ V,
    int kvpitch, float* __restrict__ Oh, float* __restrict__ Ow) {
    __shared__ float Qs[64][36];
    __shared__ float Ks[64][36];
    __shared__ float Vs[64][36];
    __shared__ float S[64][68];
    __shared__ float sinv[64];
    int bx = blockIdx.x;
    int head = bx & 7, line = (bx >> 3) & 63, b = (bx >> 9) & 7, axis = bx >> 12;
    int tstride = axis ? 1 : 64;
    int tbase = b * 4096 + (axis ? line * 64 : line);
    int hoff = head * 32;
    float* O = axis ? Ow : Oh;
    int tid = threadIdx.x;
    const float scale = 0.17677669529663687f; // 1/sqrt(32), folded into Q

    // float4 loads: 64 rows x 8 quads per array, 128 threads -> 4 iters per array
    for (int i = tid; i < 64 * 8; i += 128) {
        int r = i >> 3, q4 = i & 7;
        size_t t = (size_t)(tbase + r * tstride);
        float4 vq = *(const float4*)&Q[t * qpitch + hoff + q4 * 4];
        float4 vk = *(const float4*)&K[t * kvpitch + hoff + q4 * 4];
        float4 vv = *(const float4*)&V[t * kvpitch + hoff + q4 * 4];
        *(float4*)&Qs[r][q4 * 4] = make_float4(to_tf32(vq.x * scale), to_tf32(vq.y * scale),
                                               to_tf32(vq.z * scale), to_tf32(vq.w * scale));
        *(float4*)&Ks[r][q4 * 4] = make_float4(to_tf32(vk.x), to_tf32(vk.y),
                                               to_tf32(vk.z), to_tf32(vk.w));
        *(float4*)&Vs[r][q4 * 4] = make_float4(to_tf32(vv.x), to_tf32(vv.y),
                                               to_tf32(vv.z), to_tf32(vv.w));
    }
    __syncthreads();

    int warp = tid >> 5, lane = tid & 31;
    int grp = lane >> 2, tig = lane & 3;
    int m0 = warp * 16;

    // ---- S = (Q*scale) K^T : M=16/warp, N=64, K=32 ----
    {
        uint32_t af[4][4];
#pragma unroll
        for (int k8 = 0; k8 < 4; k8++) {
            af[k8][0] = __float_as_uint(Qs[m0 + grp][k8 * 8 + tig]);
            af[k8][1] = __float_as_uint(Qs[m0 + grp + 8][k8 * 8 + tig]);
            af[k8][2] = __float_as_uint(Qs[m0 + grp][k8 * 8 + tig + 4]);
            af[k8][3] = __float_as_uint(Qs[m0 + grp + 8][k8 * 8 + tig + 4]);
        }
#pragma unroll
        for (int n8 = 0; n8 < 8; n8++) {
            float sacc[4] = {};
#pragma unroll
            for (int k8 = 0; k8 < 4; k8++) {
                uint32_t bf[2];
                bf[0] = __float_as_uint(Ks[n8 * 8 + grp][k8 * 8 + tig]);
                bf[1] = __float_as_uint(Ks[n8 * 8 + grp][k8 * 8 + tig + 4]);
                mma_tf32(sacc, af[k8], bf);
            }
            *(float2*)&S[m0 + grp][n8 * 8 + tig * 2]     = make_float2(sacc[0], sacc[1]);
            *(float2*)&S[m0 + grp + 8][n8 * 8 + tig * 2] = make_float2(sacc[2], sacc[3]);
        }
    }
    __syncthreads();

    // ---- softmax (unnormalized): 2 threads per row; inv stored for epilogue ----
    {
        int row = tid >> 1, half = tid & 1;
        float* sr = &S[row][half * 32];
        float m = -1e30f;
#pragma unroll 8
        for (int j = 0; j < 32; j++) m = fmaxf(m, sr[j]);
        m = fmaxf(m, __shfl_xor_sync(0xffffffffu, m, 1));
        float sum = 0.f;
#pragma unroll 8
        for (int j = 0; j < 32; j++) {
            float e = __expf(sr[j] - m);
            sum += e;
            sr[j] = to_tf32(e);
        }
        sum += __shfl_xor_sync(0xffffffffu, sum, 1);
        if (half == 0) sinv[row] = 1.f / sum;
    }
    __syncthreads();

    // ---- O = P V (then row-scale by inv) : M=16/warp, N=32, K=64 ----
    {
        float oacc[4][4] = {};
#pragma unroll
        for (int k8 = 0; k8 < 8; k8++) {
            uint32_t af[4];
            af[0] = __float_as_uint(S[m0 + grp][k8 * 8 + tig]);
            af[1] = __float_as_uint(S[m0 + grp + 8][k8 * 8 + tig]);
            af[2] = __float_as_uint(S[m0 + grp][k8 * 8 + tig + 4]);
            af[3] = __float_as_uint(S[m0 + grp + 8][k8 * 8 + tig + 4]);
#pragma unroll
            for (int nn = 0; nn < 4; nn++) {
                uint32_t bf[2];
                bf[0] = __float_as_uint(Vs[k8 * 8 + tig][nn * 8 + grp]);
                bf[1] = __float_as_uint(Vs[k8 * 8 + tig + 4][nn * 8 + grp]);
                mma_tf32(oacc[nn], af, bf);
            }
        }
        float inva = sinv[m0 + grp], invb = sinv[m0 + grp + 8];
        int ta = tbase + (m0 + grp) * tstride;
        int tb = tbase + (m0 + grp + 8) * tstride;
        float* Oa = O + (size_t)ta * 256 + hoff;
        float* Ob = O + (size_t)tb * 256 + hoff;
#pragma unroll
        for (int nn = 0; nn < 4; nn++) {
            int c = nn * 8 + tig * 2;
            *(float2*)&Oa[c] = make_float2(oacc[nn][0] * inva, oacc[nn][1] * inva);
            *(float2*)&Ob[c] = make_float2(oacc[nn][2] * invb, oacc[nn][3] * invb);
        }
    }
}

// ---------------- tensor-core final GEMM (tf32): out = sc + x2 + (oh+ow)@W + b --------------
// 128x128 tile, virtual K=512 (branch1 then branch2), NCHW transposed write.
__global__ __launch_bounds__(256) void k_final(
    const float* __restrict__ oh1, const float* __restrict__ ow1,
    const float* __restrict__ oh2, const float* __restrict__ ow2,
    const float* __restrict__ W1, const float* __restrict__ W2,
    const float* __restrict__ b1, const float* __restrict__ b2,
    const float* __restrict__ p1, const float* __restrict__ x2,
    float* __restrict__ out) {
    __shared__ float As[2][16][132];
    __shared__ float Bs[2][16][132];
    int t0 = blockIdx.x * 128, o0 = blockIdx.y * 128;
    int tid = threadIdx.x;

    // tile 0 (branch1, k=0)
#pragma unroll
    for (int j = 0; j < 2; j++) {
        int i = tid + 256 * j; int kk4 = i & 3, tt = i >> 2;
        float4 va = *(const float4*)&oh1[(size_t)(t0 + tt) * 256 + kk4 * 4];
        float4 vb = *(const float4*)&ow1[(size_t)(t0 + tt) * 256 + kk4 * 4];
        As[0][kk4 * 4 + 0][tt] = to_tf32(va.x + vb.x);
        As[0][kk4 * 4 + 1][tt] = to_tf32(va.y + vb.y);
        As[0][kk4 * 4 + 2][tt] = to_tf32(va.z + vb.z);
        As[0][kk4 * 4 + 3][tt] = to_tf32(va.w + vb.w);
    }
#pragma unroll
    for (int j = 0; j < 8; j++) {
        int i = tid + 256 * j; int kk = i >> 7, oo = i & 127;
        Bs[0][kk][oo] = to_tf32(W1[kk * 256 + o0 + oo]);
    }
    __syncthreads();

    int warp = tid >> 5, lane = tid & 31;
    int warpM = warp >> 2, warpN = warp & 3;
    int grp = lane >> 2, tig = lane & 3;
    float acc[4][4][4] = {};
    int cur = 0;
    for (int kt = 0; kt < 32; kt++) {
        float ra[2][4], rb[8];
        if (kt + 1 < 32) {
            int kbn = (kt + 1) << 4;
            const float* A0 = (kbn < 256) ? oh1 : oh2;
            const float* A1 = (kbn < 256) ? ow1 : ow2;
            const float* W  = (kbn < 256) ? W1 : W2;
            int kboff = kbn & 255;
#pragma unroll
            for (int j = 0; j < 2; j++) {
                int i = tid + 256 * j; int kk4 = i & 3, tt = i >> 2;
                float4 va = *(const float4*)&A0[(size_t)(t0 + tt) * 256 + kboff + kk4 * 4];
                float4 vb = *(const float4*)&A1[(size_t)(t0 + tt) * 256 + kboff + kk4 * 4];
                ra[j][0] = va.x + vb.x; ra[j][1] = va.y + vb.y;
                ra[j][2] = va.z + vb.z; ra[j][3] = va.w + vb.w;
            }
#pragma unroll
            for (int j = 0; j < 8; j++) {
                int i = tid + 256 * j; int kk = i >> 7, oo = i & 127;
                rb[j] = W[(kboff + kk) * 256 + o0 + oo];
            }
        }
#pragma unroll
        for (int k8 = 0; k8 < 16; k8 += 8) {
            uint32_t af[4][4], bf[4][2];
#pragma unroll
            for (int mm = 0; mm < 4; mm++) {
                int r = warpM * 64 + mm * 16 + grp;
                af[mm][0] = __float_as_uint(As[cur][k8 + tig][r]);
                af[mm][1] = __float_as_uint(As[cur][k8 + tig][r + 8]);
                af[mm][2] = __float_as_uint(As[cur][k8 + tig + 4][r]);
                af[mm][3] = __float_as_uint(As[cur][k8 + tig + 4][r + 8]);
            }
#pragma unroll
            for (int nn = 0; nn < 4; nn++) {
                int c = warpN * 32 + nn * 8 + grp;
                bf[nn][0] = __float_as_uint(Bs[cur][k8 + tig][c]);
                bf[nn][1] = __float_as_uint(Bs[cur][k8 + tig + 4][c]);
            }
#pragma unroll
            for (int mm = 0; mm < 4; mm++)
#pragma unroll
                for (int nn = 0; nn < 4; nn++)
                    mma_tf32(acc[mm][nn], af[mm], bf[nn]);
        }
        if (kt + 1 < 32) {
            int nb = cur ^ 1;
#pragma unroll
            for (int j = 0; j < 2; j++) {
                int i = tid + 256 * j; int kk4 = i & 3, tt = i >> 2;
                As[nb][kk4 * 4 + 0][tt] = to_tf32(ra[j][0]);
                As[nb][kk4 * 4 + 1][tt] = to_tf32(ra[j][1]);
                As[nb][kk4 * 4 + 2][tt] = to_tf32(ra[j][2]);
                As[nb][kk4 * 4 + 3][tt] = to_tf32(ra[j][3]);
            }
#pragma unroll
            for (int j = 0; j < 8; j++) {
                int i = tid + 256 * j; int kk = i >> 7, oo = i & 127;
                Bs[nb][kk][oo] = to_tf32(rb[j]);
            }
            cur = nb;
            __syncthreads();
        }
    }

    int b = t0 >> 12, hw0 = t0 & 4095;
#pragma unroll
    for (int mm = 0; mm < 4; mm++) {
#pragma unroll
        for (int nn = 0; nn < 4; nn++) {
            int c = o0 + warpN * 32 + nn * 8 + tig * 2;
            float bv0 = b1[c] + b2[c], bv1 = b1[c + 1] + b2[c + 1];
#pragma unroll
            for (int h = 0; h < 2; h++) {
                int r = warpM * 64 + mm * 16 + grp + h * 8;
                int t = t0 + r, hw = hw0 + r;
                float2 sc = *(const float2*)&p1[(size_t)t * 1024 + 768 + c];
                size_t gi0 = ((size_t)(b * 256 + c)) * HW + hw;
                size_t gi1 = ((size_t)(b * 256 + c + 1)) * HW + hw;
                out[gi0] = acc[mm][nn][h * 2]     + bv0 + sc.x + x2[gi0];
                out[gi1] = acc[mm][nn][h * 2 + 1] + bv1 + sc.y + x2[gi1];
            }
        }
    }
}

// ---------------- host launch ----------------
extern "C" void kernel_launch(void* const* d_in, const int* in_sizes, int n_in,
                              void* d_out, int out_size) {
    const float* x1      = (const float*)d_in[0];
    const float* x2      = (const float*)d_in[1];
    const float* ln1q_w  = (const float*)d_in[2];
    const float* ln1q_b  = (const float*)d_in[3];
    const float* ln2kv_w = (const float*)d_in[4];
    const float* ln2kv_b = (const float*)d_in[5];
    const float* Wq1     = (const float*)d_in[6];
    const float* Wkv2    = (const float*)d_in[7];
    const float* Wout1   = (const float*)d_in[8];
    const float* bout1   = (const float*)d_in[9];
    const float* ln2q_w  = (const float*)d_in[10];
    const float* ln2q_b  = (const float*)d_in[11];
    const float* ln1kv_w = (const float*)d_in[12];
    const float* ln1kv_b = (const float*)d_in[13];
    const float* Wq2     = (const float*)d_in[14];
    const float* Wkv1    = (const float*)d_in[15];
    const float* Wout2   = (const float*)d_in[16];
    const float* bout2   = (const float*)d_in[17];
    const float* Wsc     = (const float*)d_in[18];
    const float* bn_g    = (const float*)d_in[19];
    const float* bn_b    = (const float*)d_in[20];
    const float* bn_m    = (const float*)d_in[21];
    const float* bn_v    = (const float*)d_in[22];
    float* out = (float*)d_out;

    float *mu1, *rs1, *mu2, *rs2, *p1, *p2, *oh1, *ow1, *oh2, *ow2;
    float *W1cat, *W2cat, *b1cat, *b2cat, *Ssc;
    cudaGetSymbolAddress((void**)&mu1, g_mu1);
    cudaGetSymbolAddress((void**)&rs1, g_rs1);
    cudaGetSymbolAddress((void**)&mu2, g_mu2);
    cudaGetSymbolAddress((void**)&rs2, g_rs2);
    cudaGetSymbolAddress((void**)&p1, g_p1);
    cudaGetSymbolAddress((void**)&p2, g_p2);
    cudaGetSymbolAddress((void**)&oh1, g_oh1);
    cudaGetSymbolAddress((void**)&ow1, g_ow1);
    cudaGetSymbolAddress((void**)&oh2, g_oh2);
    cudaGetSymbolAddress((void**)&ow2, g_ow2);
    cudaGetSymbolAddress((void**)&W1cat, g_W1cat);
    cudaGetSymbolAddress((void**)&W2cat, g_W2cat);
    cudaGetSymbolAddress((void**)&b1cat, g_b1cat);
    cudaGetSymbolAddress((void**)&b2cat, g_b2cat);
    cudaGetSymbolAddress((void**)&Ssc, g_Ssc);

    // weight/bias folding
    k_fold_wcat<<<(384 * 1024 + 256 * 768 + 255) / 256, 256>>>(
        Wq1, ln1q_w, Wkv1, ln1kv_w, Wsc, bn_g, bn_v, Wq2, ln2q_w, Wkv2, ln2kv_w,
        W1cat, W2cat);
    k_fold_bias<<<7, 256>>>(Wq1, ln1q_b, Wkv1, ln1kv_b, Wsc, bn_g, bn_b, bn_m, bn_v,
                            Wq2, ln2q_b, Wkv2, ln2kv_b, b1cat, b2cat, Ssc);

    // LN stats (both inputs, one launch)
    k_stats<<<2048, 256>>>(x1, x2, mu1, rs1, mu2, rs2);

    // fused projections (tf32 tensor cores): x1 -> [q1|k1|v1|sc], x2 -> [q2|k2|v2]
    k_proj<<<dim3(256, 8), 256>>>(x1, 384, 1024, mu1, rs1, W1cat, b1cat, Ssc, 768, p1);
    k_proj<<<dim3(256, 6), 256>>>(x2, 256, 768, mu2, rs2, W2cat, b2cat, b2cat, 1 << 30, p2);

    // axial attention (tf32 mma), both axes per launch:
    // branch1 (q1 x kv2) -> oh1/ow1 ; branch2 (q2 x kv1) -> oh2/ow2
    k_attn<<<8192, 128>>>(p1, 1024, p2 + 256, p2 + 512, 768, oh1, ow1);
    k_attn<<<8192, 128>>>(p2, 768, p1 + 256, p1 + 512, 1024, oh2, ow2);

    // output GEMMs + shortcut + residual + NCHW transpose (tf32 tensor cores)
    k_final<<<dim3(256, 2), 256>>>(oh1, ow1, oh2, ow2, Wout1, Wout2, bout1, bout2,
                                   p1, x2, out);
}

// round 9
// speedup vs baseline: 4.2957x; 1.2555x over previous
#include <cuda_runtime.h>
#include <math.h>
#include <stdint.h>

#define NTOK 32768
#define HW 4096
#define EPSV 1e-5f

// ---------------- scratch (static device memory; no allocations) ----------------
__device__ float g_mu1[NTOK], g_rs1[NTOK], g_mu2[NTOK], g_rs2[NTOK];
__device__ float g_p1[NTOK * 1024];   // per token: [q1(256) | k1(256) | v1(256) | sc(256)]
__device__ float g_p2[NTOK * 768];    // per token: [q2(256) | k2(256) | v2(256)]
__device__ float g_oh1[NTOK * 256], g_ow1[NTOK * 256];
__device__ float g_oh2[NTOK * 256], g_ow2[NTOK * 256];
__device__ float g_W1cat[384 * 1024];  // [C=384][q1|k1|v1|sc] folded, tf32-rounded
__device__ float g_W2cat[256 * 768];   // [C=256][q2|k2|v2] folded, tf32-rounded
__device__ float g_b1cat[1024], g_b2cat[768];
__device__ float g_cs1[768], g_cs2[768];   // column sums of folded W (LN-defer term)

// ---------------- tf32 helpers ----------------
__device__ __forceinline__ float to_tf32(float x) {
    float y;
    asm("cvt.rna.tf32.f32 %0, %1;" : "=f"(y) : "f"(x));
    return y;
}

__device__ __forceinline__ void mma_tf32(float* d, const uint32_t* a, const uint32_t* b) {
    asm volatile(
        "mma.sync.aligned.m16n8k8.row.col.f32.tf32.tf32.f32 "
        "{%0,%1,%2,%3}, {%4,%5,%6,%7}, {%8,%9}, {%0,%1,%2,%3};\n"
        : "+f"(d[0]), "+f"(d[1]), "+f"(d[2]), "+f"(d[3])
        : "r"(a[0]), "r"(a[1]), "r"(a[2]), "r"(a[3]), "r"(b[0]), "r"(b[1]));
}

__device__ __forceinline__ void cp_async16(void* smem_dst, const void* gmem_src) {
    uint32_t d = (uint32_t)__cvta_generic_to_shared(smem_dst);
    asm volatile("cp.async.cg.shared.global [%0], [%1], 16;\n" :: "r"(d), "l"(gmem_src));
}

// ---------------- fold all weights into two concatenated GEMM-B matrices (tf32) -------------
__global__ void k_fold_wcat(const float* __restrict__ Wq1, const float* __restrict__ ln1qw,
                            const float* __restrict__ Wkv1, const float* __restrict__ ln1kvw,
                            const float* __restrict__ Wsc, const float* __restrict__ bng,
                            const float* __restrict__ bnv,
                            const float* __restrict__ Wq2, const float* __restrict__ ln2qw,
                            const float* __restrict__ Wkv2, const float* __restrict__ ln2kvw,
                            float* __restrict__ W1cat, float* __restrict__ W2cat) {
    int idx = blockIdx.x * 256 + threadIdx.x;
    const int N1 = 384 * 1024;
    if (idx < N1) {
        int c = idx >> 10, o = idx & 1023;
        float v;
        if (o < 256)      v = Wq1[c * 256 + o] * ln1qw[c];
        else if (o < 768) v = Wkv1[c * 512 + (o - 256)] * ln1kvw[c];
        else { int oo = o - 768; v = Wsc[oo * 384 + c] * bng[oo] * rsqrtf(bnv[oo] + EPSV); }
        W1cat[idx] = to_tf32(v);
    } else if (idx < N1 + 256 * 768) {
        int i2 = idx - N1;
        int c = i2 / 768, o = i2 % 768;
        float v;
        if (o < 256) v = Wq2[c * 256 + o] * ln2qw[c];
        else         v = Wkv2[c * 512 + (o - 256)] * ln2kvw[c];
        W2cat[i2] = to_tf32(v);
    }
}

// biases + column sums of folded (tf32) W for the LN-defer epilogue
__global__ void k_fold_bias(const float* __restrict__ Wq1, const float* __restrict__ ln1qw,
                            const float* __restrict__ ln1qb,
                            const float* __restrict__ Wkv1, const float* __restrict__ ln1kvw,
                            const float* __restrict__ ln1kvb,
                            const float* __restrict__ bng,
                            const float* __restrict__ bnb, const float* __restrict__ bnm,
                            const float* __restrict__ bnv,
                            const float* __restrict__ Wq2, const float* __restrict__ ln2qw,
                            const float* __restrict__ ln2qb,
                            const float* __restrict__ Wkv2, const float* __restrict__ ln2kvw,
                            const float* __restrict__ ln2kvb,
                            float* __restrict__ b1cat, float* __restrict__ b2cat,
                            float* __restrict__ cs1, float* __restrict__ cs2) {
    int og = blockIdx.x * 256 + threadIdx.x;
    if (og < 1024) {
        float b = 0.f, cs = 0.f;
        if (og < 256) {
            for (int c = 0; c < 384; c++) {
                b += ln1qb[c] * Wq1[c * 256 + og];
                cs += to_tf32(ln1qw[c] * Wq1[c * 256 + og]);
            }
            cs1[og] = cs;
        } else if (og < 768) {
            int o = og - 256;
            for (int c = 0; c < 384; c++) {
                b += ln1kvb[c] * Wkv1[c * 512 + o];
                cs += to_tf32(ln1kvw[c] * Wkv1[c * 512 + o]);
            }
            cs1[og] = cs;
        } else {
            int oo = og - 768;
            float g = bng[oo] * rsqrtf(bnv[oo] + EPSV);
            b = bnb[oo] - bnm[oo] * g;
        }
        b1cat[og] = b;
    } else if (og < 1792) {
        int o2 = og - 1024;
        float b = 0.f, cs = 0.f;
        if (o2 < 256) {
            for (int c = 0; c < 256; c++) {
                b += ln2qb[c] * Wq2[c * 256 + o2];
                cs += to_tf32(ln2qw[c] * Wq2[c * 256 + o2]);
            }
        } else {
            int o = o2 - 256;
            for (int c = 0; c < 256; c++) {
                b += ln2kvb[c] * Wkv2[c * 512 + o];
                cs += to_tf32(ln2kvw[c] * Wkv2[c * 512 + o]);
            }
        }
        b2cat[o2] = b;
        cs2[o2] = cs;
    }
}

// ---------------- per-token LN statistics for BOTH inputs in one launch ----------------
__global__ void k_stats(const float* __restrict__ X1, const float* __restrict__ X2,
                        float* __restrict__ mu1, float* __restrict__ rs1,
                        float* __restrict__ mu2, float* __restrict__ rs2) {
    __shared__ float ss[8][33], sq[8][33];
    int half = blockIdx.x >> 10;
    const float* X = half ? X2 : X1;
    int C = half ? 256 : 384;
    float* mu = half ? mu2 : mu1;
    float* rs = half ? rs2 : rs1;
    int lane = threadIdx.x & 31, cs = threadIdx.x >> 5;
    int t = (blockIdx.x & 1023) * 32 + lane;
    int b = t >> 12, hw = t & 4095;
    const float* p = X + (size_t)b * C * HW + hw;
    float s = 0.f, s2 = 0.f;
    for (int c = cs; c < C; c += 8) {
        float v = p[(size_t)c * HW];
        s += v; s2 += v * v;
    }
    ss[cs][lane] = s; sq[cs][lane] = s2;
    __syncthreads();
    if (threadIdx.x < 32) {
        float a = 0.f, q = 0.f;
#pragma unroll
        for (int j = 0; j < 8; j++) { a += ss[j][lane]; q += sq[j][lane]; }
        float m = a / C;
        mu[t] = m;
        rs[t] = rsqrtf(q / C - m * m + EPSV);
    }
}

// ---------------- tensor-core projection GEMM (tf32, LN-deferred, cp.async) -----------------
// Mainloop computes raw X @ Wcat; epilogue applies rs*(acc - mu*colsum) + bias.
// Columns >= sc_start (BN shortcut): out = acc + bias directly.
// 128x128 tile, BK=16, 8 warps, cp.async double buffer, 2 CTAs/SM target.
__global__ __launch_bounds__(256, 2) void k_proj(
    const float* __restrict__ X, int C, int Nout,
    const float* __restrict__ mu, const float* __restrict__ rs,
    const float* __restrict__ W, const float* __restrict__ bias,
    const float* __restrict__ cs, int sc_start,
    float* __restrict__ out) {
    __shared__ float As[2][16][132];
    __shared__ float Bs[2][16][132];
    __shared__ float smu[128], srs[128];
    int t0 = blockIdx.x * 128, o0 = blockIdx.y * 128;
    int tid = threadIdx.x;
    if (tid < 128) { smu[tid] = mu[t0 + tid]; srs[tid] = rs[t0 + tid]; }
    int bb = t0 >> 12, hw0 = t0 & 4095;
    const float* Xb = X + (size_t)bb * C * HW + hw0;

    int KT = C >> 4;
    // prologue: tile 0
    {
#pragma unroll
        for (int j = 0; j < 2; j++) {
            int id = tid + 256 * j; int kk = id >> 5, c4 = id & 31;
            cp_async16(&As[0][kk][c4 * 4], Xb + (size_t)kk * HW + c4 * 4);
            cp_async16(&Bs[0][kk][c4 * 4], W + (size_t)kk * Nout + o0 + c4 * 4);
        }
        asm volatile("cp.async.commit_group;\n");
        asm volatile("cp.async.wait_group 0;\n");
        __syncthreads();
    }

    int warp = tid >> 5, lane = tid & 31;
    int warpM = warp >> 2, warpN = warp & 3;
    int grp = lane >> 2, tig = lane & 3;
    float acc[4][4][4] = {};
    int cur = 0;
    for (int kt = 0; kt < KT; kt++) {
        if (kt + 1 < KT) {
            int k0 = (kt + 1) << 4;
            int nb = cur ^ 1;
#pragma unroll
            for (int j = 0; j < 2; j++) {
                int id = tid + 256 * j; int kk = id >> 5, c4 = id & 31;
                cp_async16(&As[nb][kk][c4 * 4], Xb + (size_t)(k0 + kk) * HW + c4 * 4);
                cp_async16(&Bs[nb][kk][c4 * 4], W + (size_t)(k0 + kk) * Nout + o0 + c4 * 4);
            }
            asm volatile("cp.async.commit_group;\n");
        }
#pragma unroll
        for (int k8 = 0; k8 < 16; k8 += 8) {
            uint32_t af[4][4], bf[4][2];
#pragma unroll
            for (int mm = 0; mm < 4; mm++) {
                int r = warpM * 64 + mm * 16 + grp;
                af[mm][0] = __float_as_uint(As[cur][k8 + tig][r]);
                af[mm][1] = __float_as_uint(As[cur][k8 + tig][r + 8]);
                af[mm][2] = __float_as_uint(As[cur][k8 + tig + 4][r]);
                af[mm][3] = __float_as_uint(As[cur][k8 + tig + 4][r + 8]);
            }
#pragma unroll
            for (int nn = 0; nn < 4; nn++) {
                int c = warpN * 32 + nn * 8 + grp;
                bf[nn][0] = __float_as_uint(Bs[cur][k8 + tig][c]);
                bf[nn][1] = __float_as_uint(Bs[cur][k8 + tig + 4][c]);
            }
#pragma unroll
            for (int mm = 0; mm < 4; mm++)
#pragma unroll
                for (int nn = 0; nn < 4; nn++)
                    mma_tf32(acc[mm][nn], af[mm], bf[nn]);
        }
        if (kt + 1 < KT) {
            asm volatile("cp.async.wait_group 0;\n");
            __syncthreads();
            cur ^= 1;
        }
    }

    bool isc = (o0 >= sc_start);
#pragma unroll
    for (int mm = 0; mm < 4; mm++) {
#pragma unroll
        for (int nn = 0; nn < 4; nn++) {
            int c = o0 + warpN * 32 + nn * 8 + tig * 2;
            float bv0 = bias[c], bv1 = bias[c + 1];
            float cs0 = 0.f, cs1v = 0.f;
            if (!isc) { cs0 = cs[c]; cs1v = cs[c + 1]; }
#pragma unroll
            for (int h = 0; h < 2; h++) {
                int r = warpM * 64 + mm * 16 + grp + h * 8;
                float v0 = acc[mm][nn][h * 2], v1 = acc[mm][nn][h * 2 + 1];
                if (!isc) {
                    float rv = srs[r], m = smu[r];
                    v0 = rv * (v0 - m * cs0) + bv0;
                    v1 = rv * (v1 - m * cs1v) + bv1;
                } else { v0 += bv0; v1 += bv1; }
                *(float2*)&out[(size_t)(t0 + r) * Nout + c] = make_float2(v0, v1);
            }
        }
    }
}

// ---------------- axial attention (tf32 tensor cores), BOTH axes in one launch -------------
__global__ __launch_bounds__(128) void k_attn(
    const float* __restrict__ Q, int qpitch,
    const float* __restrict__ K, const float* __restrict__ V,
    int kvpitch, float* __restrict__ Oh, float* __restrict__ Ow) {
    __shared__ float Qs[64][36];
    __shared__ float Ks[64][36];
    __shared__ float Vs[64][36];
    __shared__ float S[64][68];
    __shared__ float sinv[64];
    int bx = blockIdx.x;
    int head = bx & 7, line = (bx >> 3) & 63, b = (bx >> 9) & 7, axis = bx >> 12;
    int tstride = axis ? 1 : 64;
    int tbase = b * 4096 + (axis ? line * 64 : line);
    int hoff = head * 32;
    float* O = axis ? Ow : Oh;
    int tid = threadIdx.x;
    const float scale = 0.17677669529663687f; // 1/sqrt(32), folded into Q

    for (int i = tid; i < 64 * 8; i += 128) {
        int r = i >> 3, q4 = i & 7;
        size_t t = (size_t)(tbase + r * tstride);
        float4 vq = *(const float4*)&Q[t * qpitch + hoff + q4 * 4];
        float4 vk = *(const float4*)&K[t * kvpitch + hoff + q4 * 4];
        float4 vv = *(const float4*)&V[t * kvpitch + hoff + q4 * 4];
        *(float4*)&Qs[r][q4 * 4] = make_float4(to_tf32(vq.x * scale), to_tf32(vq.y * scale),
                                               to_tf32(vq.z * scale), to_tf32(vq.w * scale));
        *(float4*)&Ks[r][q4 * 4] = make_float4(to_tf32(vk.x), to_tf32(vk.y),
                                               to_tf32(vk.z), to_tf32(vk.w));
        *(float4*)&Vs[r][q4 * 4] = make_float4(to_tf32(vv.x), to_tf32(vv.y),
                                               to_tf32(vv.z), to_tf32(vv.w));
    }
    __syncthreads();

    int warp = tid >> 5, lane = tid & 31;
    int grp = lane >> 2, tig = lane & 3;
    int m0 = warp * 16;

    {
        uint32_t af[4][4];
#pragma unroll
        for (int k8 = 0; k8 < 4; k8++) {
            af[k8][0] = __float_as_uint(Qs[m0 + grp][k8 * 8 + tig]);
            af[k8][1] = __float_as_uint(Qs[m0 + grp + 8][k8 * 8 + tig]);
            af[k8][2] = __float_as_uint(Qs[m0 + grp][k8 * 8 + tig + 4]);
            af[k8][3] = __float_as_uint(Qs[m0 + grp + 8][k8 * 8 + tig + 4]);
        }
#pragma unroll
        for (int n8 = 0; n8 < 8; n8++) {
            float sacc[4] = {};
#pragma unroll
            for (int k8 = 0; k8 < 4; k8++) {
                uint32_t bf[2];
                bf[0] = __float_as_uint(Ks[n8 * 8 + grp][k8 * 8 + tig]);
                bf[1] = __float_as_uint(Ks[n8 * 8 + grp][k8 * 8 + tig + 4]);
                mma_tf32(sacc, af[k8], bf);
            }
            *(float2*)&S[m0 + grp][n8 * 8 + tig * 2]     = make_float2(sacc[0], sacc[1]);
            *(float2*)&S[m0 + grp + 8][n8 * 8 + tig * 2] = make_float2(sacc[2], sacc[3]);
        }
    }
    __syncthreads();

    {
        int row = tid >> 1, half = tid & 1;
        float* sr = &S[row][half * 32];
        float m = -1e30f;
#pragma unroll 8
        for (int j = 0; j < 32; j++) m = fmaxf(m, sr[j]);
        m = fmaxf(m, __shfl_xor_sync(0xffffffffu, m, 1));
        float sum = 0.f;
#pragma unroll 8
        for (int j = 0; j < 32; j++) {
            float e = __expf(sr[j] - m);
            sum += e;
            sr[j] = to_tf32(e);
        }
        sum += __shfl_xor_sync(0xffffffffu, sum, 1);
        if (half == 0) sinv[row] = 1.f / sum;
    }
    __syncthreads();

    {
        float oacc[4][4] = {};
#pragma unroll
        for (int k8 = 0; k8 < 8; k8++) {
            uint32_t af[4];
            af[0] = __float_as_uint(S[m0 + grp][k8 * 8 + tig]);
            af[1] = __float_as_uint(S[m0 + grp + 8][k8 * 8 + tig]);
            af[2] = __float_as_uint(S[m0 + grp][k8 * 8 + tig + 4]);
            af[3] = __float_as_uint(S[m0 + grp + 8][k8 * 8 + tig + 4]);
#pragma unroll
            for (int nn = 0; nn < 4; nn++) {
                uint32_t bf[2];
                bf[0] = __float_as_uint(Vs[k8 * 8 + tig][nn * 8 + grp]);
                bf[1] = __float_as_uint(Vs[k8 * 8 + tig + 4][nn * 8 + grp]);
                mma_tf32(oacc[nn], af, bf);
            }
        }
        float inva = sinv[m0 + grp], invb = sinv[m0 + grp + 8];
        int ta = tbase + (m0 + grp) * tstride;
        int tb = tbase + (m0 + grp + 8) * tstride;
        float* Oa = O + (size_t)ta * 256 + hoff;
        float* Ob = O + (size_t)tb * 256 + hoff;
#pragma unroll
        for (int nn = 0; nn < 4; nn++) {
            int c = nn * 8 + tig * 2;
            *(float2*)&Oa[c] = make_float2(oacc[nn][0] * inva, oacc[nn][1] * inva);
            *(float2*)&Ob[c] = make_float2(oacc[nn][2] * invb, oacc[nn][3] * invb);
        }
    }
}

// ---------------- tensor-core final GEMM (tf32): out = sc + x2 + (oh+ow)@W + b --------------
__global__ __launch_bounds__(256) void k_final(
    const float* __restrict__ oh1, const float* __restrict__ ow1,
    const float* __restrict__ oh2, const float* __restrict__ ow2,
    const float* __restrict__ W1, const float* __restrict__ W2,
    const float* __restrict__ b1, const float* __restrict__ b2,
    const float* __restrict__ p1, const float* __restrict__ x2,
    float* __restrict__ out) {
    __shared__ float As[2][16][132];
    __shared__ float Bs[2][16][132];
    int t0 = blockIdx.x * 128, o0 = blockIdx.y * 128;
    int tid = threadIdx.x;

#pragma unroll
    for (int j = 0; j < 2; j++) {
        int i = tid + 256 * j; int kk4 = i & 3, tt = i >> 2;
        float4 va = *(const float4*)&oh1[(size_t)(t0 + tt) * 256 + kk4 * 4];
        float4 vb = *(const float4*)&ow1[(size_t)(t0 + tt) * 256 + kk4 * 4];
        As[0][kk4 * 4 + 0][tt] = to_tf32(va.x + vb.x);
        As[0][kk4 * 4 + 1][tt] = to_tf32(va.y + vb.y);
        As[0][kk4 * 4 + 2][tt] = to_tf32(va.z + vb.z);
        As[0][kk4 * 4 + 3][tt] = to_tf32(va.w + vb.w);
    }
#pragma unroll
    for (int j = 0; j < 8; j++) {
        int i = tid + 256 * j; int kk = i >> 7, oo = i & 127;
        Bs[0][kk][oo] = to_tf32(W1[kk * 256 + o0 + oo]);
    }
    __syncthreads();

    int warp = tid >> 5, lane = tid & 31;
    int warpM = warp >> 2, warpN = warp & 3;
    int grp = lane >> 2, tig = lane & 3;
    float acc[4][4][4] = {};
    int cur = 0;
    for (int kt = 0; kt < 32; kt++) {
        float ra[2][4], rb[8];
        if (kt + 1 < 32) {
            int kbn = (kt + 1) << 4;
            const float* A0 = (kbn < 256) ? oh1 : oh2;
            const float* A1 = (kbn < 256) ? ow1 : ow2;
            const float* W  = (kbn < 256) ? W1 : W2;
            int kboff = kbn & 255;
#pragma unroll
            for (int j = 0; j < 2; j++) {
                int i = tid + 256 * j; int kk4 = i & 3, tt = i >> 2;
                float4 va = *(const float4*)&A0[(size_t)(t0 + tt) * 256 + kboff + kk4 * 4];
                float4 vb = *(const float4*)&A1[(size_t)(t0 + tt) * 256 + kboff + kk4 * 4];
                ra[j][0] = va.x + vb.x; ra[j][1] = va.y + vb.y;
                ra[j][2] = va.z + vb.z; ra[j][3] = va.w + vb.w;
            }
#pragma unroll
            for (int j = 0; j < 8; j++) {
                int i = tid + 256 * j; int kk = i >> 7, oo = i & 127;
                rb[j] = W[(kboff + kk) * 256 + o0 + oo];
            }
        }
#pragma unroll
        for (int k8 = 0; k8 < 16; k8 += 8) {
            uint32_t af[4][4], bf[4][2];
#pragma unroll
            for (int mm = 0; mm < 4; mm++) {
                int r = warpM * 64 + mm * 16 + grp;
                af[mm][0] = __float_as_uint(As[cur][k8 + tig][r]);
                af[mm][1] = __float_as_uint(As[cur][k8 + tig][r + 8]);
                af[mm][2] = __float_as_uint(As[cur][k8 + tig + 4][r]);
                af[mm][3] = __float_as_uint(As[cur][k8 + tig + 4][r + 8]);
            }
#pragma unroll
            for (int nn = 0; nn < 4; nn++) {
                int c = warpN * 32 + nn * 8 + grp;
                bf[nn][0] = __float_as_uint(Bs[cur][k8 + tig][c]);
                bf[nn][1] = __float_as_uint(Bs[cur][k8 + tig + 4][c]);
            }
#pragma unroll
            for (int mm = 0; mm < 4; mm++)
#pragma unroll
                for (int nn = 0; nn < 4; nn++)
                    mma_tf32(acc[mm][nn], af[mm], bf[nn]);
        }
        if (kt + 1 < 32) {
            int nb = cur ^ 1;
#pragma unroll
            for (int j = 0; j < 2; j++) {
                int i = tid + 256 * j; int kk4 = i & 3, tt = i >> 2;
                As[nb][kk4 * 4 + 0][tt] = to_tf32(ra[j][0]);
                As[nb][kk4 * 4 + 1][tt] = to_tf32(ra[j][1]);
                As[nb][kk4 * 4 + 2][tt] = to_tf32(ra[j][2]);
                As[nb][kk4 * 4 + 3][tt] = to_tf32(ra[j][3]);
            }
#pragma unroll
            for (int j = 0; j < 8; j++) {
                int i = tid + 256 * j; int kk = i >> 7, oo = i & 127;
                Bs[nb][kk][oo] = to_tf32(rb[j]);
            }
            cur = nb;
            __syncthreads();
        }
    }

    int b = t0 >> 12, hw0 = t0 & 4095;
#pragma unroll
    for (int mm = 0; mm < 4; mm++) {
#pragma unroll
        for (int nn = 0; nn < 4; nn++) {
            int c = o0 + warpN * 32 + nn * 8 + tig * 2;
            float bv0 = b1[c] + b2[c], bv1 = b1[c + 1] + b2[c + 1];
#pragma unroll
            for (int h = 0; h < 2; h++) {
                int r = warpM * 64 + mm * 16 + grp + h * 8;
                int t = t0 + r, hw = hw0 + r;
                float2 sc = *(const float2*)&p1[(size_t)t * 1024 + 768 + c];
                size_t gi0 = ((size_t)(b * 256 + c)) * HW + hw;
                size_t gi1 = ((size_t)(b * 256 + c + 1)) * HW + hw;
                out[gi0] = acc[mm][nn][h * 2]     + bv0 + sc.x + x2[gi0];
                out[gi1] = acc[mm][nn][h * 2 + 1] + bv1 + sc.y + x2[gi1];
            }
        }
    }
}

// ---------------- host launch ----------------
extern "C" void kernel_launch(void* const* d_in, const int* in_sizes, int n_in,
                              void* d_out, int out_size) {
    const float* x1      = (const float*)d_in[0];
    const float* x2      = (const float*)d_in[1];
    const float* ln1q_w  = (const float*)d_in[2];
    const float* ln1q_b  = (const float*)d_in[3];
    const float* ln2kv_w = (const float*)d_in[4];
    const float* ln2kv_b = (const float*)d_in[5];
    const float* Wq1     = (const float*)d_in[6];
    const float* Wkv2    = (const float*)d_in[7];
    const float* Wout1   = (const float*)d_in[8];
    const float* bout1   = (const float*)d_in[9];
    const float* ln2q_w  = (const float*)d_in[10];
    const float* ln2q_b  = (const float*)d_in[11];
    const float* ln1kv_w = (const float*)d_in[12];
    const float* ln1kv_b = (const float*)d_in[13];
    const float* Wq2     = (const float*)d_in[14];
    const float* Wkv1    = (const float*)d_in[15];
    const float* Wout2   = (const float*)d_in[16];
    const float* bout2   = (const float*)d_in[17];
    const float* Wsc     = (const float*)d_in[18];
    const float* bn_g    = (const float*)d_in[19];
    const float* bn_b    = (const float*)d_in[20];
    const float* bn_m    = (const float*)d_in[21];
    const float* bn_v    = (const float*)d_in[22];
    float* out = (float*)d_out;

    float *mu1, *rs1, *mu2, *rs2, *p1, *p2, *oh1, *ow1, *oh2, *ow2;
    float *W1cat, *W2cat, *b1cat, *b2cat, *cs1, *cs2;
    cudaGetSymbolAddress((void**)&mu1, g_mu1);
    cudaGetSymbolAddress((void**)&rs1, g_rs1);
    cudaGetSymbolAddress((void**)&mu2, g_mu2);
    cudaGetSymbolAddress((void**)&rs2, g_rs2);
    cudaGetSymbolAddress((void**)&p1, g_p1);
    cudaGetSymbolAddress((void**)&p2, g_p2);
    cudaGetSymbolAddress((void**)&oh1, g_oh1);
    cudaGetSymbolAddress((void**)&ow1, g_ow1);
    cudaGetSymbolAddress((void**)&oh2, g_oh2);
    cudaGetSymbolAddress((void**)&ow2, g_ow2);
    cudaGetSymbolAddress((void**)&W1cat, g_W1cat);
    cudaGetSymbolAddress((void**)&W2cat, g_W2cat);
    cudaGetSymbolAddress((void**)&b1cat, g_b1cat);
    cudaGetSymbolAddress((void**)&b2cat, g_b2cat);
    cudaGetSymbolAddress((void**)&cs1, g_cs1);
    cudaGetSymbolAddress((void**)&cs2, g_cs2);

    // weight/bias folding
    k_fold_wcat<<<(384 * 1024 + 256 * 768 + 255) / 256, 256>>>(
        Wq1, ln1q_w, Wkv1, ln1kv_w, Wsc, bn_g, bn_v, Wq2, ln2q_w, Wkv2, ln2kv_w,
        W1cat, W2cat);
    k_fold_bias<<<7, 256>>>(Wq1, ln1q_w, ln1q_b, Wkv1, ln1kv_w, ln1kv_b,
                            bn_g, bn_b, bn_m, bn_v,
                            Wq2, ln2q_w, ln2q_b, Wkv2, ln2kv_w, ln2kv_b,
                            b1cat, b2cat, cs1, cs2);

    // LN stats (both inputs, one launch)
    k_stats<<<2048, 256>>>(x1, x2, mu1, rs1, mu2, rs2);

    // fused projections (tf32 tensor cores, LN deferred to epilogue)
    k_proj<<<dim3(256, 8), 256>>>(x1, 384, 1024, mu1, rs1, W1cat, b1cat, cs1, 768, p1);
    k_proj<<<dim3(256, 6), 256>>>(x2, 256, 768, mu2, rs2, W2cat, b2cat, cs2, 1 << 30, p2);

    // axial attention (tf32 mma), both axes per launch
    k_attn<<<8192, 128>>>(p1, 1024, p2 + 256, p2 + 512, 768, oh1, ow1);
    k_attn<<<8192, 128>>>(p2, 768, p1 + 256, p1 + 512, 1024, oh2, ow2);

    // output GEMMs + shortcut + residual + NCHW transpose (tf32 tensor cores)
    k_final<<<dim3(256, 2), 256>>>(oh1, ow1, oh2, ow2, Wout1, Wout2, bout1, bout2,
                                   p1, x2, out);
}

// round 10
// speedup vs baseline: 4.6772x; 1.0888x over previous
#include <cuda_runtime.h>
#include <math.h>
#include <stdint.h>

#define NTOK 32768
#define HW 4096
#define EPSV 1e-5f

// ---------------- scratch (static device memory; no allocations) ----------------
__device__ float g_mu1[NTOK], g_rs1[NTOK], g_mu2[NTOK], g_rs2[NTOK];
__device__ float g_p1[NTOK * 1024];   // per token: [q1(256) | k1(256) | v1(256) | sc(256)]
__device__ float g_p2[NTOK * 768];    // per token: [q2(256) | k2(256) | v2(256)]
__device__ float g_oh1[NTOK * 256], g_ow1[NTOK * 256];
__device__ float g_oh2[NTOK * 256], g_ow2[NTOK * 256];
__device__ float g_Wt1[1024 * 384];    // TRANSPOSED folded weights [out][C], tf32-rounded
__device__ float g_Wt2[768 * 256];
__device__ float g_b1cat[1024], g_b2cat[768];
__device__ float g_cs1[768], g_cs2[768];   // column sums of folded W (LN-defer term)

// ---------------- tf32 helpers ----------------
__device__ __forceinline__ float to_tf32(float x) {
    float y;
    asm("cvt.rna.tf32.f32 %0, %1;" : "=f"(y) : "f"(x));
    return y;
}

__device__ __forceinline__ void mma_tf32(float* d, const uint32_t* a, const uint32_t* b) {
    asm volatile(
        "mma.sync.aligned.m16n8k8.row.col.f32.tf32.tf32.f32 "
        "{%0,%1,%2,%3}, {%4,%5,%6,%7}, {%8,%9}, {%0,%1,%2,%3};\n"
        : "+f"(d[0]), "+f"(d[1]), "+f"(d[2]), "+f"(d[3])
        : "r"(a[0]), "r"(a[1]), "r"(a[2]), "r"(a[3]), "r"(b[0]), "r"(b[1]));
}

__device__ __forceinline__ void cp_async16(void* smem_dst, const void* gmem_src) {
    uint32_t d = (uint32_t)__cvta_generic_to_shared(smem_dst);
    asm volatile("cp.async.cg.shared.global [%0], [%1], 16;\n" :: "r"(d), "l"(gmem_src));
}

__device__ __forceinline__ void ldsm_x4(uint32_t& r0, uint32_t& r1, uint32_t& r2,
                                        uint32_t& r3, const void* smem) {
    uint32_t a = (uint32_t)__cvta_generic_to_shared(smem);
    asm volatile("ldmatrix.sync.aligned.m8n8.x4.shared.b16 {%0,%1,%2,%3}, [%4];\n"
                 : "=r"(r0), "=r"(r1), "=r"(r2), "=r"(r3) : "r"(a));
}

// ---------------- fold: TRANSPOSED concatenated weight matrices (tf32) ----------------
// Wt1[o][c], o in [0,1024): 0-255 q1, 256-767 kv1, 768-1023 BN-folded shortcut conv
// Wt2[o][c], o in [0,768):  0-255 q2, 256-767 kv2
__global__ void k_fold_wcat(const float* __restrict__ Wq1, const float* __restrict__ ln1qw,
                            const float* __restrict__ Wkv1, const float* __restrict__ ln1kvw,
                            const float* __restrict__ Wsc, const float* __restrict__ bng,
                            const float* __restrict__ bnv,
                            const float* __restrict__ Wq2, const float* __restrict__ ln2qw,
                            const float* __restrict__ Wkv2, const float* __restrict__ ln2kvw,
                            float* __restrict__ Wt1, float* __restrict__ Wt2) {
    int idx = blockIdx.x * 256 + threadIdx.x;
    const int N1 = 1024 * 384;
    if (idx < N1) {
        int o = idx / 384, c = idx % 384;
        float v;
        if (o < 256)      v = Wq1[c * 256 + o] * ln1qw[c];
        else if (o < 768) v = Wkv1[c * 512 + (o - 256)] * ln1kvw[c];
        else { int oo = o - 768; v = Wsc[oo * 384 + c] * bng[oo] * rsqrtf(bnv[oo] + EPSV); }
        Wt1[idx] = to_tf32(v);
    } else if (idx < N1 + 768 * 256) {
        int i2 = idx - N1;
        int o = i2 >> 8, c = i2 & 255;
        float v;
        if (o < 256) v = Wq2[c * 256 + o] * ln2qw[c];
        else         v = Wkv2[c * 512 + (o - 256)] * ln2kvw[c];
        Wt2[i2] = to_tf32(v);
    }
}

// biases + column sums of folded (tf32) W for the LN-defer epilogue
__global__ void k_fold_bias(const float* __restrict__ Wq1, const float* __restrict__ ln1qw,
                            const float* __restrict__ ln1qb,
                            const float* __restrict__ Wkv1, const float* __restrict__ ln1kvw,
                            const float* __restrict__ ln1kvb,
                            const float* __restrict__ bng,
                            const float* __restrict__ bnb, const float* __restrict__ bnm,
                            const float* __restrict__ bnv,
                            const float* __restrict__ Wq2, const float* __restrict__ ln2qw,
                            const float* __restrict__ ln2qb,
                            const float* __restrict__ Wkv2, const float* __restrict__ ln2kvw,
                            const float* __restrict__ ln2kvb,
                            float* __restrict__ b1cat, float* __restrict__ b2cat,
                            float* __restrict__ cs1, float* __restrict__ cs2) {
    int og = blockIdx.x * 256 + threadIdx.x;
    if (og < 1024) {
        float b = 0.f, cs = 0.f;
        if (og < 256) {
            for (int c = 0; c < 384; c++) {
                b += ln1qb[c] * Wq1[c * 256 + og];
                cs += to_tf32(ln1qw[c] * Wq1[c * 256 + og]);
            }
            cs1[og] = cs;
        } else if (og < 768) {
            int o = og - 256;
            for (int c = 0; c < 384; c++) {
                b += ln1kvb[c] * Wkv1[c * 512 + o];
                cs += to_tf32(ln1kvw[c] * Wkv1[c * 512 + o]);
            }
            cs1[og] = cs;
        } else {
            int oo = og - 768;
            float g = bng[oo] * rsqrtf(bnv[oo] + EPSV);
            b = bnb[oo] - bnm[oo] * g;
        }
        b1cat[og] = b;
    } else if (og < 1792) {
        int o2 = og - 1024;
        float b = 0.f, cs = 0.f;
        if (o2 < 256) {
            for (int c = 0; c < 256; c++) {
                b += ln2qb[c] * Wq2[c * 256 + o2];
                cs += to_tf32(ln2qw[c] * Wq2[c * 256 + o2]);
            }
        } else {
            int o = o2 - 256;
            for (int c = 0; c < 256; c++) {
                b += ln2kvb[c] * Wkv2[c * 512 + o];
                cs += to_tf32(ln2kvw[c] * Wkv2[c * 512 + o]);
            }
        }
        b2cat[o2] = b;
        cs2[o2] = cs;
    }
}

// ---------------- per-token LN statistics for BOTH inputs in one launch ----------------
__global__ void k_stats(const float* __restrict__ X1, const float* __restrict__ X2,
                        float* __restrict__ mu1, float* __restrict__ rs1,
                        float* __restrict__ mu2, float* __restrict__ rs2) {
    __shared__ float ss[8][33], sq[8][33];
    int half = blockIdx.x >> 10;
    const float* X = half ? X2 : X1;
    int C = half ? 256 : 384;
    float* mu = half ? mu2 : mu1;
    float* rs = half ? rs2 : rs1;
    int lane = threadIdx.x & 31, cs = threadIdx.x >> 5;
    int t = (blockIdx.x & 1023) * 32 + lane;
    int b = t >> 12, hw = t & 4095;
    const float* p = X + (size_t)b * C * HW + hw;
    float s = 0.f, s2 = 0.f;
    for (int c = cs; c < C; c += 8) {
        float v = p[(size_t)c * HW];
        s += v; s2 += v * v;
    }
    ss[cs][lane] = s; sq[cs][lane] = s2;
    __syncthreads();
    if (threadIdx.x < 32) {
        float a = 0.f, q = 0.f;
#pragma unroll
        for (int j = 0; j < 8; j++) { a += ss[j][lane]; q += sq[j][lane]; }
        float m = a / C;
        mu[t] = m;
        rs[t] = rsqrtf(q / C - m * m + EPSV);
    }
}

// ---------------- tensor-core projection GEMM (tf32, LN-deferred, cp.async + ldmatrix-B) ----
// Mainloop: raw X @ Wt^T. Epilogue: rs*(acc - mu*colsum) + bias (LN defer); shortcut cols plain.
// A smem [k][m] pad 136 (conflict-free scalar LDS); B smem [n][k] pad 20 (LDSM.x4, conflict-free).
__global__ __launch_bounds__(256, 2) void k_proj(
    const float* __restrict__ X, int C, int Nout,
    const float* __restrict__ mu, const float* __restrict__ rs,
    const float* __restrict__ Wt, const float* __restrict__ bias,
    const float* __restrict__ cs, int sc_start,
    float* __restrict__ out) {
    __shared__ float As[2][16][136];
    __shared__ float Bt[2][128][20];
    __shared__ float smu[128], srs[128];
    int t0 = blockIdx.x * 128, o0 = blockIdx.y * 128;
    int tid = threadIdx.x;
    if (tid < 128) { smu[tid] = mu[t0 + tid]; srs[tid] = rs[t0 + tid]; }
    int bb = t0 >> 12, hw0 = t0 & 4095;
    const float* Xb = X + (size_t)bb * C * HW + hw0;

    int KT = C >> 4;
    // prologue: tile 0
    {
#pragma unroll
        for (int j = 0; j < 2; j++) {
            int id = tid + 256 * j;
            int kk = id >> 5, c4 = id & 31;              // A: 16 rows x 32 chunks
            cp_async16(&As[0][kk][c4 * 4], Xb + (size_t)kk * HW + c4 * 4);
            int nr = id >> 2, k4 = id & 3;               // B: 128 rows x 4 chunks
            cp_async16(&Bt[0][nr][k4 * 4], Wt + (size_t)(o0 + nr) * C + k4 * 4);
        }
        asm volatile("cp.async.commit_group;\n");
        asm volatile("cp.async.wait_group 0;\n");
        __syncthreads();
    }

    int warp = tid >> 5, lane = tid & 31;
    int warpM = warp >> 2, warpN = warp & 3;
    int grp = lane >> 2, tig = lane & 3;
    int oct = lane >> 3, lo = lane & 7;
    float acc[4][4][4] = {};
    int cur = 0;
    for (int kt = 0; kt < KT; kt++) {
        if (kt + 1 < KT) {
            int k0 = (kt + 1) << 4;
            int nb = cur ^ 1;
#pragma unroll
            for (int j = 0; j < 2; j++) {
                int id = tid + 256 * j;
                int kk = id >> 5, c4 = id & 31;
                cp_async16(&As[nb][kk][c4 * 4], Xb + (size_t)(k0 + kk) * HW + c4 * 4);
                int nr = id >> 2, k4 = id & 3;
                cp_async16(&Bt[nb][nr][k4 * 4], Wt + (size_t)(o0 + nr) * C + k0 + k4 * 4);
            }
            asm volatile("cp.async.commit_group;\n");
        }
#pragma unroll
        for (int k8 = 0; k8 < 16; k8 += 8) {
            uint32_t af[4][4], bf[4][2];
#pragma unroll
            for (int mm = 0; mm < 4; mm++) {
                int r = warpM * 64 + mm * 16 + grp;
                af[mm][0] = __float_as_uint(As[cur][k8 + tig][r]);
                af[mm][1] = __float_as_uint(As[cur][k8 + tig][r + 8]);
                af[mm][2] = __float_as_uint(As[cur][k8 + tig + 4][r]);
                af[mm][3] = __float_as_uint(As[cur][k8 + tig + 4][r + 8]);
            }
            // B frags via ldmatrix: 2x x4, each covering two nn-chunks.
            // lanes 0-7: rows nn*8+lo @k8 ; 8-15: same rows @k8+4 ;
            // 16-23: rows (nn+1)*8+lo @k8 ; 24-31: @k8+4
#pragma unroll
            for (int p = 0; p < 2; p++) {
                int nrow = warpN * 32 + p * 16 + ((oct >> 1) << 3) + lo;
                int kc = k8 + ((oct & 1) << 2);
                ldsm_x4(bf[p * 2][0], bf[p * 2][1], bf[p * 2 + 1][0], bf[p * 2 + 1][1],
                        &Bt[cur][nrow][kc]);
            }
#pragma unroll
            for (int mm = 0; mm < 4; mm++)
#pragma unroll
                for (int nn = 0; nn < 4; nn++)
                    mma_tf32(acc[mm][nn], af[mm], bf[nn]);
        }
        if (kt + 1 < KT) {
            asm volatile("cp.async.wait_group 0;\n");
            __syncthreads();
            cur ^= 1;
        }
    }

    bool isc = (o0 >= sc_start);
#pragma unroll
    for (int mm = 0; mm < 4; mm++) {
#pragma unroll
        for (int nn = 0; nn < 4; nn++) {
            int c = o0 + warpN * 32 + nn * 8 + tig * 2;
            float bv0 = bias[c], bv1 = bias[c + 1];
            float cs0 = 0.f, cs1v = 0.f;
            if (!isc) { cs0 = cs[c]; cs1v = cs[c + 1]; }
#pragma unroll
            for (int h = 0; h < 2; h++) {
                int r = warpM * 64 + mm * 16 + grp + h * 8;
                float v0 = acc[mm][nn][h * 2], v1 = acc[mm][nn][h * 2 + 1];
                if (!isc) {
                    float rv = srs[r], m = smu[r];
                    v0 = rv * (v0 - m * cs0) + bv0;
                    v1 = rv * (v1 - m * cs1v) + bv1;
                } else { v0 += bv0; v1 += bv1; }
                *(float2*)&out[(size_t)(t0 + r) * Nout + c] = make_float2(v0, v1);
            }
        }
    }
}

// ---------------- axial attention (tf32 tensor cores), BOTH axes in one launch -------------
__global__ __launch_bounds__(128) void k_attn(
    const float* __restrict__ Q, int qpitch,
    const float* __restrict__ K, const float* __restrict__ V,
    int kvpitch, float* __restrict__ Oh, float* __restrict__ Ow) {
    __shared__ float Qs[64][36];
    __shared__ float Ks[64][36];
    __shared__ float Vs[64][36];
    __shared__ float S[64][68];
    __shared__ float sinv[64];
    int bx = blockIdx.x;
    int head = bx & 7, line = (bx >> 3) & 63, b = (bx >> 9) & 7, axis = bx >> 12;
    int tstride = axis ? 1 : 64;
    int tbase = b * 4096 + (axis ? line * 64 : line);
    int hoff = head * 32;
    float* O = axis ? Ow : Oh;
    int tid = threadIdx.x;
    const float scale = 0.17677669529663687f; // 1/sqrt(32), folded into Q

    for (int i = tid; i < 64 * 8; i += 128) {
        int r = i >> 3, q4 = i & 7;
        size_t t = (size_t)(tbase + r * tstride);
        float4 vq = *(const float4*)&Q[t * qpitch + hoff + q4 * 4];
        float4 vk = *(const float4*)&K[t * kvpitch + hoff + q4 * 4];
        float4 vv = *(const float4*)&V[t * kvpitch + hoff + q4 * 4];
        *(float4*)&Qs[r][q4 * 4] = make_float4(to_tf32(vq.x * scale), to_tf32(vq.y * scale),
                                               to_tf32(vq.z * scale), to_tf32(vq.w * scale));
        *(float4*)&Ks[r][q4 * 4] = make_float4(to_tf32(vk.x), to_tf32(vk.y),
                                               to_tf32(vk.z), to_tf32(vk.w));
        *(float4*)&Vs[r][q4 * 4] = make_float4(to_tf32(vv.x), to_tf32(vv.y),
                                               to_tf32(vv.z), to_tf32(vv.w));
    }
    __syncthreads();

    int warp = tid >> 5, lane = tid & 31;
    int grp = lane >> 2, tig = lane & 3;
    int m0 = warp * 16;

    {
        uint32_t af[4][4];
#pragma unroll
        for (int k8 = 0; k8 < 4; k8++) {
            af[k8][0] = __float_as_uint(Qs[m0 + grp][k8 * 8 + tig]);
            af[k8][1] = __float_as_uint(Qs[m0 + grp + 8][k8 * 8 + tig]);
            af[k8][2] = __float_as_uint(Qs[m0 + grp][k8 * 8 + tig + 4]);
            af[k8][3] = __float_as_uint(Qs[m0 + grp + 8][k8 * 8 + tig + 4]);
        }
#pragma unroll
        for (int n8 = 0; n8 < 8; n8++) {
            float sacc[4] = {};
#pragma unroll
            for (int k8 = 0; k8 < 4; k8++) {
                uint32_t bf[2];
                bf[0] = __float_as_uint(Ks[n8 * 8 + grp][k8 * 8 + tig]);
                bf[1] = __float_as_uint(Ks[n8 * 8 + grp][k8 * 8 + tig + 4]);
                mma_tf32(sacc, af[k8], bf);
            }
            *(float2*)&S[m0 + grp][n8 * 8 + tig * 2]     = make_float2(sacc[0], sacc[1]);
            *(float2*)&S[m0 + grp + 8][n8 * 8 + tig * 2] = make_float2(sacc[2], sacc[3]);
        }
    }
    __syncthreads();

    {
        int row = tid >> 1, half = tid & 1;
        float* sr = &S[row][half * 32];
        float m = -1e30f;
#pragma unroll 8
        for (int j = 0; j < 32; j++) m = fmaxf(m, sr[j]);
        m = fmaxf(m, __shfl_xor_sync(0xffffffffu, m, 1));
        float sum = 0.f;
#pragma unroll 8
        for (int j = 0; j < 32; j++) {
            float e = __expf(sr[j] - m);
            sum += e;
            sr[j] = to_tf32(e);
        }
        sum += __shfl_xor_sync(0xffffffffu, sum, 1);
        if (half == 0) sinv[row] = 1.f / sum;
    }
    __syncthreads();

    {
        float oacc[4][4] = {};
#pragma unroll
        for (int k8 = 0; k8 < 8; k8++) {
            uint32_t af[4];
            af[0] = __float_as_uint(S[m0 + grp][k8 * 8 + tig]);
            af[1] = __float_as_uint(S[m0 + grp + 8][k8 * 8 + tig]);
            af[2] = __float_as_uint(S[m0 + grp][k8 * 8 + tig + 4]);
            af[3] = __float_as_uint(S[m0 + grp + 8][k8 * 8 + tig + 4]);
#pragma unroll
            for (int nn = 0; nn < 4; nn++) {
                uint32_t bf[2];
                bf[0] = __float_as_uint(Vs[k8 * 8 + tig][nn * 8 + grp]);
                bf[1] = __float_as_uint(Vs[k8 * 8 + tig + 4][nn * 8 + grp]);
                mma_tf32(oacc[nn], af, bf);
            }
        }
        float inva = sinv[m0 + grp], invb = sinv[m0 + grp + 8];
        int ta = tbase + (m0 + grp) * tstride;
        int tb = tbase + (m0 + grp + 8) * tstride;
        float* Oa = O + (size_t)ta * 256 + hoff;
        float* Ob = O + (size_t)tb * 256 + hoff;
#pragma unroll
        for (int nn = 0; nn < 4; nn++) {
            int c = nn * 8 + tig * 2;
            *(float2*)&Oa[c] = make_float2(oacc[nn][0] * inva, oacc[nn][1] * inva);
            *(float2*)&Ob[c] = make_float2(oacc[nn][2] * invb, oacc[nn][3] * invb);
        }
    }
}

// ---------------- tensor-core final GEMM (tf32): out = sc + x2 + (oh+ow)@W + b --------------
__global__ __launch_bounds__(256) void k_final(
    const float* __restrict__ oh1, const float* __restrict__ ow1,
    const float* __restrict__ oh2, const float* __restrict__ ow2,
    const float* __restrict__ W1, const float* __restrict__ W2,
    const float* __restrict__ b1, const float* __restrict__ b2,
    const float* __restrict__ p1, const float* __restrict__ x2,
    float* __restrict__ out) {
    __shared__ float As[2][16][136];
    __shared__ float Bs[2][16][136];
    int t0 = blockIdx.x * 128, o0 = blockIdx.y * 128;
    int tid = threadIdx.x;

#pragma unroll
    for (int j = 0; j < 2; j++) {
        int i = tid + 256 * j; int kk4 = i & 3, tt = i >> 2;
        float4 va = *(const float4*)&oh1[(size_t)(t0 + tt) * 256 + kk4 * 4];
        float4 vb = *(const float4*)&ow1[(size_t)(t0 + tt) * 256 + kk4 * 4];
        As[0][kk4 * 4 + 0][tt] = to_tf32(va.x + vb.x);
        As[0][kk4 * 4 + 1][tt] = to_tf32(va.y + vb.y);
        As[0][kk4 * 4 + 2][tt] = to_tf32(va.z + vb.z);
        As[0][kk4 * 4 + 3][tt] = to_tf32(va.w + vb.w);
    }
#pragma unroll
    for (int j = 0; j < 8; j++) {
        int i = tid + 256 * j; int kk = i >> 7, oo = i & 127;
        Bs[0][kk][oo] = to_tf32(W1[kk * 256 + o0 + oo]);
    }
    __syncthreads();

    int warp = tid >> 5, lane = tid & 31;
    int warpM = warp >> 2, warpN = warp & 3;
    int grp = lane >> 2, tig = lane & 3;
    float acc[4][4][4] = {};
    int cur = 0;
    for (int kt = 0; kt < 32; kt++) {
        float ra[2][4], rb[8];
        if (kt + 1 < 32) {
            int kbn = (kt + 1) << 4;
            const float* A0 = (kbn < 256) ? oh1 : oh2;
            const float* A1 = (kbn < 256) ? ow1 : ow2;
            const float* W  = (kbn < 256) ? W1 : W2;
            int kboff = kbn & 255;
#pragma unroll
            for (int j = 0; j < 2; j++) {
                int i = tid + 256 * j; int kk4 = i & 3, tt = i >> 2;
                float4 va = *(const float4*)&A0[(size_t)(t0 + tt) * 256 + kboff + kk4 * 4];
                float4 vb = *(const float4*)&A1[(size_t)(t0 + tt) * 256 + kboff + kk4 * 4];
                ra[j][0] = va.x + vb.x; ra[j][1] = va.y + vb.y;
                ra[j][2] = va.z + vb.z; ra[j][3] = va.w + vb.w;
            }
#pragma unroll
            for (int j = 0; j < 8; j++) {
                int i = tid + 256 * j; int kk = i >> 7, oo = i & 127;
                rb[j] = W[(kboff + kk) * 256 + o0 + oo];
            }
        }
#pragma unroll
        for (int k8 = 0; k8 < 16; k8 += 8) {
            uint32_t af[4][4], bf[4][2];
#pragma unroll
            for (int mm = 0; mm < 4; mm++) {
                int r = warpM * 64 + mm * 16 + grp;
                af[mm][0] = __float_as_uint(As[cur][k8 + tig][r]);
                af[mm][1] = __float_as_uint(As[cur][k8 + tig][r + 8]);
                af[mm][2] = __float_as_uint(As[cur][k8 + tig + 4][r]);
                af[mm][3] = __float_as_uint(As[cur][k8 + tig + 4][r + 8]);
            }
#pragma unroll
            for (int nn = 0; nn < 4; nn++) {
                int c = warpN * 32 + nn * 8 + grp;
                bf[nn][0] = __float_as_uint(Bs[cur][k8 + tig][c]);
                bf[nn][1] = __float_as_uint(Bs[cur][k8 + tig + 4][c]);
            }
#pragma unroll
            for (int mm = 0; mm < 4; mm++)
#pragma unroll
                for (int nn = 0; nn < 4; nn++)
                    mma_tf32(acc[mm][nn], af[mm], bf[nn]);
        }
        if (kt + 1 < 32) {
            int nb = cur ^ 1;
#pragma unroll
            for (int j = 0; j < 2; j++) {
                int i = tid + 256 * j; int kk4 = i & 3, tt = i >> 2;
                As[nb][kk4 * 4 + 0][tt] = to_tf32(ra[j][0]);
                As[nb][kk4 * 4 + 1][tt] = to_tf32(ra[j][1]);
                As[nb][kk4 * 4 + 2][tt] = to_tf32(ra[j][2]);
                As[nb][kk4 * 4 + 3][tt] = to_tf32(ra[j][3]);
            }
#pragma unroll
            for (int j = 0; j < 8; j++) {
                int i = tid + 256 * j; int kk = i >> 7, oo = i & 127;
                Bs[nb][kk][oo] = to_tf32(rb[j]);
            }
            cur = nb;
            __syncthreads();
        }
    }

    int b = t0 >> 12, hw0 = t0 & 4095;
#pragma unroll
    for (int mm = 0; mm < 4; mm++) {
#pragma unroll
        for (int nn = 0; nn < 4; nn++) {
            int c = o0 + warpN * 32 + nn * 8 + tig * 2;
            float bv0 = b1[c] + b2[c], bv1 = b1[c + 1] + b2[c + 1];
#pragma unroll
            for (int h = 0; h < 2; h++) {
                int r = warpM * 64 + mm * 16 + grp + h * 8;
                int t = t0 + r, hw = hw0 + r;
                float2 sc = *(const float2*)&p1[(size_t)t * 1024 + 768 + c];
                size_t gi0 = ((size_t)(b * 256 + c)) * HW + hw;
                size_t gi1 = ((size_t)(b * 256 + c + 1)) * HW + hw;
                out[gi0] = acc[mm][nn][h * 2]     + bv0 + sc.x + x2[gi0];
                out[gi1] = acc[mm][nn][h * 2 + 1] + bv1 + sc.y + x2[gi1];
            }
        }
    }
}

// ---------------- host launch ----------------
extern "C" void kernel_launch(void* const* d_in, const int* in_sizes, int n_in,
                              void* d_out, int out_size) {
    const float* x1      = (const float*)d_in[0];
    const float* x2      = (const float*)d_in[1];
    const float* ln1q_w  = (const float*)d_in[2];
    const float* ln1q_b  = (const float*)d_in[3];
    const float* ln2kv_w = (const float*)d_in[4];
    const float* ln2kv_b = (const float*)d_in[5];
    const float* Wq1     = (const float*)d_in[6];
    const float* Wkv2    = (const float*)d_in[7];
    const float* Wout1   = (const float*)d_in[8];
    const float* bout1   = (const float*)d_in[9];
    const float* ln2q_w  = (const float*)d_in[10];
    const float* ln2q_b  = (const float*)d_in[11];
    const float* ln1kv_w = (const float*)d_in[12];
    const float* ln1kv_b = (const float*)d_in[13];
    const float* Wq2     = (const float*)d_in[14];
    const float* Wkv1    = (const float*)d_in[15];
    const float* Wout2   = (const float*)d_in[16];
    const float* bout2   = (const float*)d_in[17];
    const float* Wsc     = (const float*)d_in[18];
    const float* bn_g    = (const float*)d_in[19];
    const float* bn_b    = (const float*)d_in[20];
    const float* bn_m    = (const float*)d_in[21];
    const float* bn_v    = (const float*)d_in[22];
    float* out = (float*)d_out;

    float *mu1, *rs1, *mu2, *rs2, *p1, *p2, *oh1, *ow1, *oh2, *ow2;
    float *Wt1, *Wt2, *b1cat, *b2cat, *cs1, *cs2;
    cudaGetSymbolAddress((void**)&mu1, g_mu1);
    cudaGetSymbolAddress((void**)&rs1, g_rs1);
    cudaGetSymbolAddress((void**)&mu2, g_mu2);
    cudaGetSymbolAddress((void**)&rs2, g_rs2);
    cudaGetSymbolAddress((void**)&p1, g_p1);
    cudaGetSymbolAddress((void**)&p2, g_p2);
    cudaGetSymbolAddress((void**)&oh1, g_oh1);
    cudaGetSymbolAddress((void**)&ow1, g_ow1);
    cudaGetSymbolAddress((void**)&oh2, g_oh2);
    cudaGetSymbolAddress((void**)&ow2, g_ow2);
    cudaGetSymbolAddress((void**)&Wt1, g_Wt1);
    cudaGetSymbolAddress((void**)&Wt2, g_Wt2);
    cudaGetSymbolAddress((void**)&b1cat, g_b1cat);
    cudaGetSymbolAddress((void**)&b2cat, g_b2cat);
    cudaGetSymbolAddress((void**)&cs1, g_cs1);
    cudaGetSymbolAddress((void**)&cs2, g_cs2);

    // weight/bias folding (weights transposed to [out][C] for ldmatrix-B)
    k_fold_wcat<<<(1024 * 384 + 768 * 256 + 255) / 256, 256>>>(
        Wq1, ln1q_w, Wkv1, ln1kv_w, Wsc, bn_g, bn_v, Wq2, ln2q_w, Wkv2, ln2kv_w,
        Wt1, Wt2);
    k_fold_bias<<<7, 256>>>(Wq1, ln1q_w, ln1q_b, Wkv1, ln1kv_w, ln1kv_b,
                            bn_g, bn_b, bn_m, bn_v,
                            Wq2, ln2q_w, ln2q_b, Wkv2, ln2kv_w, ln2kv_b,
                            b1cat, b2cat, cs1, cs2);

    // LN stats (both inputs, one launch)
    k_stats<<<2048, 256>>>(x1, x2, mu1, rs1, mu2, rs2);

    // fused projections (tf32 tensor cores, LN deferred, ldmatrix-B)
    k_proj<<<dim3(256, 8), 256>>>(x1, 384, 1024, mu1, rs1, Wt1, b1cat, cs1, 768, p1);
    k_proj<<<dim3(256, 6), 256>>>(x2, 256, 768, mu2, rs2, Wt2, b2cat, cs2, 1 << 30, p2);

    // axial attention (tf32 mma), both axes per launch
    k_attn<<<8192, 128>>>(p1, 1024, p2 + 256, p2 + 512, 768, oh1, ow1);
    k_attn<<<8192, 128>>>(p2, 768, p1 + 256, p1 + 512, 1024, oh2, ow2);

    // output GEMMs + shortcut + residual + NCHW transpose (tf32 tensor cores)
    k_final<<<dim3(256, 2), 256>>>(oh1, ow1, oh2, ow2, Wout1, Wout2, bout1, bout2,
                                   p1, x2, out);
}

// round 12
// speedup vs baseline: 4.9712x; 1.0628x over previous
#include <cuda_runtime.h>
#include <math.h>
#include <stdint.h>

#define NTOK 32768
#define HW 4096
#define EPSV 1e-5f

// ---------------- scratch (static device memory; no allocations) ----------------
__device__ float g_mu1[NTOK], g_rs1[NTOK], g_mu2[NTOK], g_rs2[NTOK];
__device__ float g_p1[NTOK * 1024];   // per token: [q1(256) | k1(256) | v1(256) | sc(256)]
__device__ float g_p2[NTOK * 768];    // per token: [q2(256) | k2(256) | v2(256)]
__device__ float g_oh1[NTOK * 256], g_ow1[NTOK * 256];
__device__ float g_oh2[NTOK * 256], g_ow2[NTOK * 256];
__device__ float g_Wt1[1024 * 384];    // TRANSPOSED folded weights [out][C], tf32-rounded
__device__ float g_Wt2[768 * 256];
__device__ float g_b1cat[1024], g_b2cat[768];
__device__ float g_cs1[768], g_cs2[768];   // column sums of folded W (LN-defer term)

// ---------------- tf32 helpers ----------------
__device__ __forceinline__ float to_tf32(float x) {
    float y;
    asm("cvt.rna.tf32.f32 %0, %1;" : "=f"(y) : "f"(x));
    return y;
}

__device__ __forceinline__ void mma_tf32(float* d, const uint32_t* a, const uint32_t* b) {
    asm volatile(
        "mma.sync.aligned.m16n8k8.row.col.f32.tf32.tf32.f32 "
        "{%0,%1,%2,%3}, {%4,%5,%6,%7}, {%8,%9}, {%0,%1,%2,%3};\n"
        : "+f"(d[0]), "+f"(d[1]), "+f"(d[2]), "+f"(d[3])
        : "r"(a[0]), "r"(a[1]), "r"(a[2]), "r"(a[3]), "r"(b[0]), "r"(b[1]));
}

__device__ __forceinline__ void cp_async16(void* smem_dst, const void* gmem_src) {
    uint32_t d = (uint32_t)__cvta_generic_to_shared(smem_dst);
    asm volatile("cp.async.cg.shared.global [%0], [%1], 16;\n" :: "r"(d), "l"(gmem_src));
}

__device__ __forceinline__ void ldsm_x4(uint32_t& r0, uint32_t& r1, uint32_t& r2,
                                        uint32_t& r3, const void* smem) {
    uint32_t a = (uint32_t)__cvta_generic_to_shared(smem);
    asm volatile("ldmatrix.sync.aligned.m8n8.x4.shared.b16 {%0,%1,%2,%3}, [%4];\n"
                 : "=r"(r0), "=r"(r1), "=r"(r2), "=r"(r3) : "r"(a));
}

// ---------------- fold: TRANSPOSED concatenated weight matrices (tf32) ----------------
__global__ void k_fold_wcat(const float* __restrict__ Wq1, const float* __restrict__ ln1qw,
                            const float* __restrict__ Wkv1, const float* __restrict__ ln1kvw,
                            const float* __restrict__ Wsc, const float* __restrict__ bng,
                            const float* __restrict__ bnv,
                            const float* __restrict__ Wq2, const float* __restrict__ ln2qw,
                            const float* __restrict__ Wkv2, const float* __restrict__ ln2kvw,
                            float* __restrict__ Wt1, float* __restrict__ Wt2) {
    int idx = blockIdx.x * 256 + threadIdx.x;
    const int N1 = 1024 * 384;
    if (idx < N1) {
        int o = idx / 384, c = idx % 384;
        float v;
        if (o < 256)      v = Wq1[c * 256 + o] * ln1qw[c];
        else if (o < 768) v = Wkv1[c * 512 + (o - 256)] * ln1kvw[c];
        else { int oo = o - 768; v = Wsc[oo * 384 + c] * bng[oo] * rsqrtf(bnv[oo] + EPSV); }
        Wt1[idx] = to_tf32(v);
    } else if (idx < N1 + 768 * 256) {
        int i2 = idx - N1;
        int o = i2 >> 8, c = i2 & 255;
        float v;
        if (o < 256) v = Wq2[c * 256 + o] * ln2qw[c];
        else         v = Wkv2[c * 512 + (o - 256)] * ln2kvw[c];
        Wt2[i2] = to_tf32(v);
    }
}

// biases + column sums of folded (tf32) W for the LN-defer epilogue
__global__ void k_fold_bias(const float* __restrict__ Wq1, const float* __restrict__ ln1qw,
                            const float* __restrict__ ln1qb,
                            const float* __restrict__ Wkv1, const float* __restrict__ ln1kvw,
                            const float* __restrict__ ln1kvb,
                            const float* __restrict__ bng,
                            const float* __restrict__ bnb, const float* __restrict__ bnm,
                            const float* __restrict__ bnv,
                            const float* __restrict__ Wq2, const float* __restrict__ ln2qw,
                            const float* __restrict__ ln2qb,
                            const float* __restrict__ Wkv2, const float* __restrict__ ln2kvw,
                            const float* __restrict__ ln2kvb,
                            float* __restrict__ b1cat, float* __restrict__ b2cat,
                            float* __restrict__ cs1, float* __restrict__ cs2) {
    int og = blockIdx.x * 256 + threadIdx.x;
    if (og < 1024) {
        float b = 0.f, cs = 0.f;
        if (og < 256) {
            for (int c = 0; c < 384; c++) {
                b += ln1qb[c] * Wq1[c * 256 + og];
                cs += to_tf32(ln1qw[c] * Wq1[c * 256 + og]);
            }
            cs1[og] = cs;
        } else if (og < 768) {
            int o = og - 256;
            for (int c = 0; c < 384; c++) {
                b += ln1kvb[c] * Wkv1[c * 512 + o];
                cs += to_tf32(ln1kvw[c] * Wkv1[c * 512 + o]);
            }
            cs1[og] = cs;
        } else {
            int oo = og - 768;
            float g = bng[oo] * rsqrtf(bnv[oo] + EPSV);
            b = bnb[oo] - bnm[oo] * g;
        }
        b1cat[og] = b;
    } else if (og < 1792) {
        int o2 = og - 1024;
        float b = 0.f, cs = 0.f;
        if (o2 < 256) {
            for (int c = 0; c < 256; c++) {
                b += ln2qb[c] * Wq2[c * 256 + o2];
                cs += to_tf32(ln2qw[c] * Wq2[c * 256 + o2]);
            }
        } else {
            int o = o2 - 256;
            for (int c = 0; c < 256; c++) {
                b += ln2kvb[c] * Wkv2[c * 512 + o];
                cs += to_tf32(ln2kvw[c] * Wkv2[c * 512 + o]);
            }
        }
        b2cat[o2] = b;
        cs2[o2] = cs;
    }
}

// ---------------- per-token LN statistics for BOTH inputs in one launch ----------------
__global__ void k_stats(const float* __restrict__ X1, const float* __restrict__ X2,
                        float* __restrict__ mu1, float* __restrict__ rs1,
                        float* __restrict__ mu2, float* __restrict__ rs2) {
    __shared__ float ss[8][33], sq[8][33];
    int half = blockIdx.x >> 10;
    const float* X = half ? X2 : X1;
    int C = half ? 256 : 384;
    float* mu = half ? mu2 : mu1;
    float* rs = half ? rs2 : rs1;
    int lane = threadIdx.x & 31, cs = threadIdx.x >> 5;
    int t = (blockIdx.x & 1023) * 32 + lane;
    int b = t >> 12, hw = t & 4095;
    const float* p = X + (size_t)b * C * HW + hw;
    float s = 0.f, s2 = 0.f;
    for (int c = cs; c < C; c += 8) {
        float v = p[(size_t)c * HW];
        s += v; s2 += v * v;
    }
    ss[cs][lane] = s; sq[cs][lane] = s2;
    __syncthreads();
    if (threadIdx.x < 32) {
        float a = 0.f, q = 0.f;
#pragma unroll
        for (int j = 0; j < 8; j++) { a += ss[j][lane]; q += sq[j][lane]; }
        float m = a / C;
        mu[t] = m;
        rs[t] = rsqrtf(q / C - m * m + EPSV);
    }
}

// ---------------- merged projection GEMM (tf32, LN-deferred, cp.async + ldmatrix-B) ---------
// BOTH branches in one launch: grid.y 0-7 -> x1 (C=384, Nout=1024), 8-13 -> x2 (C=256, 768).
// BK=32 (halved barrier count), dynamic smem double buffer, 2 CTAs/SM.
#define PROJ_SMEM_FLOATS (2 * 32 * 136 + 2 * 128 * 36 + 256)
__global__ __launch_bounds__(256, 2) void k_proj(
    const float* __restrict__ x1, const float* __restrict__ x2,
    const float* __restrict__ mu1, const float* __restrict__ rs1,
    const float* __restrict__ mu2, const float* __restrict__ rs2,
    const float* __restrict__ Wt1, const float* __restrict__ Wt2,
    const float* __restrict__ b1cat, const float* __restrict__ b2cat,
    const float* __restrict__ cs1, const float* __restrict__ cs2,
    float* __restrict__ p1, float* __restrict__ p2) {
    extern __shared__ float dyn[];
    float (*As)[32][136] = (float(*)[32][136])dyn;
    float (*Bt)[128][36] = (float(*)[128][36])(dyn + 2 * 32 * 136);
    float* smu = dyn + 2 * 32 * 136 + 2 * 128 * 36;
    float* srs = smu + 128;

    int by = blockIdx.y;
    int br2 = (by >= 8);
    const float* X   = br2 ? x2 : x1;
    const float* mu  = br2 ? mu2 : mu1;
    const float* rs  = br2 ? rs2 : rs1;
    const float* Wt  = br2 ? Wt2 : Wt1;
    const float* bias = br2 ? b2cat : b1cat;
    const float* cs  = br2 ? cs2 : cs1;
    float* out       = br2 ? p2 : p1;
    int C    = br2 ? 256 : 384;
    int Nout = br2 ? 768 : 1024;
    int sc_start = br2 ? (1 << 30) : 768;
    int o0 = (br2 ? (by - 8) : by) * 128;

    int t0 = blockIdx.x * 128;
    int tid = threadIdx.x;
    if (tid < 128) { smu[tid] = mu[t0 + tid]; srs[tid] = rs[t0 + tid]; }
    int bb = t0 >> 12, hw0 = t0 & 4095;
    const float* Xb = X + (size_t)bb * C * HW + hw0;

    int KT = C >> 5;
    // prologue: tile 0  (A: 32x128 = 1024 f4; B: 128 rows x 8 k-chunks = 1024 f4)
    {
#pragma unroll
        for (int j = 0; j < 4; j++) {
            int id = tid + 256 * j;
            int kk = id >> 5, c4 = id & 31;
            cp_async16(&As[0][kk][c4 * 4], Xb + (size_t)kk * HW + c4 * 4);
            int nr = id >> 3, k4 = id & 7;
            cp_async16(&Bt[0][nr][k4 * 4], Wt + (size_t)(o0 + nr) * C + k4 * 4);
        }
        asm volatile("cp.async.commit_group;\n");
        asm volatile("cp.async.wait_group 0;\n");
        __syncthreads();
    }

    int warp = tid >> 5, lane = tid & 31;
    int warpM = warp >> 2, warpN = warp & 3;
    int grp = lane >> 2, tig = lane & 3;
    int oct = lane >> 3, lo = lane & 7;
    float acc[4][4][4] = {};
    int cur = 0;
    for (int kt = 0; kt < KT; kt++) {
        if (kt + 1 < KT) {
            int k0 = (kt + 1) << 5;
            int nb = cur ^ 1;
#pragma unroll
            for (int j = 0; j < 4; j++) {
                int id = tid + 256 * j;
                int kk = id >> 5, c4 = id & 31;
                cp_async16(&As[nb][kk][c4 * 4], Xb + (size_t)(k0 + kk) * HW + c4 * 4);
                int nr = id >> 3, k4 = id & 7;
                cp_async16(&Bt[nb][nr][k4 * 4], Wt + (size_t)(o0 + nr) * C + k0 + k4 * 4);
            }
            asm volatile("cp.async.commit_group;\n");
        }
#pragma unroll
        for (int k8 = 0; k8 < 32; k8 += 8) {
            uint32_t af[4][4], bf[4][2];
#pragma unroll
            for (int mm = 0; mm < 4; mm++) {
                int r = warpM * 64 + mm * 16 + grp;
                af[mm][0] = __float_as_uint(As[cur][k8 + tig][r]);
                af[mm][1] = __float_as_uint(As[cur][k8 + tig][r + 8]);
                af[mm][2] = __float_as_uint(As[cur][k8 + tig + 4][r]);
                af[mm][3] = __float_as_uint(As[cur][k8 + tig + 4][r + 8]);
            }
#pragma unroll
            for (int p = 0; p < 2; p++) {
                int nrow = warpN * 32 + p * 16 + ((oct >> 1) << 3) + lo;
                int kc = k8 + ((oct & 1) << 2);
                ldsm_x4(bf[p * 2][0], bf[p * 2][1], bf[p * 2 + 1][0], bf[p * 2 + 1][1],
                        &Bt[cur][nrow][kc]);
            }
#pragma unroll
            for (int mm = 0; mm < 4; mm++)
#pragma unroll
                for (int nn = 0; nn < 4; nn++)
                    mma_tf32(acc[mm][nn], af[mm], bf[nn]);
        }
        if (kt + 1 < KT) {
            asm volatile("cp.async.wait_group 0;\n");
            __syncthreads();
            cur ^= 1;
        }
    }

    bool isc = (o0 >= sc_start);
#pragma unroll
    for (int mm = 0; mm < 4; mm++) {
#pragma unroll
        for (int nn = 0; nn < 4; nn++) {
            int c = o0 + warpN * 32 + nn * 8 + tig * 2;
            float bv0 = bias[c], bv1 = bias[c + 1];
            float cs0 = 0.f, cs1v = 0.f;
            if (!isc) { cs0 = cs[c]; cs1v = cs[c + 1]; }
#pragma unroll
            for (int h = 0; h < 2; h++) {
                int r = warpM * 64 + mm * 16 + grp + h * 8;
                float v0 = acc[mm][nn][h * 2], v1 = acc[mm][nn][h * 2 + 1];
                if (!isc) {
                    float rv = srs[r], m = smu[r];
                    v0 = rv * (v0 - m * cs0) + bv0;
                    v1 = rv * (v1 - m * cs1v) + bv1;
                } else { v0 += bv0; v1 += bv1; }
                *(float2*)&out[(size_t)(t0 + r) * Nout + c] = make_float2(v0, v1);
            }
        }
    }
}

// ---------------- axial attention (tf32), BOTH branches AND axes in one launch -------------
// 16384 blocks: branch = bx>>13; within: axis = (bx>>12)&1, b=(bx>>9)&7, line=(bx>>3)&63, head=bx&7
__global__ __launch_bounds__(128) void k_attn(
    const float* __restrict__ p1, const float* __restrict__ p2,
    float* __restrict__ oh1, float* __restrict__ ow1,
    float* __restrict__ oh2, float* __restrict__ ow2) {
    __shared__ float Qs[64][36];
    __shared__ float Ks[64][36];
    __shared__ float Vs[64][36];
    __shared__ float S[64][68];
    __shared__ float sinv[64];
    int bx = blockIdx.x;
    int branch = bx >> 13;
    int head = bx & 7, line = (bx >> 3) & 63, b = (bx >> 9) & 7, axis = (bx >> 12) & 1;
    const float* Q = branch ? p2 : p1;
    const float* K = branch ? (p1 + 256) : (p2 + 256);
    const float* V = branch ? (p1 + 512) : (p2 + 512);
    int qpitch  = branch ? 768 : 1024;
    int kvpitch = branch ? 1024 : 768;
    float* O = branch ? (axis ? ow2 : oh2) : (axis ? ow1 : oh1);
    int tstride = axis ? 1 : 64;
    int tbase = b * 4096 + (axis ? line * 64 : line);
    int hoff = head * 32;
    int tid = threadIdx.x;
    const float scale = 0.17677669529663687f; // 1/sqrt(32), folded into Q

    for (int i = tid; i < 64 * 8; i += 128) {
        int r = i >> 3, q4 = i & 7;
        size_t t = (size_t)(tbase + r * tstride);
        float4 vq = *(const float4*)&Q[t * qpitch + hoff + q4 * 4];
        float4 vk = *(const float4*)&K[t * kvpitch + hoff + q4 * 4];
        float4 vv = *(const float4*)&V[t * kvpitch + hoff + q4 * 4];
        *(float4*)&Qs[r][q4 * 4] = make_float4(to_tf32(vq.x * scale), to_tf32(vq.y * scale),
                                               to_tf32(vq.z * scale), to_tf32(vq.w * scale));
        *(float4*)&Ks[r][q4 * 4] = make_float4(to_tf32(vk.x), to_tf32(vk.y),
                                               to_tf32(vk.z), to_tf32(vk.w));
        *(float4*)&Vs[r][q4 * 4] = make_float4(to_tf32(vv.x), to_tf32(vv.y),
                                               to_tf32(vv.z), to_tf32(vv.w));
    }
    __syncthreads();

    int warp = tid >> 5, lane = tid & 31;
    int grp = lane >> 2, tig = lane & 3;
    int m0 = warp * 16;

    {
        uint32_t af[4][4];
#pragma unroll
        for (int k8 = 0; k8 < 4; k8++) {
            af[k8][0] = __float_as_uint(Qs[m0 + grp][k8 * 8 + tig]);
            af[k8][1] = __float_as_uint(Qs[m0 + grp + 8][k8 * 8 + tig]);
            af[k8][2] = __float_as_uint(Qs[m0 + grp][k8 * 8 + tig + 4]);
            af[k8][3] = __float_as_uint(Qs[m0 + grp + 8][k8 * 8 + tig + 4]);
        }
#pragma unroll
        for (int n8 = 0; n8 < 8; n8++) {
            float sacc[4] = {};
#pragma unroll
            for (int k8 = 0; k8 < 4; k8++) {
                uint32_t bf[2];
                bf[0] = __float_as_uint(Ks[n8 * 8 + grp][k8 * 8 + tig]);
                bf[1] = __float_as_uint(Ks[n8 * 8 + grp][k8 * 8 + tig + 4]);
                mma_tf32(sacc, af[k8], bf);
            }
            *(float2*)&S[m0 + grp][n8 * 8 + tig * 2]     = make_float2(sacc[0], sacc[1]);
            *(float2*)&S[m0 + grp + 8][n8 * 8 + tig * 2] = make_float2(sacc[2], sacc[3]);
        }
    }
    __syncthreads();

    {
        int row = tid >> 1, half = tid & 1;
        float* sr = &S[row][half * 32];
        float m = -1e30f;
#pragma unroll 8
        for (int j = 0; j < 32; j++) m = fmaxf(m, sr[j]);
        m = fmaxf(m, __shfl_xor_sync(0xffffffffu, m, 1));
        float sum = 0.f;
#pragma unroll 8
        for (int j = 0; j < 32; j++) {
            float e = __expf(sr[j] - m);
            sum += e;
            sr[j] = to_tf32(e);
        }
        sum += __shfl_xor_sync(0xffffffffu, sum, 1);
        if (half == 0) sinv[row] = 1.f / sum;
    }
    __syncthreads();

    {
        float oacc[4][4] = {};
#pragma unroll
        for (int k8 = 0; k8 < 8; k8++) {
            uint32_t af[4];
            af[0] = __float_as_uint(S[m0 + grp][k8 * 8 + tig]);
            af[1] = __float_as_uint(S[m0 + grp + 8][k8 * 8 + tig]);
            af[2] = __float_as_uint(S[m0 + grp][k8 * 8 + tig + 4]);
            af[3] = __float_as_uint(S[m0 + grp + 8][k8 * 8 + tig + 4]);
#pragma unroll
            for (int nn = 0; nn < 4; nn++) {
                uint32_t bf[2];
                bf[0] = __float_as_uint(Vs[k8 * 8 + tig][nn * 8 + grp]);
                bf[1] = __float_as_uint(Vs[k8 * 8 + tig + 4][nn * 8 + grp]);
                mma_tf32(oacc[nn], af, bf);
            }
        }
        float inva = sinv[m0 + grp], invb = sinv[m0 + grp + 8];
        int ta = tbase + (m0 + grp) * tstride;
        int tb = tbase + (m0 + grp + 8) * tstride;
        float* Oa = O + (size_t)ta * 256 + hoff;
        float* Ob = O + (size_t)tb * 256 + hoff;
#pragma unroll
        for (int nn = 0; nn < 4; nn++) {
            int c = nn * 8 + tig * 2;
            *(float2*)&Oa[c] = make_float2(oacc[nn][0] * inva, oacc[nn][1] * inva);
            *(float2*)&Ob[c] = make_float2(oacc[nn][2] * invb, oacc[nn][3] * invb);
        }
    }
}

// ---------------- tensor-core final GEMM (tf32): out = sc + x2 + (oh+ow)@W + b --------------
__global__ __launch_bounds__(256) void k_final(
    const float* __restrict__ oh1, const float* __restrict__ ow1,
    const float* __restrict__ oh2, const float* __restrict__ ow2,
    const float* __restrict__ W1, const float* __restrict__ W2,
    const float* __restrict__ b1, const float* __restrict__ b2,
    const float* __restrict__ p1, const float* __restrict__ x2,
    float* __restrict__ out) {
    __shared__ float As[2][16][136];
    __shared__ float Bs[2][16][136];
    int t0 = blockIdx.x * 128, o0 = blockIdx.y * 128;
    int tid = threadIdx.x;

#pragma unroll
    for (int j = 0; j < 2; j++) {
        int i = tid + 256 * j; int kk4 = i & 3, tt = i >> 2;
        float4 va = *(const float4*)&oh1[(size_t)(t0 + tt) * 256 + kk4 * 4];
        float4 vb = *(const float4*)&ow1[(size_t)(t0 + tt) * 256 + kk4 * 4];
        As[0][kk4 * 4 + 0][tt] = to_tf32(va.x + vb.x);
        As[0][kk4 * 4 + 1][tt] = to_tf32(va.y + vb.y);
        As[0][kk4 * 4 + 2][tt] = to_tf32(va.z + vb.z);
        As[0][kk4 * 4 + 3][tt] = to_tf32(va.w + vb.w);
    }
#pragma unroll
    for (int j = 0; j < 8; j++) {
        int i = tid + 256 * j; int kk = i >> 7, oo = i & 127;
        Bs[0][kk][oo] = to_tf32(W1[kk * 256 + o0 + oo]);
    }
    __syncthreads();

    int warp = tid >> 5, lane = tid & 31;
    int warpM = warp >> 2, warpN = warp & 3;
    int grp = lane >> 2, tig = lane & 3;
    float acc[4][4][4] = {};
    int cur = 0;
    for (int kt = 0; kt < 32; kt++) {
        float ra[2][4], rb[8];
        if (kt + 1 < 32) {
            int kbn = (kt + 1) << 4;
            const float* A0 = (kbn < 256) ? oh1 : oh2;
            const float* A1 = (kbn < 256) ? ow1 : ow2;
            const float* W  = (kbn < 256) ? W1 : W2;
            int kboff = kbn & 255;
#pragma unroll
            for (int j = 0; j < 2; j++) {
                int i = tid + 256 * j; int kk4 = i & 3, tt = i >> 2;
                float4 va = *(const float4*)&A0[(size_t)(t0 + tt) * 256 + kboff + kk4 * 4];
                float4 vb = *(const float4*)&A1[(size_t)(t0 + tt) * 256 + kboff + kk4 * 4];
                ra[j][0] = va.x + vb.x; ra[j][1] = va.y + vb.y;
                ra[j][2] = va.z + vb.z; ra[j][3] = va.w + vb.w;
            }
#pragma unroll
            for (int j = 0; j < 8; j++) {
                int i = tid + 256 * j; int kk = i >> 7, oo = i & 127;
                rb[j] = W[(kboff + kk) * 256 + o0 + oo];
            }
        }
#pragma unroll
        for (int k8 = 0; k8 < 16; k8 += 8) {
            uint32_t af[4][4], bf[4][2];
#pragma unroll
            for (int mm = 0; mm < 4; mm++) {
                int r = warpM * 64 + mm * 16 + grp;
                af[mm][0] = __float_as_uint(As[cur][k8 + tig][r]);
                af[mm][1] = __float_as_uint(As[cur][k8 + tig][r + 8]);
                af[mm][2] = __float_as_uint(As[cur][k8 + tig + 4][r]);
                af[mm][3] = __float_as_uint(As[cur][k8 + tig + 4][r + 8]);
            }
#pragma unroll
            for (int nn = 0; nn < 4; nn++) {
                int c = warpN * 32 + nn * 8 + grp;
                bf[nn][0] = __float_as_uint(Bs[cur][k8 + tig][c]);
                bf[nn][1] = __float_as_uint(Bs[cur][k8 + tig + 4][c]);
            }
#pragma unroll
            for (int mm = 0; mm < 4; mm++)
#pragma unroll
                for (int nn = 0; nn < 4; nn++)
                    mma_tf32(acc[mm][nn], af[mm], bf[nn]);
        }
        if (kt + 1 < 32) {
            int nb = cur ^ 1;
#pragma unroll
            for (int j = 0; j < 2; j++) {
                int i = tid + 256 * j; int kk4 = i & 3, tt = i >> 2;
                As[nb][kk4 * 4 + 0][tt] = to_tf32(ra[j][0]);
                As[nb][kk4 * 4 + 1][tt] = to_tf32(ra[j][1]);
                As[nb][kk4 * 4 + 2][tt] = to_tf32(ra[j][2]);
                As[nb][kk4 * 4 + 3][tt] = to_tf32(ra[j][3]);
            }
#pragma unroll
            for (int j = 0; j < 8; j++) {
                int i = tid + 256 * j; int kk = i >> 7, oo = i & 127;
                Bs[nb][kk][oo] = to_tf32(rb[j]);
            }
            cur = nb;
            __syncthreads();
        }
    }

    int b = t0 >> 12, hw0 = t0 & 4095;
#pragma unroll
    for (int mm = 0; mm < 4; mm++) {
#pragma unroll
        for (int nn = 0; nn < 4; nn++) {
            int c = o0 + warpN * 32 + nn * 8 + tig * 2;
            float bv0 = b1[c] + b2[c], bv1 = b1[c + 1] + b2[c + 1];
#pragma unroll
            for (int h = 0; h < 2; h++) {
                int r = warpM * 64 + mm * 16 + grp + h * 8;
                int t = t0 + r, hw = hw0 + r;
                float2 sc = *(const float2*)&p1[(size_t)t * 1024 + 768 + c];
                size_t gi0 = ((size_t)(b * 256 + c)) * HW + hw;
                size_t gi1 = ((size_t)(b * 256 + c + 1)) * HW + hw;
                out[gi0] = acc[mm][nn][h * 2]     + bv0 + sc.x + x2[gi0];
                out[gi1] = acc[mm][nn][h * 2 + 1] + bv1 + sc.y + x2[gi1];
            }
        }
    }
}

// ---------------- host launch ----------------
extern "C" void kernel_launch(void* const* d_in, const int* in_sizes, int n_in,
                              void* d_out, int out_size) {
    const float* x1      = (const float*)d_in[0];
    const float* x2      = (const float*)d_in[1];
    const float* ln1q_w  = (const float*)d_in[2];
    const float* ln1q_b  = (const float*)d_in[3];
    const float* ln2kv_w = (const float*)d_in[4];
    const float* ln2kv_b = (const float*)d_in[5];
    const float* Wq1     = (const float*)d_in[6];
    const float* Wkv2    = (const float*)d_in[7];
    const float* Wout1   = (const float*)d_in[8];
    const float* bout1   = (const float*)d_in[9];
    const float* ln2q_w  = (const float*)d_in[10];
    const float* ln2q_b  = (const float*)d_in[11];
    const float* ln1kv_w = (const float*)d_in[12];
    const float* ln1kv_b = (const float*)d_in[13];
    const float* Wq2     = (const float*)d_in[14];
    const float* Wkv1    = (const float*)d_in[15];
    const float* Wout2   = (const float*)d_in[16];
    const float* bout2   = (const float*)d_in[17];
    const float* Wsc     = (const float*)d_in[18];
    const float* bn_g    = (const float*)d_in[19];
    const float* bn_b    = (const float*)d_in[20];
    const float* bn_m    = (const float*)d_in[21];
    const float* bn_v    = (const float*)d_in[22];
    float* out = (float*)d_out;

    float *mu1, *rs1, *mu2, *rs2, *p1, *p2, *oh1, *ow1, *oh2, *ow2;
    float *Wt1, *Wt2, *b1cat, *b2cat, *cs1, *cs2;
    cudaGetSymbolAddress((void**)&mu1, g_mu1);
    cudaGetSymbolAddress((void**)&rs1, g_rs1);
    cudaGetSymbolAddress((void**)&mu2, g_mu2);
    cudaGetSymbolAddress((void**)&rs2, g_rs2);
    cudaGetSymbolAddress((void**)&p1, g_p1);
    cudaGetSymbolAddress((void**)&p2, g_p2);
    cudaGetSymbolAddress((void**)&oh1, g_oh1);
    cudaGetSymbolAddress((void**)&ow1, g_ow1);
    cudaGetSymbolAddress((void**)&oh2, g_oh2);
    cudaGetSymbolAddress((void**)&ow2, g_ow2);
    cudaGetSymbolAddress((void**)&Wt1, g_Wt1);
    cudaGetSymbolAddress((void**)&Wt2, g_Wt2);
    cudaGetSymbolAddress((void**)&b1cat, g_b1cat);
    cudaGetSymbolAddress((void**)&b2cat, g_b2cat);
    cudaGetSymbolAddress((void**)&cs1, g_cs1);
    cudaGetSymbolAddress((void**)&cs2, g_cs2);

    static int smem_set = 0;
    const int proj_smem = PROJ_SMEM_FLOATS * 4;
    if (!smem_set) {
        cudaFuncSetAttribute(k_proj, cudaFuncAttributeMaxDynamicSharedMemorySize, proj_smem);
        smem_set = 1;
    }

    // weight/bias folding (weights transposed to [out][C] for ldmatrix-B)
    k_fold_wcat<<<(1024 * 384 + 768 * 256 + 255) / 256, 256>>>(
        Wq1, ln1q_w, Wkv1, ln1kv_w, Wsc, bn_g, bn_v, Wq2, ln2q_w, Wkv2, ln2kv_w,
        Wt1, Wt2);
    k_fold_bias<<<7, 256>>>(Wq1, ln1q_w, ln1q_b, Wkv1, ln1kv_w, ln1kv_b,
                            bn_g, bn_b, bn_m, bn_v,
                            Wq2, ln2q_w, ln2q_b, Wkv2, ln2kv_w, ln2kv_b,
                            b1cat, b2cat, cs1, cs2);

    // LN stats (both inputs, one launch)
    k_stats<<<2048, 256>>>(x1, x2, mu1, rs1, mu2, rs2);

    // merged projections (tf32 tensor cores, BK=32, LN deferred, ldmatrix-B)
    k_proj<<<dim3(256, 14), 256, proj_smem>>>(x1, x2, mu1, rs1, mu2, rs2,
                                              Wt1, Wt2, b1cat, b2cat, cs1, cs2, p1, p2);

    // merged axial attention (both branches + both axes in one launch)
    k_attn<<<16384, 128>>>(p1, p2, oh1, ow1, oh2, ow2);

    // output GEMMs + shortcut + residual + NCHW transpose (tf32 tensor cores)
    k_final<<<dim3(256, 2), 256>>>(oh1, ow1, oh2, ow2, Wout1, Wout2, bout1, bout2,
                                   p1, x2, out);
}

// round 16
// speedup vs baseline: 5.0490x; 1.0157x over previous
#include <cuda_runtime.h>
#include <math.h>
#include <stdint.h>

#define NTOK 32768
#define HW 4096
#define EPSV 1e-5f

// ---------------- scratch (static device memory; no allocations) ----------------
__device__ float g_mu1[NTOK], g_rs1[NTOK], g_mu2[NTOK], g_rs2[NTOK];
__device__ float g_p1[NTOK * 1024];   // per token: [q1(256) | k1(256) | v1(256) | sc(256)]
__device__ float g_p2[NTOK * 768];    // per token: [q2(256) | k2(256) | v2(256)]
__device__ float g_oh1[NTOK * 256], g_ow1[NTOK * 256];
__device__ float g_oh2[NTOK * 256], g_ow2[NTOK * 256];
__device__ float g_Wt1[1024 * 384];    // TRANSPOSED folded weights [out][C], tf32-rounded
__device__ float g_Wt2[768 * 256];
__device__ float g_b1cat[1024], g_b2cat[768];
__device__ float g_cs1[768], g_cs2[768];   // column sums of folded W (LN-defer term)

// ---------------- tf32 helpers ----------------
__device__ __forceinline__ float to_tf32(float x) {
    float y;
    asm("cvt.rna.tf32.f32 %0, %1;" : "=f"(y) : "f"(x));
    return y;
}

__device__ __forceinline__ void mma_tf32(float* d, const uint32_t* a, const uint32_t* b) {
    asm volatile(
        "mma.sync.aligned.m16n8k8.row.col.f32.tf32.tf32.f32 "
        "{%0,%1,%2,%3}, {%4,%5,%6,%7}, {%8,%9}, {%0,%1,%2,%3};\n"
        : "+f"(d[0]), "+f"(d[1]), "+f"(d[2]), "+f"(d[3])
        : "r"(a[0]), "r"(a[1]), "r"(a[2]), "r"(a[3]), "r"(b[0]), "r"(b[1]));
}

__device__ __forceinline__ void cp_async16(void* smem_dst, const void* gmem_src) {
    uint32_t d = (uint32_t)__cvta_generic_to_shared(smem_dst);
    asm volatile("cp.async.cg.shared.global [%0], [%1], 16;\n" :: "r"(d), "l"(gmem_src));
}

__device__ __forceinline__ void ldsm_x4(uint32_t& r0, uint32_t& r1, uint32_t& r2,
                                        uint32_t& r3, const void* smem) {
    uint32_t a = (uint32_t)__cvta_generic_to_shared(smem);
    asm volatile("ldmatrix.sync.aligned.m8n8.x4.shared.b16 {%0,%1,%2,%3}, [%4];\n"
                 : "=r"(r0), "=r"(r1), "=r"(r2), "=r"(r3) : "r"(a));
}

// ---------------- merged setup: LN stats + weight folding + bias folding (one launch) -------
// blocks [0,2048): per-token stats; [2048,4352): transposed weight fold; [4352,4359): biases.
__global__ void k_setup(
    const float* __restrict__ X1, const float* __restrict__ X2,
    float* __restrict__ mu1, float* __restrict__ rs1,
    float* __restrict__ mu2, float* __restrict__ rs2,
    const float* __restrict__ Wq1, const float* __restrict__ ln1qw, const float* __restrict__ ln1qb,
    const float* __restrict__ Wkv1, const float* __restrict__ ln1kvw, const float* __restrict__ ln1kvb,
    const float* __restrict__ Wsc, const float* __restrict__ bng, const float* __restrict__ bnb,
    const float* __restrict__ bnm, const float* __restrict__ bnv,
    const float* __restrict__ Wq2, const float* __restrict__ ln2qw, const float* __restrict__ ln2qb,
    const float* __restrict__ Wkv2, const float* __restrict__ ln2kvw, const float* __restrict__ ln2kvb,
    float* __restrict__ Wt1, float* __restrict__ Wt2,
    float* __restrict__ b1cat, float* __restrict__ b2cat,
    float* __restrict__ cs1, float* __restrict__ cs2) {
    int bid = blockIdx.x;
    int tid = threadIdx.x;
    if (bid < 2048) {
        // ---- LN stats ----
        __shared__ float ss[8][33], sq[8][33];
        int half = bid >> 10;
        const float* X = half ? X2 : X1;
        int C = half ? 256 : 384;
        float* mu = half ? mu2 : mu1;
        float* rs = half ? rs2 : rs1;
        int lane = tid & 31, cs = tid >> 5;
        int t = (bid & 1023) * 32 + lane;
        int b = t >> 12, hw = t & 4095;
        const float* p = X + (size_t)b * C * HW + hw;
        float s = 0.f, s2 = 0.f;
        for (int c = cs; c < C; c += 8) {
            float v = p[(size_t)c * HW];
            s += v; s2 += v * v;
        }
        ss[cs][lane] = s; sq[cs][lane] = s2;
        __syncthreads();
        if (tid < 32) {
            float a = 0.f, q = 0.f;
#pragma unroll
            for (int j = 0; j < 8; j++) { a += ss[j][lane]; q += sq[j][lane]; }
            float m = a / C;
            mu[t] = m;
            rs[t] = rsqrtf(q / C - m * m + EPSV);
        }
    } else if (bid < 4352) {
        // ---- transposed weight fold (tf32) ----
        int idx = (bid - 2048) * 256 + tid;
        const int N1 = 1024 * 384;
        if (idx < N1) {
            int o = idx / 384, c = idx % 384;
            float v;
            if (o < 256)      v = Wq1[c * 256 + o] * ln1qw[c];
            else if (o < 768) v = Wkv1[c * 512 + (o - 256)] * ln1kvw[c];
            else { int oo = o - 768; v = Wsc[oo * 384 + c] * bng[oo] * rsqrtf(bnv[oo] + EPSV); }
            Wt1[idx] = to_tf32(v);
        } else if (idx < N1 + 768 * 256) {
            int i2 = idx - N1;
            int o = i2 >> 8, c = i2 & 255;
            float v;
            if (o < 256) v = Wq2[c * 256 + o] * ln2qw[c];
            else         v = Wkv2[c * 512 + (o - 256)] * ln2kvw[c];
            Wt2[i2] = to_tf32(v);
        }
    } else {
        // ---- biases + colsums ----
        int og = (bid - 4352) * 256 + tid;
        if (og < 1024) {
            float b = 0.f, cs = 0.f;
            if (og < 256) {
                for (int c = 0; c < 384; c++) {
                    b += ln1qb[c] * Wq1[c * 256 + og];
                    cs += to_tf32(ln1qw[c] * Wq1[c * 256 + og]);
                }
                cs1[og] = cs;
            } else if (og < 768) {
                int o = og - 256;
                for (int c = 0; c < 384; c++) {
                    b += ln1kvb[c] * Wkv1[c * 512 + o];
                    cs += to_tf32(ln1kvw[c] * Wkv1[c * 512 + o]);
                }
                cs1[og] = cs;
            } else {
                int oo = og - 768;
                float g = bng[oo] * rsqrtf(bnv[oo] + EPSV);
                b = bnb[oo] - bnm[oo] * g;
            }
            b1cat[og] = b;
        } else if (og < 1792) {
            int o2 = og - 1024;
            float b = 0.f, cs = 0.f;
            if (o2 < 256) {
                for (int c = 0; c < 256; c++) {
                    b += ln2qb[c] * Wq2[c * 256 + o2];
                    cs += to_tf32(ln2qw[c] * Wq2[c * 256 + o2]);
                }
            } else {
                int o = o2 - 256;
                for (int c = 0; c < 256; c++) {
                    b += ln2kvb[c] * Wkv2[c * 512 + o];
                    cs += to_tf32(ln2kvw[c] * Wkv2[c * 512 + o]);
                }
            }
            b2cat[o2] = b;
            cs2[o2] = cs;
        }
    }
}

// ---------------- merged projection GEMM (tf32, LN-deferred, 4-stage cp.async + ldmatrix-B) -
// BOTH branches: grid.y 0-7 -> x1 (C=384, Nout=1024), 8-13 -> x2 (C=256, 768).
// BK=16, 4 pipeline stages, wait_group 2 (stage slack = 3 k-tiles), 2 CTAs/SM.
#define PROJ_SMEM_FLOATS (4 * 16 * 136 + 4 * 128 * 20 + 256)
__global__ __launch_bounds__(256, 2) void k_proj(
    const float* __restrict__ x1, const float* __restrict__ x2,
    const float* __restrict__ mu1, const float* __restrict__ rs1,
    const float* __restrict__ mu2, const float* __restrict__ rs2,
    const float* __restrict__ Wt1, const float* __restrict__ Wt2,
    const float* __restrict__ b1cat, const float* __restrict__ b2cat,
    const float* __restrict__ cs1, const float* __restrict__ cs2,
    float* __restrict__ p1, float* __restrict__ p2) {
    extern __shared__ float dyn[];
    float (*As)[16][136] = (float(*)[16][136])dyn;
    float (*Bt)[128][20] = (float(*)[128][20])(dyn + 4 * 16 * 136);
    float* smu = dyn + 4 * 16 * 136 + 4 * 128 * 20;
    float* srs = smu + 128;

    int by = blockIdx.y;
    int br2 = (by >= 8);
    const float* X   = br2 ? x2 : x1;
    const float* mu  = br2 ? mu2 : mu1;
    const float* rs  = br2 ? rs2 : rs1;
    const float* Wt  = br2 ? Wt2 : Wt1;
    const float* bias = br2 ? b2cat : b1cat;
    const float* cs  = br2 ? cs2 : cs1;
    float* out       = br2 ? p2 : p1;
    int C    = br2 ? 256 : 384;
    int Nout = br2 ? 768 : 1024;
    int sc_start = br2 ? (1 << 30) : 768;
    int o0 = (br2 ? (by - 8) : by) * 128;

    int t0 = blockIdx.x * 128;
    int tid = threadIdx.x;
    if (tid < 128) { smu[tid] = mu[t0 + tid]; srs[tid] = rs[t0 + tid]; }
    int bb = t0 >> 12, hw0 = t0 & 4095;
    const float* Xb = X + (size_t)bb * C * HW + hw0;

    int KT = C >> 4;

    // fill stage s with k-tile kt (A: 512 f4, B: 512 f4 -> 2 cp.async x2 per thread)
    auto fill = [&](int s, int kt) {
        int k0 = kt << 4;
#pragma unroll
        for (int j = 0; j < 2; j++) {
            int id = tid + 256 * j;
            int kk = id >> 5, c4 = id & 31;
            cp_async16(&As[s][kk][c4 * 4], Xb + (size_t)(k0 + kk) * HW + c4 * 4);
            int nr = id >> 2, k4 = id & 3;
            cp_async16(&Bt[s][nr][k4 * 4], Wt + (size_t)(o0 + nr) * C + k0 + k4 * 4);
        }
    };

    // prologue: stages 0..2 in flight
#pragma unroll
    for (int s = 0; s < 3; s++) {
        fill(s, s);
        asm volatile("cp.async.commit_group;\n");
    }

    int warp = tid >> 5, lane = tid & 31;
    int warpM = warp >> 2, warpN = warp & 3;
    int grp = lane >> 2, tig = lane & 3;
    int oct = lane >> 3, lo = lane & 7;
    float acc[4][4][4] = {};
    for (int kt = 0; kt < KT; kt++) {
        int cur = kt & 3;
        asm volatile("cp.async.wait_group 2;\n");
        __syncthreads();
        // prefetch stage kt+3 (empty commit keeps group bookkeeping uniform)
        if (kt + 3 < KT) fill((kt + 3) & 3, kt + 3);
        asm volatile("cp.async.commit_group;\n");
#pragma unroll
        for (int k8 = 0; k8 < 16; k8 += 8) {
            uint32_t af[4][4], bf[4][2];
#pragma unroll
            for (int mm = 0; mm < 4; mm++) {
                int r = warpM * 64 + mm * 16 + grp;
                af[mm][0] = __float_as_uint(As[cur][k8 + tig][r]);
                af[mm][1] = __float_as_uint(As[cur][k8 + tig][r + 8]);
                af[mm][2] = __float_as_uint(As[cur][k8 + tig + 4][r]);
                af[mm][3] = __float_as_uint(As[cur][k8 + tig + 4][r + 8]);
            }
#pragma unroll
            for (int p = 0; p < 2; p++) {
                int nrow = warpN * 32 + p * 16 + ((oct >> 1) << 3) + lo;
                int kc = k8 + ((oct & 1) << 2);
                ldsm_x4(bf[p * 2][0], bf[p * 2][1], bf[p * 2 + 1][0], bf[p * 2 + 1][1],
                        &Bt[cur][nrow][kc]);
            }
#pragma unroll
            for (int mm = 0; mm < 4; mm++)
#pragma unroll
                for (int nn = 0; nn < 4; nn++)
                    mma_tf32(acc[mm][nn], af[mm], bf[nn]);
        }
        __syncthreads();   // stage cur consumed; safe to refill at iter kt+1's prefetch
    }

    bool isc = (o0 >= sc_start);
#pragma unroll
    for (int mm = 0; mm < 4; mm++) {
#pragma unroll
        for (int nn = 0; nn < 4; nn++) {
            int c = o0 + warpN * 32 + nn * 8 + tig * 2;
            float bv0 = bias[c], bv1 = bias[c + 1];
            float cs0 = 0.f, cs1v = 0.f;
            if (!isc) { cs0 = cs[c]; cs1v = cs[c + 1]; }
#pragma unroll
            for (int h = 0; h < 2; h++) {
                int r = warpM * 64 + mm * 16 + grp + h * 8;
                float v0 = acc[mm][nn][h * 2], v1 = acc[mm][nn][h * 2 + 1];
                if (!isc) {
                    float rv = srs[r], m = smu[r];
                    v0 = rv * (v0 - m * cs0) + bv0;
                    v1 = rv * (v1 - m * cs1v) + bv1;
                } else { v0 += bv0; v1 += bv1; }
                *(float2*)&out[(size_t)(t0 + r) * Nout + c] = make_float2(v0, v1);
            }
        }
    }
}

// ---------------- axial attention (tf32), BOTH branches AND axes in one launch -------------
__global__ __launch_bounds__(128) void k_attn(
    const float* __restrict__ p1, const float* __restrict__ p2,
    float* __restrict__ oh1, float* __restrict__ ow1,
    float* __restrict__ oh2, float* __restrict__ ow2) {
    __shared__ float Qs[64][36];
    __shared__ float Ks[64][36];
    __shared__ float Vs[64][36];
    __shared__ float S[64][68];
    __shared__ float sinv[64];
    int bx = blockIdx.x;
    int branch = bx >> 13;
    int head = bx & 7, line = (bx >> 3) & 63, b = (bx >> 9) & 7, axis = (bx >> 12) & 1;
    const float* Q = branch ? p2 : p1;
    const float* K = branch ? (p1 + 256) : (p2 + 256);
    const float* V = branch ? (p1 + 512) : (p2 + 512);
    int qpitch  = branch ? 768 : 1024;
    int kvpitch = branch ? 1024 : 768;
    float* O = branch ? (axis ? ow2 : oh2) : (axis ? ow1 : oh1);
    int tstride = axis ? 1 : 64;
    int tbase = b * 4096 + (axis ? line * 64 : line);
    int hoff = head * 32;
    int tid = threadIdx.x;
    const float scale = 0.17677669529663687f; // 1/sqrt(32), folded into Q

    for (int i = tid; i < 64 * 8; i += 128) {
        int r = i >> 3, q4 = i & 7;
        size_t t = (size_t)(tbase + r * tstride);
        float4 vq = *(const float4*)&Q[t * qpitch + hoff + q4 * 4];
        float4 vk = *(const float4*)&K[t * kvpitch + hoff + q4 * 4];
        float4 vv = *(const float4*)&V[t * kvpitch + hoff + q4 * 4];
        *(float4*)&Qs[r][q4 * 4] = make_float4(to_tf32(vq.x * scale), to_tf32(vq.y * scale),
                                               to_tf32(vq.z * scale), to_tf32(vq.w * scale));
        *(float4*)&Ks[r][q4 * 4] = make_float4(to_tf32(vk.x), to_tf32(vk.y),
                                               to_tf32(vk.z), to_tf32(vk.w));
        *(float4*)&Vs[r][q4 * 4] = make_float4(to_tf32(vv.x), to_tf32(vv.y),
                                               to_tf32(vv.z), to_tf32(vv.w));
    }
    __syncthreads();

    int warp = tid >> 5, lane = tid & 31;
    int grp = lane >> 2, tig = lane & 3;
    int m0 = warp * 16;

    {
        uint32_t af[4][4];
#pragma unroll
        for (int k8 = 0; k8 < 4; k8++) {
            af[k8][0] = __float_as_uint(Qs[m0 + grp][k8 * 8 + tig]);
            af[k8][1] = __float_as_uint(Qs[m0 + grp + 8][k8 * 8 + tig]);
            af[k8][2] = __float_as_uint(Qs[m0 + grp][k8 * 8 + tig + 4]);
            af[k8][3] = __float_as_uint(Qs[m0 + grp + 8][k8 * 8 + tig + 4]);
        }
#pragma unroll
        for (int n8 = 0; n8 < 8; n8++) {
            float sacc[4] = {};
#pragma unroll
            for (int k8 = 0; k8 < 4; k8++) {
                uint32_t bf[2];
                bf[0] = __float_as_uint(Ks[n8 * 8 + grp][k8 * 8 + tig]);
                bf[1] = __float_as_uint(Ks[n8 * 8 + grp][k8 * 8 + tig + 4]);
                mma_tf32(sacc, af[k8], bf);
            }
            *(float2*)&S[m0 + grp][n8 * 8 + tig * 2]     = make_float2(sacc[0], sacc[1]);
            *(float2*)&S[m0 + grp + 8][n8 * 8 + tig * 2] = make_float2(sacc[2], sacc[3]);
        }
    }
    __syncthreads();

    {
        int row = tid >> 1, half = tid & 1;
        float* sr = &S[row][half * 32];
        float m = -1e30f;
#pragma unroll 8
        for (int j = 0; j < 32; j++) m = fmaxf(m, sr[j]);
        m = fmaxf(m, __shfl_xor_sync(0xffffffffu, m, 1));
        float sum = 0.f;
#pragma unroll 8
        for (int j = 0; j < 32; j++) {
            float e = __expf(sr[j] - m);
            sum += e;
            sr[j] = to_tf32(e);
        }
        sum += __shfl_xor_sync(0xffffffffu, sum, 1);
        if (half == 0) sinv[row] = 1.f / sum;
    }
    __syncthreads();

    {
        float oacc[4][4] = {};
#pragma unroll
        for (int k8 = 0; k8 < 8; k8++) {
            uint32_t af[4];
            af[0] = __float_as_uint(S[m0 + grp][k8 * 8 + tig]);
            af[1] = __float_as_uint(S[m0 + grp + 8][k8 * 8 + tig]);
            af[2] = __float_as_uint(S[m0 + grp][k8 * 8 + tig + 4]);
            af[3] = __float_as_uint(S[m0 + grp + 8][k8 * 8 + tig + 4]);
#pragma unroll
            for (int nn = 0; nn < 4; nn++) {
                uint32_t bf[2];
                bf[0] = __float_as_uint(Vs[k8 * 8 + tig][nn * 8 + grp]);
                bf[1] = __float_as_uint(Vs[k8 * 8 + tig + 4][nn * 8 + grp]);
                mma_tf32(oacc[nn], af, bf);
            }
        }
        float inva = sinv[m0 + grp], invb = sinv[m0 + grp + 8];
        int ta = tbase + (m0 + grp) * tstride;
        int tb = tbase + (m0 + grp + 8) * tstride;
        float* Oa = O + (size_t)ta * 256 + hoff;
        float* Ob = O + (size_t)tb * 256 + hoff;
#pragma unroll
        for (int nn = 0; nn < 4; nn++) {
            int c = nn * 8 + tig * 2;
            *(float2*)&Oa[c] = make_float2(oacc[nn][0] * inva, oacc[nn][1] * inva);
            *(float2*)&Ob[c] = make_float2(oacc[nn][2] * invb, oacc[nn][3] * invb);
        }
    }
}

// ---------------- tensor-core final GEMM (tf32): out = sc + x2 + (oh+ow)@W + b --------------
__global__ __launch_bounds__(256) void k_final(
    const float* __restrict__ oh1, const float* __restrict__ ow1,
    const float* __restrict__ oh2, const float* __restrict__ ow2,
    const float* __restrict__ W1, const float* __restrict__ W2,
    const float* __restrict__ b1, const float* __restrict__ b2,
    const float* __restrict__ p1, const float* __restrict__ x2,
    float* __restrict__ out) {
    __shared__ float As[2][16][136];
    __shared__ float Bs[2][16][136];
    int t0 = blockIdx.x * 128, o0 = blockIdx.y * 128;
    int tid = threadIdx.x;

#pragma unroll
    for (int j = 0; j < 2; j++) {
        int i = tid + 256 * j; int kk4 = i & 3, tt = i >> 2;
        float4 va = *(const float4*)&oh1[(size_t)(t0 + tt) * 256 + kk4 * 4];
        float4 vb = *(const float4*)&ow1[(size_t)(t0 + tt) * 256 + kk4 * 4];
        As[0][kk4 * 4 + 0][tt] = to_tf32(va.x + vb.x);
        As[0][kk4 * 4 + 1][tt] = to_tf32(va.y + vb.y);
        As[0][kk4 * 4 + 2][tt] = to_tf32(va.z + vb.z);
        As[0][kk4 * 4 + 3][tt] = to_tf32(va.w + vb.w);
    }
#pragma unroll
    for (int j = 0; j < 8; j++) {
        int i = tid + 256 * j; int kk = i >> 7, oo = i & 127;
        Bs[0][kk][oo] = to_tf32(W1[kk * 256 + o0 + oo]);
    }
    __syncthreads();

    int warp = tid >> 5, lane = tid & 31;
    int warpM = warp >> 2, warpN = warp & 3;
    int grp = lane >> 2, tig = lane & 3;
    float acc[4][4][4] = {};
    int cur = 0;
    for (int kt = 0; kt < 32; kt++) {
        float ra[2][4], rb[8];
        if (kt + 1 < 32) {
            int kbn = (kt + 1) << 4;
            const float* A0 = (kbn < 256) ? oh1 : oh2;
            const float* A1 = (kbn < 256) ? ow1 : ow2;
            const float* W  = (kbn < 256) ? W1 : W2;
            int kboff = kbn & 255;
#pragma unroll
            for (int j = 0; j < 2; j++) {
                int i = tid + 256 * j; int kk4 = i & 3, tt = i >> 2;
                float4 va = *(const float4*)&A0[(size_t)(t0 + tt) * 256 + kboff + kk4 * 4];
                float4 vb = *(const float4*)&A1[(size_t)(t0 + tt) * 256 + kboff + kk4 * 4];
                ra[j][0] = va.x + vb.x; ra[j][1] = va.y + vb.y;
                ra[j][2] = va.z + vb.z; ra[j][3] = va.w + vb.w;
            }
#pragma unroll
            for (int j = 0; j < 8; j++) {
                int i = tid + 256 * j; int kk = i >> 7, oo = i & 127;
                rb[j] = W[(kboff + kk) * 256 + o0 + oo];
            }
        }
#pragma unroll
        for (int k8 = 0; k8 < 16; k8 += 8) {
            uint32_t af[4][4], bf[4][2];
#pragma unroll
            for (int mm = 0; mm < 4; mm++) {
                int r = warpM * 64 + mm * 16 + grp;
                af[mm][0] = __float_as_uint(As[cur][k8 + tig][r]);
                af[mm][1] = __float_as_uint(As[cur][k8 + tig][r + 8]);
                af[mm][2] = __float_as_uint(As[cur][k8 + tig + 4][r]);
                af[mm][3] = __float_as_uint(As[cur][k8 + tig + 4][r + 8]);
            }
#pragma unroll
            for (int nn = 0; nn < 4; nn++) {
                int c = warpN * 32 + nn * 8 + grp;
                bf[nn][0] = __float_as_uint(Bs[cur][k8 + tig][c]);
                bf[nn][1] = __float_as_uint(Bs[cur][k8 + tig + 4][c]);
            }
#pragma unroll
            for (int mm = 0; mm < 4; mm++)
#pragma unroll
                for (int nn = 0; nn < 4; nn++)
                    mma_tf32(acc[mm][nn], af[mm], bf[nn]);
        }
        if (kt + 1 < 32) {
            int nb = cur ^ 1;
#pragma unroll
            for (int j = 0; j < 2; j++) {
                int i = tid + 256 * j; int kk4 = i & 3, tt = i >> 2;
                As[nb][kk4 * 4 + 0][tt] = to_tf32(ra[j][0]);
                As[nb][kk4 * 4 + 1][tt] = to_tf32(ra[j][1]);
                As[nb][kk4 * 4 + 2][tt] = to_tf32(ra[j][2]);
                As[nb][kk4 * 4 + 3][tt] = to_tf32(ra[j][3]);
            }
#pragma unroll
            for (int j = 0; j < 8; j++) {
                int i = tid + 256 * j; int kk = i >> 7, oo = i & 127;
                Bs[nb][kk][oo] = to_tf32(rb[j]);
            }
            cur = nb;
            __syncthreads();
        }
    }

    int b = t0 >> 12, hw0 = t0 & 4095;
#pragma unroll
    for (int mm = 0; mm < 4; mm++) {
#pragma unroll
        for (int nn = 0; nn < 4; nn++) {
            int c = o0 + warpN * 32 + nn * 8 + tig * 2;
            float bv0 = b1[c] + b2[c], bv1 = b1[c + 1] + b2[c + 1];
#pragma unroll
            for (int h = 0; h < 2; h++) {
                int r = warpM * 64 + mm * 16 + grp + h * 8;
                int t = t0 + r, hw = hw0 + r;
                float2 sc = *(const float2*)&p1[(size_t)t * 1024 + 768 + c];
                size_t gi0 = ((size_t)(b * 256 + c)) * HW + hw;
                size_t gi1 = ((size_t)(b * 256 + c + 1)) * HW + hw;
                out[gi0] = acc[mm][nn][h * 2]     + bv0 + sc.x + x2[gi0];
                out[gi1] = acc[mm][nn][h * 2 + 1] + bv1 + sc.y + x2[gi1];
            }
        }
    }
}

// ---------------- host launch ----------------
extern "C" void kernel_launch(void* const* d_in, const int* in_sizes, int n_in,
                              void* d_out, int out_size) {
    const float* x1      = (const float*)d_in[0];
    const float* x2      = (const float*)d_in[1];
    const float* ln1q_w  = (const float*)d_in[2];
    const float* ln1q_b  = (const float*)d_in[3];
    const float* ln2kv_w = (const float*)d_in[4];
    const float* ln2kv_b = (const float*)d_in[5];
    const float* Wq1     = (const float*)d_in[6];
    const float* Wkv2    = (const float*)d_in[7];
    const float* Wout1   = (const float*)d_in[8];
    const float* bout1   = (const float*)d_in[9];
    const float* ln2q_w  = (const float*)d_in[10];
    const float* ln2q_b  = (const float*)d_in[11];
    const float* ln1kv_w = (const float*)d_in[12];
    const float* ln1kv_b = (const float*)d_in[13];
    const float* Wq2     = (const float*)d_in[14];
    const float* Wkv1    = (const float*)d_in[15];
    const float* Wout2   = (const float*)d_in[16];
    const float* bout2   = (const float*)d_in[17];
    const float* Wsc     = (const float*)d_in[18];
    const float* bn_g    = (const float*)d_in[19];
    const float* bn_b    = (const float*)d_in[20];
    const float* bn_m    = (const float*)d_in[21];
    const float* bn_v    = (const float*)d_in[22];
    float* out = (float*)d_out;

    float *mu1, *rs1, *mu2, *rs2, *p1, *p2, *oh1, *ow1, *oh2, *ow2;
    float *Wt1, *Wt2, *b1cat, *b2cat, *cs1, *cs2;
    cudaGetSymbolAddress((void**)&mu1, g_mu1);
    cudaGetSymbolAddress((void**)&rs1, g_rs1);
    cudaGetSymbolAddress((void**)&mu2, g_mu2);
    cudaGetSymbolAddress((void**)&rs2, g_rs2);
    cudaGetSymbolAddress((void**)&p1, g_p1);
    cudaGetSymbolAddress((void**)&p2, g_p2);
    cudaGetSymbolAddress((void**)&oh1, g_oh1);
    cudaGetSymbolAddress((void**)&ow1, g_ow1);
    cudaGetSymbolAddress((void**)&oh2, g_oh2);
    cudaGetSymbolAddress((void**)&ow2, g_ow2);
    cudaGetSymbolAddress((void**)&Wt1, g_Wt1);
    cudaGetSymbolAddress((void**)&Wt2, g_Wt2);
    cudaGetSymbolAddress((void**)&b1cat, g_b1cat);
    cudaGetSymbolAddress((void**)&b2cat, g_b2cat);
    cudaGetSymbolAddress((void**)&cs1, g_cs1);
    cudaGetSymbolAddress((void**)&cs2, g_cs2);

    static int smem_set = 0;
    const int proj_smem = PROJ_SMEM_FLOATS * 4;
    if (!smem_set) {
        cudaFuncSetAttribute(k_proj, cudaFuncAttributeMaxDynamicSharedMemorySize, proj_smem);
        smem_set = 1;
    }

    // merged setup: LN stats + weight fold + bias fold (one launch)
    k_setup<<<4359, 256>>>(x1, x2, mu1, rs1, mu2, rs2,
                           Wq1, ln1q_w, ln1q_b, Wkv1, ln1kv_w, ln1kv_b,
                           Wsc, bn_g, bn_b, bn_m, bn_v,
                           Wq2, ln2q_w, ln2q_b, Wkv2, ln2kv_w, ln2kv_b,
                           Wt1, Wt2, b1cat, b2cat, cs1, cs2);

    // merged projections (tf32 tensor cores, 4-stage cp.async, LN deferred, ldmatrix-B)
    k_proj<<<dim3(256, 14), 256, proj_smem>>>(x1, x2, mu1, rs1, mu2, rs2,
                                              Wt1, Wt2, b1cat, b2cat, cs1, cs2, p1, p2);

    // merged axial attention (both branches + both axes in one launch)
    k_attn<<<16384, 128>>>(p1, p2, oh1, ow1, oh2, ow2);

    // output GEMMs + shortcut + residual + NCHW transpose (tf32 tensor cores)
    k_final<<<dim3(256, 2), 256>>>(oh1, ow1, oh2, ow2, Wout1, Wout2, bout1, bout2,
                                   p1, x2, out);
}